// round 13
// baseline (speedup 1.0000x reference)
#include <cuda_runtime.h>
#include <cuda_bf16.h>
#include <cuda_fp16.h>
#include <math.h>
#include <stdint.h>

#define BATCH 4
#define SEQ   2048
#define DM    512
#define NH    8
#define DK    64
#define ROWS  (BATCH * SEQ)   // 8192

#if defined(__CUDA_ARCH_FEAT_SM103_ALL) || defined(__CUDA_ARCH_FEAT_SM100_ALL) || \
    defined(__CUDA_ARCH_SPECIFIC__) || defined(__CUDA_ARCH_FAMILY_SPECIFIC__)
#define HAS_TC 1
#else
#define HAS_TC 0
#endif

// ---------------- scratch ----------------
__device__ float g_pe[SEQ * DM];
__device__ float g_h [ROWS * DM];
__device__ float g_fc[ROWS * DM];
__device__ __nv_bfloat16 g_ah[ROWS * DM];
__device__ __nv_bfloat16 g_al[ROWS * DM];
__device__ __nv_bfloat16 g_qh[ROWS * DM];
__device__ __nv_bfloat16 g_ql[ROWS * DM];
__device__ __nv_bfloat16 g_kh[ROWS * DM];
__device__ __nv_bfloat16 g_kl[ROWS * DM];
__device__ __nv_bfloat16 g_oh[ROWS * DM];
__device__ __nv_bfloat16 g_ol[ROWS * DM];
__device__ __half        g_vt[BATCH * NH * DK * SEQ];   // V^T fp16 [bh][dim][key]
__device__ __nv_bfloat16 g_wth[4][DM * DM];
__device__ __nv_bfloat16 g_wtl[4][DM * DM];

// ================= helpers =================
__device__ __forceinline__ uint32_t smem_u32(const void* p) {
    uint32_t a;
    asm("{ .reg .u64 t; cvta.to.shared.u64 t, %1; cvt.u32.u64 %0, t; }"
        : "=r"(a) : "l"(p));
    return a;
}

// cheap exp2: magic-constant rounding + deg-4 poly. Valid for |x| < ~60.
__device__ __forceinline__ float fexp2(float x) {
    float z = x + 12582912.f;
    int   iz = __float_as_int(z);
    float f  = x - (z - 12582912.f);
    float p  = 9.6788e-3f;
    p = fmaf(p, f, 5.55041e-2f);
    p = fmaf(p, f, 2.402265e-1f);
    p = fmaf(p, f, 6.931472e-1f);
    p = fmaf(p, f, 1.0f);
    return p * __int_as_float((iz << 23) + 0x3F800000);
}

#if HAS_TC
__device__ __forceinline__ uint32_t elect1() {
    uint32_t p;
    asm volatile("{\n\t.reg .pred p;\n\telect.sync _|p, 0xFFFFFFFF;\n\t"
                 "selp.b32 %0, 1, 0, p;\n\t}" : "=r"(p));
    return p;
}
#define TC_ALLOC(smemaddr, ncols) \
    asm volatile("tcgen05.alloc.cta_group::1.sync.aligned.shared::cta.b32 [%0], %1;" \
                 :: "r"(smemaddr), "r"(ncols) : "memory")
#define TC_RELINQ() \
    asm volatile("tcgen05.relinquish_alloc_permit.cta_group::1.sync.aligned;")
#define TC_DEALLOC(tmem, ncols) \
    asm volatile("tcgen05.dealloc.cta_group::1.sync.aligned.b32 %0, %1;" \
                 :: "r"(tmem), "r"(ncols))
#define TC_COMMIT(mbar) \
    asm volatile("tcgen05.commit.cta_group::1.mbarrier::arrive::one.shared::cluster.b64 [%0];" \
                 :: "r"(mbar) : "memory")
#define TC_FENCE_AFTER()  asm volatile("tcgen05.fence::after_thread_sync;" ::: "memory")
#define TC_FENCE_BEFORE() asm volatile("tcgen05.fence::before_thread_sync;" ::: "memory")
#define TC_WAIT_LD()      asm volatile("tcgen05.wait::ld.sync.aligned;" ::: "memory")
#define FENCE_ASYNC_SHARED() asm volatile("fence.proxy.async.shared::cta;" ::: "memory")
#define MBAR_INIT(mbar, cnt) \
    asm volatile("mbarrier.init.shared.b64 [%0], %1;" :: "r"(mbar), "r"(cnt) : "memory")

__device__ __forceinline__ void mbar_wait(uint32_t mbar, uint32_t parity) {
    asm volatile(
        "{\n\t.reg .pred P;\n\t"
        "WL_%=:\n\t"
        "mbarrier.try_wait.parity.acquire.cta.shared::cta.b64 P, [%0], %1, 0x989680;\n\t"
        "@P bra.uni WD_%=;\n\t"
        "bra.uni WL_%=;\n\t"
        "WD_%=:\n\t}"
        :: "r"(mbar), "r"(parity) : "memory");
}

__device__ __forceinline__ void tc_ld_x32(uint32_t* r, uint32_t tmem_addr) {
    asm volatile(
        "tcgen05.ld.sync.aligned.32x32b.x32.b32 "
        "{%0, %1, %2, %3, %4, %5, %6, %7, %8, %9, %10, %11, %12, %13, %14, %15, "
        " %16, %17, %18, %19, %20, %21, %22, %23, %24, %25, %26, %27, %28, %29, %30, %31}, [%32];"
        : "=r"(r[0]),  "=r"(r[1]),  "=r"(r[2]),  "=r"(r[3]),
          "=r"(r[4]),  "=r"(r[5]),  "=r"(r[6]),  "=r"(r[7]),
          "=r"(r[8]),  "=r"(r[9]),  "=r"(r[10]), "=r"(r[11]),
          "=r"(r[12]), "=r"(r[13]), "=r"(r[14]), "=r"(r[15]),
          "=r"(r[16]), "=r"(r[17]), "=r"(r[18]), "=r"(r[19]),
          "=r"(r[20]), "=r"(r[21]), "=r"(r[22]), "=r"(r[23]),
          "=r"(r[24]), "=r"(r[25]), "=r"(r[26]), "=r"(r[27]),
          "=r"(r[28]), "=r"(r[29]), "=r"(r[30]), "=r"(r[31])
        : "r"(tmem_addr));
}

__device__ __forceinline__ void mma_f16_ss(uint32_t d, uint64_t a, uint64_t b,
                                           uint32_t idesc, uint32_t en) {
    asm volatile(
        "{\n\t.reg .pred p;\n\tsetp.ne.u32 p, %4, 0;\n\t"
        "tcgen05.mma.cta_group::1.kind::f16 [%0], %1, %2, %3, {%5, %5, %5, %5}, p;\n\t}"
        :: "r"(d), "l"(a), "l"(b), "r"(idesc), "r"(en), "r"(0u) : "memory");
}

static __device__ __forceinline__ uint64_t make_desc_sw128(uint32_t base) {
    const uint64_t BASE =
        (uint64_t(2) << 61) | (uint64_t(1) << 46) | (uint64_t(64) << 32) | (uint64_t(1) << 16);
    return BASE | ((uint64_t)(base >> 4) & 0x3FFF);
}
#endif  // HAS_TC

// ---------------- wsplit x4 (launch #1) ----------------
__global__ void wsplit4_kernel(const float* __restrict__ W0,
                               const float* __restrict__ W1,
                               const float* __restrict__ W2,
                               const float* __restrict__ W3,
                               __nv_bfloat16* __restrict__ Th,
                               __nv_bfloat16* __restrict__ Tl) {
    __shared__ float t[32][33];
    int z = blockIdx.z;
    int tid = threadIdx.x;
    const float* W = (z == 0) ? W0 : (z == 1) ? W1 : (z == 2) ? W2 : W3;
    __nv_bfloat16* th = Th + (size_t)z * DM * DM;
    __nv_bfloat16* tl = Tl + (size_t)z * DM * DM;
    int n0 = blockIdx.x * 32, k0 = blockIdx.y * 32;
    int tx = tid & 31, ty = tid >> 5;
#pragma unroll
    for (int i = 0; i < 32; i += 8)
        t[ty + i][tx] = W[(size_t)(k0 + ty + i) * DM + n0 + tx];
    __syncthreads();
#pragma unroll
    for (int i = 0; i < 32; i += 8) {
        float v = t[tx][ty + i];
        __nv_bfloat16 h = __float2bfloat16(v);
        __nv_bfloat16 l = __float2bfloat16(v - __bfloat162float(h));
        size_t o = (size_t)(n0 + ty + i) * DM + k0 + tx;
        th[o] = h; tl[o] = l;
    }
}

// ---------------- positional encoding (launch #2) ----------------
__global__ void pe_kernel(float* __restrict__ pe) {
    int tid = threadIdx.x;
    int trow = blockIdx.x * 8 + (tid >> 5);
    int lane = tid & 31;
    const double c = -(9.210340371976184 / 512.0);
#pragma unroll
    for (int u = 0; u < 16; u++) {
        int col = lane * 16 + u;
        int i2  = col & ~1;
        double arg = (double)trow * exp((double)i2 * c);
        pe[trow * DM + col] = (col & 1) ? (float)cos(arg) : (float)sin(arg);
    }
}

// ---------------- LN1 + pe (+ bf16 split of h) ----------------
__global__ void ln1_pos_kernel(const float* __restrict__ x,
                               const float* __restrict__ gam,
                               const float* __restrict__ bet,
                               const float* __restrict__ pe,
                               float* __restrict__ h,
                               __nv_bfloat16* __restrict__ hh,
                               __nv_bfloat16* __restrict__ hl) {
    __shared__ float redS[8], redS2[8];
    int row = blockIdx.x;
    int t   = row & (SEQ - 1);
    const float* xr = x  + (size_t)row * DM;
    const float* pr = pe + (size_t)t   * DM;
    int tid = threadIdx.x;

    float a = xr[tid], b = xr[tid + 256];
    float s  = a + b;
    float s2 = a * a + b * b;
#pragma unroll
    for (int off = 16; off; off >>= 1) {
        s  += __shfl_xor_sync(0xffffffffu, s,  off);
        s2 += __shfl_xor_sync(0xffffffffu, s2, off);
    }
    if ((tid & 31) == 0) { redS[tid >> 5] = s; redS2[tid >> 5] = s2; }
    __syncthreads();
    if (tid == 0) {
        float S = 0.f, S2 = 0.f;
#pragma unroll
        for (int w = 0; w < 8; w++) { S += redS[w]; S2 += redS2[w]; }
        redS[0] = S; redS2[0] = S2;
    }
    __syncthreads();
    float mu   = redS[0] * (1.f / 512.f);
    float var  = redS2[0] * (1.f / 512.f) - mu * mu;
    float rstd = rsqrtf(var + 1e-5f);
#pragma unroll
    for (int u = 0; u < 2; u++) {
        int col = tid + u * 256;
        float xv = u ? b : a;
        float hv = (xv - mu) * rstd * gam[col] + bet[col] + pr[col];
        size_t o = (size_t)row * DM + col;
        h[o] = hv;
        __nv_bfloat16 hi = __float2bfloat16(hv);
        hh[o] = hi;
        hl[o] = __float2bfloat16(hv - __bfloat162float(hi));
    }
}

// ---------------- LN2 + residuals ----------------
__global__ void ln2_kernel(const float* __restrict__ o2,
                           const float* __restrict__ r1,
                           const float* __restrict__ x,
                           const float* __restrict__ gam,
                           const float* __restrict__ bet,
                           float* __restrict__ out) {
    __shared__ float redS[8], redS2[8];
    int row = blockIdx.x;
    const float* or_ = o2 + (size_t)row * DM;
    const float* rr  = r1 + (size_t)row * DM;
    const float* xr  = x  + (size_t)row * DM;
    float*       wr  = out + (size_t)row * DM;
    int tid = threadIdx.x;

    float a = or_[tid]       + rr[tid];
    float b = or_[tid + 256] + rr[tid + 256];
    float s  = a + b;
    float s2 = a * a + b * b;
#pragma unroll
    for (int off = 16; off; off >>= 1) {
        s  += __shfl_xor_sync(0xffffffffu, s,  off);
        s2 += __shfl_xor_sync(0xffffffffu, s2, off);
    }
    if ((tid & 31) == 0) { redS[tid >> 5] = s; redS2[tid >> 5] = s2; }
    __syncthreads();
    if (tid == 0) {
        float S = 0.f, S2 = 0.f;
#pragma unroll
        for (int w = 0; w < 8; w++) { S += redS[w]; S2 += redS2[w]; }
        redS[0] = S; redS2[0] = S2;
    }
    __syncthreads();
    float mu   = redS[0] * (1.f / 512.f);
    float var  = redS2[0] * (1.f / 512.f) - mu * mu;
    float rstd = rsqrtf(var + 1e-6f);
#pragma unroll
    for (int u = 0; u < 2; u++) {
        int col = tid + u * 256;
        float vv = u ? b : a;
        wr[col] = (vv - mu) * rstd * gam[col] + bet[col] + xr[col];
    }
}

// ====== GEMM core (bf16x3, 128x128 tile, A db + B single-buffer w/ reg prefetch,
//                   2 CTA/SM) ====
#define GIDESC ((1u << 4) | (1u << 7) | (1u << 10) | ((128u / 8) << 17) | ((128u / 16) << 24))
#define GEMM_DSMEM 100352   // 96KB layout + 1KB align slack + pad

#if HAS_TC
__device__ __forceinline__ uint32_t gemm_mainloop_tc(
    const __nv_bfloat16* __restrict__ Ah, const __nv_bfloat16* __restrict__ Al,
    const __nv_bfloat16* __restrict__ Bh, const __nv_bfloat16* __restrict__ Bl,
    int m0, int n0, char* dsm_raw,
    uint64_t* s_mbar, uint32_t* s_tm,
    uint32_t tid, uint32_t wid)
{
    uint32_t raw = smem_u32(dsm_raw);
    uint32_t sb  = (raw + 1023) & ~1023u;
    char* dsm = dsm_raw + (sb - raw);

    uint32_t mb = smem_u32(&s_mbar[0]);
    if (wid == 0) { TC_ALLOC(smem_u32(s_tm), 128); TC_RELINQ(); }
    if (tid == 0) { MBAR_INIT(mb, 1); }
    __syncthreads();
    uint32_t tmem = s_tm[0];

    // layout: A buf0 @0 (AH 16K, AL 16K), A buf1 @32768, B @65536 (BH, BL)
    const uint32_t OFF_B = 65536u;

    int r = (int)tid >> 1, g2 = ((int)tid & 1) * 4;   // 4x16B groups per tile

    const __nv_bfloat16* Ahb = Ah + (size_t)m0 * DM;
    const __nv_bfloat16* Alb = Al + (size_t)m0 * DM;
    const __nv_bfloat16* Bhb = Bh + (size_t)n0 * DM;
    const __nv_bfloat16* Blb = Bl + (size_t)n0 * DM;

    // precomputed swizzled smem offsets for this thread's 4 groups
    uint32_t soff[4];
#pragma unroll
    for (int i = 0; i < 4; i++) {
        uint32_t o = (uint32_t)(r * 128 + (g2 + i) * 16);
        soff[i] = o ^ ((o >> 3) & 0x70);
    }

    uint4 rbh[4], rbl[4];   // B register prefetch

    auto copyA = [&](int c, uint32_t boff) {
        int k0 = c * 64;
#pragma unroll
        for (int i = 0; i < 4; i++) {
            size_t ga = (size_t)r * DM + k0 + (g2 + i) * 8;
            *(uint4*)(dsm + boff + soff[i])         = *(const uint4*)(Ahb + ga);
            *(uint4*)(dsm + boff + 16384 + soff[i]) = *(const uint4*)(Alb + ga);
        }
    };
    auto ldB = [&](int c) {
        int k0 = c * 64;
#pragma unroll
        for (int i = 0; i < 4; i++) {
            size_t gb = (size_t)r * DM + k0 + (g2 + i) * 8;
            rbh[i] = *(const uint4*)(Bhb + gb);
            rbl[i] = *(const uint4*)(Blb + gb);
        }
    };
    auto stsB = [&]() {
#pragma unroll
        for (int i = 0; i < 4; i++) {
            *(uint4*)(dsm + OFF_B + soff[i])         = rbh[i];
            *(uint4*)(dsm + OFF_B + 16384 + soff[i]) = rbl[i];
        }
    };
    auto issue = [&](uint32_t boff, uint32_t en0) {
        if (wid == 0 && elect1()) {
            FENCE_ASYNC_SHARED();
            uint64_t dah = make_desc_sw128(sb + boff);
            uint64_t dal = make_desc_sw128(sb + boff + 16384);
            uint64_t dbh = make_desc_sw128(sb + OFF_B);
            uint64_t dbl = make_desc_sw128(sb + OFF_B + 16384);
#pragma unroll
            for (int ks = 0; ks < 4; ks++) {
                mma_f16_ss(tmem, dah + ks * 2, dbh + ks * 2, GIDESC,
                           (ks == 0) ? en0 : 1u);
                mma_f16_ss(tmem, dah + ks * 2, dbl + ks * 2, GIDESC, 1u);
                mma_f16_ss(tmem, dal + ks * 2, dbh + ks * 2, GIDESC, 1u);
            }
            TC_COMMIT(mb);
        }
    };

    // prologue
    copyA(0, 0);
    ldB(0);
    stsB();
    __syncthreads();
    issue(0, 0u);
    copyA(1, 32768u);        // buf1 never read yet: safe
    ldB(1);                  // prefetch B(1); latency overlaps MMA(0)

#pragma unroll 1
    for (int c = 1; c < 8; c++) {
        mbar_wait(mb, (uint32_t)((c - 1) & 1));   // MMA(c-1) done -> B smem free
        stsB();                                   // regs -> smem only
        __syncthreads();
        issue((uint32_t)(c & 1) * 32768u, 1u);
        if (c < 7) {
            copyA(c + 1, (uint32_t)((c + 1) & 1) * 32768u);  // safe: MMA(c-1) done
            ldB(c + 1);                                      // overlaps MMA(c)
        }
    }
    mbar_wait(mb, 1u);   // MMA(7) done
    TC_FENCE_AFTER();
    return tmem;
}
#else
__device__ __forceinline__ void gemm_mainloop_simt(
    const __nv_bfloat16* __restrict__ Ah, const __nv_bfloat16* __restrict__ Al,
    const __nv_bfloat16* __restrict__ Bh, const __nv_bfloat16* __restrict__ Bl,
    int m0, int n0, char* dsm_raw, uint32_t tid, float acc[8][8])
{
    float* As = (float*)dsm_raw;
    float* Ws = As + 2 * 8 * 132;
    int tx = tid & 15, ty = (int)(tid >> 4);
    int r = tid & 127;
    bool isA = tid < 128;
    const __nv_bfloat16* Ph = isA ? Ah + (size_t)(m0 + r) * DM
                                  : Bh + (size_t)(n0 + r) * DM;
    const __nv_bfloat16* Pl = isA ? Al + (size_t)(m0 + r) * DM
                                  : Bl + (size_t)(n0 + r) * DM;
    int stride = isA ? 132 : 128;
#pragma unroll
    for (int i = 0; i < 8; i++)
#pragma unroll
        for (int j = 0; j < 8; j++) acc[i][j] = 0.f;

    auto stage = [&](int buf, int k0) {
        uint4 vh = *(const uint4*)(Ph + k0);
        uint4 vl = *(const uint4*)(Pl + k0);
        const __nv_bfloat16* bh = (const __nv_bfloat16*)&vh;
        const __nv_bfloat16* bl = (const __nv_bfloat16*)&vl;
        float* dst = (isA ? As + buf * 8 * 132 : Ws + buf * 8 * 128) + r;
#pragma unroll
        for (int k = 0; k < 8; k++)
            dst[k * stride] = __bfloat162float(bh[k]) + __bfloat162float(bl[k]);
    };
    stage(0, 0);
    __syncthreads();
    int buf = 0;
#pragma unroll 1
    for (int k0 = 0; k0 < 512; k0 += 8) {
        if (k0 + 8 < 512) stage(buf ^ 1, k0 + 8);
#pragma unroll
        for (int kk = 0; kk < 8; kk++) {
            float av[8], bv[8];
            const float* ar = As + buf * 8 * 132 + kk * 132;
            const float* wr = Ws + buf * 8 * 128 + kk * 128;
            *(float4*)(av)     = *(const float4*)(ar + ty * 4);
            *(float4*)(av + 4) = *(const float4*)(ar + 64 + ty * 4);
            *(float4*)(bv)     = *(const float4*)(wr + tx * 4);
            *(float4*)(bv + 4) = *(const float4*)(wr + 64 + tx * 4);
#pragma unroll
            for (int i = 0; i < 8; i++)
#pragma unroll
                for (int j = 0; j < 8; j++) acc[i][j] += av[i] * bv[j];
        }
        __syncthreads();
        buf ^= 1;
    }
}
#endif

// ---------------- fused Q/K/V projection ----------------
__global__ void __launch_bounds__(256, 2)
gemm_qkv_kernel(const __nv_bfloat16* __restrict__ Ah,
                const __nv_bfloat16* __restrict__ Al,
                const __nv_bfloat16* __restrict__ Wh,
                const __nv_bfloat16* __restrict__ Wl,
                __nv_bfloat16* __restrict__ Qh, __nv_bfloat16* __restrict__ Ql,
                __nv_bfloat16* __restrict__ Kh, __nv_bfloat16* __restrict__ Kl,
                __half* __restrict__ Vt, float qscale) {
    extern __shared__ char dsm_raw[];
    uint32_t tid = threadIdx.x, wid = tid >> 5, lid = tid & 31;
    int m0 = blockIdx.x * 128, n0 = blockIdx.y * 128;
    int z = blockIdx.z;
    const __nv_bfloat16* Bh = Wh + (size_t)z * DM * DM;
    const __nv_bfloat16* Bl = Wl + (size_t)z * DM * DM;
    float scale = (z == 0) ? qscale : 1.0f;

#if HAS_TC
    __shared__ __align__(16) uint64_t s_mbar[1];
    __shared__ uint32_t s_tm[1];
    uint32_t tmem = gemm_mainloop_tc(Ah, Al, Bh, Bl, m0, n0, dsm_raw,
                                     s_mbar, s_tm, tid, wid);
    int sub  = wid & 3;
    int colb = (wid >> 2) * 64;
    int row  = m0 + sub * 32 + (int)lid;
    size_t rowoff = (size_t)row * DM + n0 + colb;

    uint32_t d0[32], d1[32];
    tc_ld_x32(d0, tmem + colb);
    tc_ld_x32(d1, tmem + colb + 32);
    TC_WAIT_LD();

    if (z < 2) {
        __nv_bfloat16* Ch = (z == 0) ? Qh : Kh;
        __nv_bfloat16* Cl = (z == 0) ? Ql : Kl;
        uint32_t hw[32], lw[32];
#pragma unroll
        for (int m = 0; m < 16; m++) {
            float v0 = __uint_as_float(d0[2*m])   * scale;
            float v1 = __uint_as_float(d0[2*m+1]) * scale;
            __nv_bfloat162 h2 = __floats2bfloat162_rn(v0, v1);
            __nv_bfloat162 l2 = __floats2bfloat162_rn(v0 - __bfloat162float(h2.x),
                                                      v1 - __bfloat162float(h2.y));
            hw[m] = *(uint32_t*)&h2; lw[m] = *(uint32_t*)&l2;
        }
#pragma unroll
        for (int m = 0; m < 16; m++) {
            float v0 = __uint_as_float(d1[2*m])   * scale;
            float v1 = __uint_as_float(d1[2*m+1]) * scale;
            __nv_bfloat162 h2 = __floats2bfloat162_rn(v0, v1);
            __nv_bfloat162 l2 = __floats2bfloat162_rn(v0 - __bfloat162float(h2.x),
                                                      v1 - __bfloat162float(h2.y));
            hw[16 + m] = *(uint32_t*)&h2; lw[16 + m] = *(uint32_t*)&l2;
        }
#pragma unroll
        for (int u = 0; u < 8; u++) {
            *(uint4*)(Ch + rowoff + u * 8) =
                make_uint4(hw[4*u], hw[4*u+1], hw[4*u+2], hw[4*u+3]);
            *(uint4*)(Cl + rowoff + u * 8) =
                make_uint4(lw[4*u], lw[4*u+1], lw[4*u+2], lw[4*u+3]);
        }
    } else {
        int b = row >> 11, t = row & (SEQ - 1);
#pragma unroll
        for (int j = 0; j < 32; j++) {
            int c = n0 + colb + j;
            size_t o = ((size_t)((b << 3) + (c >> 6)) * 64 + (c & 63)) * SEQ + t;
            Vt[o] = __float2half(__uint_as_float(d0[j]));
        }
#pragma unroll
        for (int j = 0; j < 32; j++) {
            int c = n0 + colb + 32 + j;
            size_t o = ((size_t)((b << 3) + (c >> 6)) * 64 + (c & 63)) * SEQ + t;
            Vt[o] = __float2half(__uint_as_float(d1[j]));
        }
    }
    TC_FENCE_BEFORE();
    __syncthreads();
    if (wid == 0) TC_DEALLOC(tmem, 128);
#else
    float acc[8][8];
    gemm_mainloop_simt(Ah, Al, Bh, Bl, m0, n0, dsm_raw, tid, acc);
    int tx = tid & 15, ty = (int)(tid >> 4);
#pragma unroll
    for (int i = 0; i < 8; i++) {
        int row = m0 + ((i < 4) ? (ty * 4 + i) : (64 + ty * 4 + i - 4));
#pragma unroll
        for (int j = 0; j < 8; j++) {
            int col = n0 + ((j < 4) ? (tx * 4 + j) : (64 + tx * 4 + j - 4));
            float v = acc[i][j] * scale;
            if (z < 2) {
                __nv_bfloat16* Ch = (z == 0) ? Qh : Kh;
                __nv_bfloat16* Cl = (z == 0) ? Ql : Kl;
                __nv_bfloat16 h = __float2bfloat16(v);
                Ch[(size_t)row * DM + col] = h;
                Cl[(size_t)row * DM + col] = __float2bfloat16(v - __bfloat162float(h));
            } else {
                int b = row >> 11, t = row & (SEQ - 1);
                size_t o = ((size_t)((b << 3) + (col >> 6)) * 64 + (col & 63)) * SEQ + t;
                Vt[o] = __float2half(v);
            }
        }
    }
#endif
}

// ---------------- FC projection (fp32 out) ----------------
__global__ void __launch_bounds__(256, 2)
gemm_fc_kernel(const __nv_bfloat16* __restrict__ Ah,
               const __nv_bfloat16* __restrict__ Al,
               const __nv_bfloat16* __restrict__ Bh,
               const __nv_bfloat16* __restrict__ Bl,
               float* __restrict__ C) {
    extern __shared__ char dsm_raw[];
    uint32_t tid = threadIdx.x, wid = tid >> 5, lid = tid & 31;
    int m0 = blockIdx.x * 128, n0 = blockIdx.y * 128;
#if HAS_TC
    __shared__ __align__(16) uint64_t s_mbar[1];
    __shared__ uint32_t s_tm[1];
    uint32_t tmem = gemm_mainloop_tc(Ah, Al, Bh, Bl, m0, n0, dsm_raw,
                                     s_mbar, s_tm, tid, wid);
    int sub  = wid & 3;
    int colb = (wid >> 2) * 64;
    int row  = m0 + sub * 32 + (int)lid;
    float* Cr = C + (size_t)row * DM + n0 + colb;

    uint32_t d0[32], d1[32];
    tc_ld_x32(d0, tmem + colb);
    tc_ld_x32(d1, tmem + colb + 32);
    TC_WAIT_LD();
#pragma unroll
    for (int j = 0; j < 8; j++)
        *(float4*)(Cr + j * 4) = make_float4(
            __uint_as_float(d0[4*j]),   __uint_as_float(d0[4*j+1]),
            __uint_as_float(d0[4*j+2]), __uint_as_float(d0[4*j+3]));
#pragma unroll
    for (int j = 0; j < 8; j++)
        *(float4*)(Cr + 32 + j * 4) = make_float4(
            __uint_as_float(d1[4*j]),   __uint_as_float(d1[4*j+1]),
            __uint_as_float(d1[4*j+2]), __uint_as_float(d1[4*j+3]));
    TC_FENCE_BEFORE();
    __syncthreads();
    if (wid == 0) TC_DEALLOC(tmem, 128);
#else
    float acc[8][8];
    gemm_mainloop_simt(Ah, Al, Bh, Bl, m0, n0, dsm_raw, tid, acc);
    int tx = tid & 15, ty = (int)(tid >> 4);
#pragma unroll
    for (int i = 0; i < 8; i++) {
        int row = m0 + ((i < 4) ? (ty * 4 + i) : (64 + ty * 4 + i - 4));
#pragma unroll
        for (int j = 0; j < 8; j++) {
            int col = n0 + ((j < 4) ? (tx * 4 + j) : (64 + tx * 4 + j - 4));
            C[(size_t)row * DM + col] = acc[i][j];
        }
    }
#endif
}

// ========== attention (pipelined, triple-buffered V, cheap softmax) ==========
#define AIDESC_S  ((1u << 4) | (1u << 7) | (1u << 10) | ((64u / 8) << 17) | ((128u / 16) << 24))
#define AIDESC_PV ((1u << 4) | ((64u / 8) << 17) | ((128u / 16) << 24))
#define ATTN_DSMEM 108544

#if HAS_TC
__global__ void __launch_bounds__(256, 2)
attn_kernel(const __nv_bfloat16* __restrict__ Qh, const __nv_bfloat16* __restrict__ Ql,
            const __nv_bfloat16* __restrict__ Kh, const __nv_bfloat16* __restrict__ Kl,
            const __half* __restrict__ Vt,
            __nv_bfloat16* __restrict__ Oh, __nv_bfloat16* __restrict__ Ol) {
    extern __shared__ char dsm_raw[];
    __shared__ __align__(16) uint64_t s_mbar[3];
    __shared__ uint32_t s_tm[1];
    uint32_t tid = threadIdx.x, wid = tid >> 5, lane = tid & 31;
    int qt = (int)(gridDim.x - 1) - (int)blockIdx.x;
    int bh = blockIdx.y, bb = bh >> 3, hd = bh & 7;

    uint32_t raw = smem_u32(dsm_raw);
    uint32_t sb  = (raw + 1023) & ~1023u;
    char* dsm = dsm_raw + (sb - raw);

    const uint32_t OFF_QH = 0,     OFF_QL = 16384,
                   OFF_KH = 32768, OFF_KL = 49152,
                   OFF_V  = 65536,
                   OFF_P  = 90112,
                   OFF_L  = 106496;

    uint32_t mbS0 = smem_u32(&s_mbar[0]);
    uint32_t mbS1 = smem_u32(&s_mbar[1]);
    uint32_t mbPV = smem_u32(&s_mbar[2]);
    if (wid == 0) { TC_ALLOC(smem_u32(s_tm), 256); TC_RELINQ(); }
    if (tid == 0) { MBAR_INIT(mbS0, 1); MBAR_INIT(mbS1, 1); MBAR_INIT(mbPV, 1); }
    __syncthreads();
    uint32_t tmem = s_tm[0];

    size_t rowbase = (size_t)bb * SEQ;
    const __nv_bfloat16* khb = Kh + rowbase * DM + hd * 64;
    const __nv_bfloat16* klb = Kl + rowbase * DM + hd * 64;
    const __half*        vtb = Vt + ((size_t)bh * 64) * SEQ;

    int cr0 = (int)tid >> 3,         cg0 = ((int)tid & 7) * 8;
    int cr1 = (int)(tid + 256) >> 3, cg1 = (((int)tid + 256) & 7) * 8;
    uint32_t so0, so1;
    {
        uint32_t o0 = (uint32_t)(cr0 * 128 + cg0 * 2), o1 = (uint32_t)(cr1 * 128 + cg1 * 2);
        so0 = o0 ^ ((o0 >> 3) & 0x70);
        so1 = o1 ^ ((o1 >> 3) & 0x70);
    }

    {
        const __nv_bfloat16* qhp = Qh + (rowbase + (size_t)qt * 128) * DM + hd * 64;
        const __nv_bfloat16* qlp = Ql + (rowbase + (size_t)qt * 128) * DM + hd * 64;
#pragma unroll
        for (int i = 0; i < 4; i++) {
            int idx = i * 256 + (int)tid;
            int r = idx >> 3, g = idx & 7;
            uint32_t o = (uint32_t)(r * 128 + g * 16), so = o ^ ((o >> 3) & 0x70);
            *(uint4*)(dsm + OFF_QH + so) = *(const uint4*)(qhp + (size_t)r * DM + g * 8);
            *(uint4*)(dsm + OFF_QL + so) = *(const uint4*)(qlp + (size_t)r * DM + g * 8);
        }
        *(uint4*)(dsm + OFF_KH + so0) = *(const uint4*)(khb + (size_t)cr0 * DM + cg0);
        *(uint4*)(dsm + OFF_KH + so1) = *(const uint4*)(khb + (size_t)cr1 * DM + cg1);
        *(uint4*)(dsm + OFF_KL + so0) = *(const uint4*)(klb + (size_t)cr0 * DM + cg0);
        *(uint4*)(dsm + OFF_KL + so1) = *(const uint4*)(klb + (size_t)cr1 * DM + cg1);
        *(uint4*)(dsm + OFF_V  + so0) = *(const uint4*)(vtb + (size_t)cr0 * SEQ + cg0);
        *(uint4*)(dsm + OFF_V  + so1) = *(const uint4*)(vtb + (size_t)cr1 * SEQ + cg1);
    }

    int ktmax = 2 * qt + 1;

    uint4 pkh0, pkh1, pkl0, pkl1, pv0, pv1;
    {
        const __nv_bfloat16* khp = khb + (size_t)64 * DM;
        const __nv_bfloat16* klp = klb + (size_t)64 * DM;
        const __half*        vhp = vtb + 64;
        pkh0 = *(const uint4*)(khp + (size_t)cr0 * DM + cg0);
        pkh1 = *(const uint4*)(khp + (size_t)cr1 * DM + cg1);
        pkl0 = *(const uint4*)(klp + (size_t)cr0 * DM + cg0);
        pkl1 = *(const uint4*)(klp + (size_t)cr1 * DM + cg1);
        pv0  = *(const uint4*)(vhp + (size_t)cr0 * SEQ + cg0);
        pv1  = *(const uint4*)(vhp + (size_t)cr1 * SEQ + cg1);
    }
    __syncthreads();

    uint64_t dqh = make_desc_sw128(sb + OFF_QH);
    uint64_t dql = make_desc_sw128(sb + OFF_QL);

    if (wid == 0 && elect1()) {
        FENCE_ASYNC_SHARED();
        uint64_t dkh = make_desc_sw128(sb + OFF_KH);
        uint64_t dkl = make_desc_sw128(sb + OFF_KL);
#pragma unroll
        for (int ks = 0; ks < 4; ks++)
            mma_f16_ss(tmem, dqh + ks * 2, dkh + ks * 2, AIDESC_S, ks ? 1u : 0u);
#pragma unroll
        for (int ks = 0; ks < 4; ks++)
            mma_f16_ss(tmem, dqh + ks * 2, dkl + ks * 2, AIDESC_S, 1u);
#pragma unroll
        for (int ks = 0; ks < 4; ks++)
            mma_f16_ss(tmem, dql + ks * 2, dkh + ks * 2, AIDESC_S, 1u);
        TC_COMMIT(mbS0);
    }

    int sub = wid & 3, half = (int)(wid >> 2);
    int rl = sub * 32 + (int)lane;
    int grow = qt * 128 + rl;
    float lsum = 0.f;
    uint32_t phS0 = 0, phS1 = 0, phPV = 0;
    int vslot = 0;

#pragma unroll 1
    for (int kt = 0; kt <= ktmax; kt++) {
        int buf = kt & 1;

        if (kt < ktmax) {
            int nbuf = buf ^ 1;
            int nvslot = vslot + 1; if (nvslot == 3) nvslot = 0;
            uint32_t kb   = OFF_KH + (uint32_t)nbuf * 8192u;
            uint32_t klb2 = OFF_KL + (uint32_t)nbuf * 8192u;
            uint32_t vb   = OFF_V  + (uint32_t)nvslot * 8192u;
            *(uint4*)(dsm + kb   + so0) = pkh0;
            *(uint4*)(dsm + kb   + so1) = pkh1;
            *(uint4*)(dsm + klb2 + so0) = pkl0;
            *(uint4*)(dsm + klb2 + so1) = pkl1;
            *(uint4*)(dsm + vb   + so0) = pv0;
            *(uint4*)(dsm + vb   + so1) = pv1;
            __syncthreads();
            if (wid == 0 && elect1()) {
                FENCE_ASYNC_SHARED();
                uint64_t dkh = make_desc_sw128(sb + kb);
                uint64_t dkl = make_desc_sw128(sb + klb2);
                uint32_t stm = tmem + (uint32_t)nbuf * 64u;
#pragma unroll
                for (int ks = 0; ks < 4; ks++)
                    mma_f16_ss(stm, dqh + ks * 2, dkh + ks * 2, AIDESC_S, ks ? 1u : 0u);
#pragma unroll
                for (int ks = 0; ks < 4; ks++)
                    mma_f16_ss(stm, dqh + ks * 2, dkl + ks * 2, AIDESC_S, 1u);
#pragma unroll
                for (int ks = 0; ks < 4; ks++)
                    mma_f16_ss(stm, dql + ks * 2, dkh + ks * 2, AIDESC_S, 1u);
                TC_COMMIT(nbuf == 0 ? mbS0 : mbS1);
            }
            if (kt + 2 <= ktmax) {
                const __nv_bfloat16* khp = khb + (size_t)(kt + 2) * 64 * DM;
                const __nv_bfloat16* klp = klb + (size_t)(kt + 2) * 64 * DM;
                const __half*        vhp = vtb + (size_t)(kt + 2) * 64;
                pkh0 = *(const uint4*)(khp + (size_t)cr0 * DM + cg0);
                pkh1 = *(const uint4*)(khp + (size_t)cr1 * DM + cg1);
                pkl0 = *(const uint4*)(klp + (size_t)cr0 * DM + cg0);
                pkl1 = *(const uint4*)(klp + (size_t)cr1 * DM + cg1);
                pv0  = *(const uint4*)(vhp + (size_t)cr0 * SEQ + cg0);
                pv1  = *(const uint4*)(vhp + (size_t)cr1 * SEQ + cg1);
            }
        }

        if (buf == 0) { mbar_wait(mbS0, phS0); phS0 ^= 1; }
        else          { mbar_wait(mbS1, phS1); phS1 ^= 1; }
        TC_FENCE_AFTER();

        uint32_t sreg[32];
        tc_ld_x32(sreg, tmem + (uint32_t)buf * 64u + half * 32);
        TC_WAIT_LD();

        if (kt >= 1) { mbar_wait(mbPV, phPV); phPV ^= 1; }

        int jmax = grow - (kt * 64 + half * 32);
        uint32_t pbase = (uint32_t)(rl * 128 + half * 64);
        if (jmax >= 31) {
#pragma unroll
            for (int gj = 0; gj < 4; gj++) {
                uint32_t w[4];
#pragma unroll
                for (int m = 0; m < 4; m++) {
                    int j0 = gj * 8 + m * 2;
                    float p0 = fexp2(__uint_as_float(sreg[j0]));
                    float p1 = fexp2(__uint_as_float(sreg[j0 + 1]));
                    lsum += p0 + p1;
                    __half2 h2 = __floats2half2_rn(p0, p1);
                    w[m] = *(uint32_t*)&h2;
                }
                uint32_t o = pbase + gj * 16, so = o ^ ((o >> 3) & 0x70);
                *(uint4*)(dsm + OFF_P + so) = make_uint4(w[0], w[1], w[2], w[3]);
            }
        } else {
#pragma unroll
            for (int gj = 0; gj < 4; gj++) {
                uint32_t w[4];
#pragma unroll
                for (int m = 0; m < 4; m++) {
                    int j0 = gj * 8 + m * 2;
                    float p0 = (j0     <= jmax) ? fexp2(__uint_as_float(sreg[j0]))     : 0.f;
                    float p1 = (j0 + 1 <= jmax) ? fexp2(__uint_as_float(sreg[j0 + 1])) : 0.f;
                    lsum += p0 + p1;
                    __half2 h2 = __floats2half2_rn(p0, p1);
                    w[m] = *(uint32_t*)&h2;
                }
                uint32_t o = pbase + gj * 16, so = o ^ ((o >> 3) & 0x70);
                *(uint4*)(dsm + OFF_P + so) = make_uint4(w[0], w[1], w[2], w[3]);
            }
        }
        __syncthreads();

        if (wid == 0 && elect1()) {
            FENCE_ASYNC_SHARED();
            uint64_t dp = make_desc_sw128(sb + OFF_P);
            uint64_t dv = make_desc_sw128(sb + OFF_V + (uint32_t)vslot * 8192u);
#pragma unroll
            for (int ks = 0; ks < 4; ks++)
                mma_f16_ss(tmem + 128, dp + ks * 2, dv + ks * 2, AIDESC_PV,
                           (kt == 0 && ks == 0) ? 0u : 1u);
            TC_COMMIT(mbPV);
        }
        vslot++; if (vslot == 3) vslot = 0;
    }

    mbar_wait(mbPV, phPV);
    TC_FENCE_AFTER();

    float* sl = (float*)(dsm + OFF_L);
    sl[rl * 2 + half] = lsum;
    __syncthreads();
    float inv = 1.f / (sl[rl * 2] + sl[rl * 2 + 1]);

    uint32_t oreg[32];
    tc_ld_x32(oreg, tmem + 128 + half * 32);
    TC_WAIT_LD();
    TC_FENCE_BEFORE();

    size_t obase = (rowbase + (size_t)grow) * DM + hd * 64 + half * 32;
    uint32_t hw[16], lw[16];
#pragma unroll
    for (int m = 0; m < 16; m++) {
        float v0 = __uint_as_float(oreg[2*m])   * inv;
        float v1 = __uint_as_float(oreg[2*m+1]) * inv;
        __nv_bfloat162 h2 = __floats2bfloat162_rn(v0, v1);
        __nv_bfloat162 l2 = __floats2bfloat162_rn(v0 - __bfloat162float(h2.x),
                                                  v1 - __bfloat162float(h2.y));
        hw[m] = *(uint32_t*)&h2; lw[m] = *(uint32_t*)&l2;
    }
#pragma unroll
    for (int u = 0; u < 4; u++) {
        *(uint4*)(Oh + obase + u * 8) = make_uint4(hw[4*u], hw[4*u+1], hw[4*u+2], hw[4*u+3]);
        *(uint4*)(Ol + obase + u * 8) = make_uint4(lw[4*u], lw[4*u+1], lw[4*u+2], lw[4*u+3]);
    }
    __syncthreads();
    if (wid == 0) TC_DEALLOC(tmem, 256);
}

#else  // ---------------- SIMT fallback attention ----------------
__global__ void __launch_bounds__(256)
attn_kernel(const __nv_bfloat16* __restrict__ Qh, const __nv_bfloat16* __restrict__ Ql,
            const __nv_bfloat16* __restrict__ Kh, const __nv_bfloat16* __restrict__ Kl,
            const __half* __restrict__ Vt,
            __nv_bfloat16* __restrict__ Oh, __nv_bfloat16* __restrict__ Ol) {
    extern __shared__ float sm[];
    float* sQ = sm;
    float* sK = sQ + 128 * 68;
    float* sV = sK + 64 * 68;
    float* sP = sV + 64 * 64;

    int qt = (int)(gridDim.x - 1) - (int)blockIdx.x;
    int bh = blockIdx.y;
    int bb = bh >> 3, hd = bh & 7;
    int tid = threadIdx.x;
    int tx = tid & 15, ty = tid >> 4;
    size_t base = ((size_t)bb * SEQ) * DM + (size_t)hd * DK;

    for (int idx = tid; idx < 128 * 64; idx += 256) {
        int r = idx >> 6, c = idx & 63;
        size_t o = base + (size_t)(qt * 128 + r) * DM + c;
        sQ[r * 68 + c] = __bfloat162float(Qh[o]) + __bfloat162float(Ql[o]);
    }

    float Oacc[8][4], m_i[8], l_i[8];
#pragma unroll
    for (int i = 0; i < 8; i++) {
        m_i[i] = -1e30f; l_i[i] = 0.f;
#pragma unroll
        for (int j = 0; j < 4; j++) Oacc[i][j] = 0.f;
    }

    int ktmax = 2 * qt + 1;
    for (int kt = 0; kt <= ktmax; kt++) {
        for (int idx = tid; idx < 64 * 64; idx += 256) {
            int r = idx >> 6, c = idx & 63;
            size_t ga = base + (size_t)(kt * 64 + r) * DM + c;
            sK[r * 68 + c] = __bfloat162float(Kh[ga]) + __bfloat162float(Kl[ga]);
            sV[r * 64 + c] = __half2float(Vt[((size_t)bh * 64 + c) * SEQ + kt * 64 + r]);
        }
        __syncthreads();

        float s[8][4];
#pragma unroll
        for (int i = 0; i < 8; i++)
#pragma unroll
            for (int j = 0; j < 4; j++) s[i][j] = 0.f;
#pragma unroll
        for (int d4 = 0; d4 < 16; d4++) {
            float4 kv[4];
#pragma unroll
            for (int j = 0; j < 4; j++)
                kv[j] = *(const float4*)&sK[(tx + 16 * j) * 68 + d4 * 4];
#pragma unroll
            for (int i = 0; i < 8; i++) {
                float4 qv = *(const float4*)&sQ[(ty + 16 * i) * 68 + d4 * 4];
#pragma unroll
                for (int j = 0; j < 4; j++)
                    s[i][j] += qv.x * kv[j].x + qv.y * kv[j].y +
                               qv.z * kv[j].z + qv.w * kv[j].w;
            }
        }
        if (kt >= 2 * qt) {
#pragma unroll
            for (int i = 0; i < 8; i++) {
                int grow = qt * 128 + ty + 16 * i;
#pragma unroll
                for (int j = 0; j < 4; j++)
                    if (kt * 64 + tx + 16 * j > grow) s[i][j] = -1e30f;
            }
        }
#pragma unroll
        for (int i = 0; i < 8; i++) {
            float mt = fmaxf(fmaxf(s[i][0], s[i][1]), fmaxf(s[i][2], s[i][3]));
#pragma unroll
            for (int off = 8; off; off >>= 1)
                mt = fmaxf(mt, __shfl_xor_sync(0xffffffffu, mt, off));
            float mn = fmaxf(m_i[i], mt);
            float corr = exp2f(m_i[i] - mn);
            m_i[i] = mn;
            float rs = 0.f;
#pragma unroll
            for (int j = 0; j < 4; j++) {
                float p = exp2f(s[i][j] - mn);
                s[i][j] = p; rs += p;
            }
#pragma unroll
            for (int off = 8; off; off >>= 1)
                rs += __shfl_xor_sync(0xffffffffu, rs, off);
            l_i[i] = l_i[i] * corr + rs;
#pragma unroll
            for (int j = 0; j < 4; j++) Oacc[i][j] *= corr;
#pragma unroll
            for (int j = 0; j < 4; j++)
                sP[(ty + 16 * i) * 68 + tx + 16 * j] = s[i][j];
        }
        __syncthreads();
#pragma unroll 4
        for (int k = 0; k < 64; k += 4) {
            float4 vv0 = *(const float4*)&sV[(k + 0) * 64 + tx * 4];
            float4 vv1 = *(const float4*)&sV[(k + 1) * 64 + tx * 4];
            float4 vv2 = *(const float4*)&sV[(k + 2) * 64 + tx * 4];
            float4 vv3 = *(const float4*)&sV[(k + 3) * 64 + tx * 4];
#pragma unroll
            for (int i = 0; i < 8; i++) {
                float4 pv = *(const float4*)&sP[(ty + 16 * i) * 68 + k];
                Oacc[i][0] += pv.x * vv0.x + pv.y * vv1.x + pv.z * vv2.x + pv.w * vv3.x;
                Oacc[i][1] += pv.x * vv0.y + pv.y * vv1.y + pv.z * vv2.y + pv.w * vv3.y;
                Oacc[i][2] += pv.x * vv0.z + pv.y * vv1.z + pv.z * vv2.z + pv.w * vv3.z;
                Oacc[i][3] += pv.x * vv0.w + pv.y * vv1.w + pv.z * vv2.w + pv.w * vv3.w;
            }
        }
        __syncthreads();
    }
#pragma unroll
    for (int i = 0; i < 8; i++) {
        float inv = 1.f / l_i[i];
        size_t rowa = base + (size_t)(qt * 128 + ty + 16 * i) * DM + tx * 4;
#pragma unroll
        for (int j = 0; j < 4; j++) {
            float v = Oacc[i][j] * inv;
            __nv_bfloat16 h = __float2bfloat16(v);
            Oh[rowa + j] = h;
            Ol[rowa + j] = __float2bfloat16(v - __bfloat162float(h));
        }
    }
}
#endif

// ---------------- launch ----------------
extern "C" void kernel_launch(void* const* d_in, const int* in_sizes, int n_in,
                              void* d_out, int out_size) {
    const float* x     = (const float*)d_in[0];
    const float* ln1_g = (const float*)d_in[1];
    const float* ln1_b = (const float*)d_in[2];
    const float* wq    = (const float*)d_in[3];
    const float* wk    = (const float*)d_in[4];
    const float* wv    = (const float*)d_in[5];
    const float* wfc   = (const float*)d_in[6];
    const float* ln2_g = (const float*)d_in[7];
    const float* ln2_b = (const float*)d_in[8];
    float* out = (float*)d_out;

    float *ppe, *ph, *pfc;
    __nv_bfloat16 *pwh, *pwl, *pah, *pal, *pqh, *pql, *pkh, *pkl, *poh, *pol;
    __half *pvt;
    cudaGetSymbolAddress((void**)&ppe,  g_pe);
    cudaGetSymbolAddress((void**)&ph,   g_h);
    cudaGetSymbolAddress((void**)&pfc,  g_fc);
    cudaGetSymbolAddress((void**)&pwh,  g_wth);
    cudaGetSymbolAddress((void**)&pwl,  g_wtl);
    cudaGetSymbolAddress((void**)&pah,  g_ah);
    cudaGetSymbolAddress((void**)&pal,  g_al);
    cudaGetSymbolAddress((void**)&pqh,  g_qh);
    cudaGetSymbolAddress((void**)&pql,  g_ql);
    cudaGetSymbolAddress((void**)&pkh,  g_kh);
    cudaGetSymbolAddress((void**)&pkl,  g_kl);
    cudaGetSymbolAddress((void**)&poh,  g_oh);
    cudaGetSymbolAddress((void**)&pol,  g_ol);
    cudaGetSymbolAddress((void**)&pvt,  g_vt);

    cudaFuncSetAttribute(attn_kernel,
                         cudaFuncAttributeMaxDynamicSharedMemorySize, ATTN_DSMEM);
    cudaFuncSetAttribute(gemm_qkv_kernel,
                         cudaFuncAttributeMaxDynamicSharedMemorySize, GEMM_DSMEM);
    cudaFuncSetAttribute(gemm_fc_kernel,
                         cudaFuncAttributeMaxDynamicSharedMemorySize, GEMM_DSMEM);

    const float qscale = 0.125f * 1.4426950408889634f;

    // #1: wsplit x4
    wsplit4_kernel<<<dim3(16, 16, 4), 256>>>(wq, wk, wv, wfc, pwh, pwl);
    // #2: pe
    pe_kernel<<<256, 256>>>(ppe);
    // #3: ln1
    ln1_pos_kernel<<<ROWS, 256>>>(x, ln1_g, ln1_b, ppe, ph, pah, pal);
    // #4: fused q/k/v projections  (process-launch #6 -> ncu capture target)
    gemm_qkv_kernel<<<dim3(ROWS / 128, DM / 128, 3), 256, GEMM_DSMEM>>>(
        pah, pal, pwh, pwl, pqh, pql, pkh, pkl, pvt, qscale);
    // #5: attention
    dim3 ga(SEQ / 128, BATCH * NH);
    attn_kernel<<<ga, 256, ATTN_DSMEM>>>(pqh, pql, pkh, pkl, pvt, poh, pol);
    // #6: fc
    gemm_fc_kernel<<<dim3(ROWS / 128, DM / 128), 256, GEMM_DSMEM>>>(
        poh, pol, pwh + 3 * (size_t)DM * DM, pwl + 3 * (size_t)DM * DM, pfc);
    // #7: ln2
    ln2_kernel<<<ROWS, 256>>>(pfc, ph, x, ln2_g, ln2_b, out);
}

// round 14
// speedup vs baseline: 1.0229x; 1.0229x over previous
#include <cuda_runtime.h>
#include <cuda_bf16.h>
#include <cuda_fp16.h>
#include <math.h>
#include <stdint.h>

#define BATCH 4
#define SEQ   2048
#define DM    512
#define NH    8
#define DK    64
#define ROWS  (BATCH * SEQ)   // 8192

#if defined(__CUDA_ARCH_FEAT_SM103_ALL) || defined(__CUDA_ARCH_FEAT_SM100_ALL) || \
    defined(__CUDA_ARCH_SPECIFIC__) || defined(__CUDA_ARCH_FAMILY_SPECIFIC__)
#define HAS_TC 1
#else
#define HAS_TC 0
#endif

// ---------------- scratch ----------------
__device__ float g_pe[SEQ * DM];
__device__ float g_h [ROWS * DM];
__device__ float g_fc[ROWS * DM];
__device__ __nv_bfloat16 g_ah[ROWS * DM];
__device__ __nv_bfloat16 g_al[ROWS * DM];
__device__ __nv_bfloat16 g_qh[ROWS * DM];
__device__ __nv_bfloat16 g_ql[ROWS * DM];
__device__ __nv_bfloat16 g_kh[ROWS * DM];
__device__ __nv_bfloat16 g_kl[ROWS * DM];
__device__ __nv_bfloat16 g_oh[ROWS * DM];
__device__ __nv_bfloat16 g_ol[ROWS * DM];
__device__ __half        g_vt[BATCH * NH * DK * SEQ];   // V^T fp16 [bh][dim][key]
__device__ __nv_bfloat16 g_wth[4][DM * DM];
__device__ __nv_bfloat16 g_wtl[4][DM * DM];

// ================= helpers =================
__device__ __forceinline__ uint32_t smem_u32(const void* p) {
    uint32_t a;
    asm("{ .reg .u64 t; cvta.to.shared.u64 t, %1; cvt.u32.u64 %0, t; }"
        : "=r"(a) : "l"(p));
    return a;
}

// cheap exp2: magic-constant rounding + deg-4 poly. Valid for |x| < ~60.
__device__ __forceinline__ float fexp2(float x) {
    float z = x + 12582912.f;
    int   iz = __float_as_int(z);
    float f  = x - (z - 12582912.f);
    float p  = 9.6788e-3f;
    p = fmaf(p, f, 5.55041e-2f);
    p = fmaf(p, f, 2.402265e-1f);
    p = fmaf(p, f, 6.931472e-1f);
    p = fmaf(p, f, 1.0f);
    return p * __int_as_float((iz << 23) + 0x3F800000);
}

#if HAS_TC
__device__ __forceinline__ uint32_t elect1() {
    uint32_t p;
    asm volatile("{\n\t.reg .pred p;\n\telect.sync _|p, 0xFFFFFFFF;\n\t"
                 "selp.b32 %0, 1, 0, p;\n\t}" : "=r"(p));
    return p;
}
#define TC_ALLOC(smemaddr, ncols) \
    asm volatile("tcgen05.alloc.cta_group::1.sync.aligned.shared::cta.b32 [%0], %1;" \
                 :: "r"(smemaddr), "r"(ncols) : "memory")
#define TC_RELINQ() \
    asm volatile("tcgen05.relinquish_alloc_permit.cta_group::1.sync.aligned;")
#define TC_DEALLOC(tmem, ncols) \
    asm volatile("tcgen05.dealloc.cta_group::1.sync.aligned.b32 %0, %1;" \
                 :: "r"(tmem), "r"(ncols))
#define TC_COMMIT(mbar) \
    asm volatile("tcgen05.commit.cta_group::1.mbarrier::arrive::one.shared::cluster.b64 [%0];" \
                 :: "r"(mbar) : "memory")
#define TC_FENCE_AFTER()  asm volatile("tcgen05.fence::after_thread_sync;" ::: "memory")
#define TC_FENCE_BEFORE() asm volatile("tcgen05.fence::before_thread_sync;" ::: "memory")
#define TC_WAIT_LD()      asm volatile("tcgen05.wait::ld.sync.aligned;" ::: "memory")
#define FENCE_ASYNC_SHARED() asm volatile("fence.proxy.async.shared::cta;" ::: "memory")
#define MBAR_INIT(mbar, cnt) \
    asm volatile("mbarrier.init.shared.b64 [%0], %1;" :: "r"(mbar), "r"(cnt) : "memory")

__device__ __forceinline__ void mbar_wait(uint32_t mbar, uint32_t parity) {
    asm volatile(
        "{\n\t.reg .pred P;\n\t"
        "WL_%=:\n\t"
        "mbarrier.try_wait.parity.acquire.cta.shared::cta.b64 P, [%0], %1, 0x989680;\n\t"
        "@P bra.uni WD_%=;\n\t"
        "bra.uni WL_%=;\n\t"
        "WD_%=:\n\t}"
        :: "r"(mbar), "r"(parity) : "memory");
}

__device__ __forceinline__ void tc_ld_x32(uint32_t* r, uint32_t tmem_addr) {
    asm volatile(
        "tcgen05.ld.sync.aligned.32x32b.x32.b32 "
        "{%0, %1, %2, %3, %4, %5, %6, %7, %8, %9, %10, %11, %12, %13, %14, %15, "
        " %16, %17, %18, %19, %20, %21, %22, %23, %24, %25, %26, %27, %28, %29, %30, %31}, [%32];"
        : "=r"(r[0]),  "=r"(r[1]),  "=r"(r[2]),  "=r"(r[3]),
          "=r"(r[4]),  "=r"(r[5]),  "=r"(r[6]),  "=r"(r[7]),
          "=r"(r[8]),  "=r"(r[9]),  "=r"(r[10]), "=r"(r[11]),
          "=r"(r[12]), "=r"(r[13]), "=r"(r[14]), "=r"(r[15]),
          "=r"(r[16]), "=r"(r[17]), "=r"(r[18]), "=r"(r[19]),
          "=r"(r[20]), "=r"(r[21]), "=r"(r[22]), "=r"(r[23]),
          "=r"(r[24]), "=r"(r[25]), "=r"(r[26]), "=r"(r[27]),
          "=r"(r[28]), "=r"(r[29]), "=r"(r[30]), "=r"(r[31])
        : "r"(tmem_addr));
}

__device__ __forceinline__ void mma_f16_ss(uint32_t d, uint64_t a, uint64_t b,
                                           uint32_t idesc, uint32_t en) {
    asm volatile(
        "{\n\t.reg .pred p;\n\tsetp.ne.u32 p, %4, 0;\n\t"
        "tcgen05.mma.cta_group::1.kind::f16 [%0], %1, %2, %3, {%5, %5, %5, %5}, p;\n\t}"
        :: "r"(d), "l"(a), "l"(b), "r"(idesc), "r"(en), "r"(0u) : "memory");
}

static __device__ __forceinline__ uint64_t make_desc_sw128(uint32_t base) {
    const uint64_t BASE =
        (uint64_t(2) << 61) | (uint64_t(1) << 46) | (uint64_t(64) << 32) | (uint64_t(1) << 16);
    return BASE | ((uint64_t)(base >> 4) & 0x3FFF);
}
#endif  // HAS_TC

// ---------------- wsplit x4 (launch #1) ----------------
__global__ void wsplit4_kernel(const float* __restrict__ W0,
                               const float* __restrict__ W1,
                               const float* __restrict__ W2,
                               const float* __restrict__ W3,
                               __nv_bfloat16* __restrict__ Th,
                               __nv_bfloat16* __restrict__ Tl) {
    __shared__ float t[32][33];
    int z = blockIdx.z;
    int tid = threadIdx.x;
    const float* W = (z == 0) ? W0 : (z == 1) ? W1 : (z == 2) ? W2 : W3;
    __nv_bfloat16* th = Th + (size_t)z * DM * DM;
    __nv_bfloat16* tl = Tl + (size_t)z * DM * DM;
    int n0 = blockIdx.x * 32, k0 = blockIdx.y * 32;
    int tx = tid & 31, ty = tid >> 5;
#pragma unroll
    for (int i = 0; i < 32; i += 8)
        t[ty + i][tx] = W[(size_t)(k0 + ty + i) * DM + n0 + tx];
    __syncthreads();
#pragma unroll
    for (int i = 0; i < 32; i += 8) {
        float v = t[tx][ty + i];
        __nv_bfloat16 h = __float2bfloat16(v);
        __nv_bfloat16 l = __float2bfloat16(v - __bfloat162float(h));
        size_t o = (size_t)(n0 + ty + i) * DM + k0 + tx;
        th[o] = h; tl[o] = l;
    }
}

// ---------------- positional encoding (launch #2) ----------------
__global__ void pe_kernel(float* __restrict__ pe) {
    int tid = threadIdx.x;
    int trow = blockIdx.x * 8 + (tid >> 5);
    int lane = tid & 31;
    const double c = -(9.210340371976184 / 512.0);
#pragma unroll
    for (int u = 0; u < 16; u++) {
        int col = lane * 16 + u;
        int i2  = col & ~1;
        double arg = (double)trow * exp((double)i2 * c);
        pe[trow * DM + col] = (col & 1) ? (float)cos(arg) : (float)sin(arg);
    }
}

// ---------------- LN1 + pe (+ bf16 split of h) ----------------
__global__ void ln1_pos_kernel(const float* __restrict__ x,
                               const float* __restrict__ gam,
                               const float* __restrict__ bet,
                               const float* __restrict__ pe,
                               float* __restrict__ h,
                               __nv_bfloat16* __restrict__ hh,
                               __nv_bfloat16* __restrict__ hl) {
    __shared__ float redS[8], redS2[8];
    int row = blockIdx.x;
    int t   = row & (SEQ - 1);
    const float* xr = x  + (size_t)row * DM;
    const float* pr = pe + (size_t)t   * DM;
    int tid = threadIdx.x;

    float a = xr[tid], b = xr[tid + 256];
    float s  = a + b;
    float s2 = a * a + b * b;
#pragma unroll
    for (int off = 16; off; off >>= 1) {
        s  += __shfl_xor_sync(0xffffffffu, s,  off);
        s2 += __shfl_xor_sync(0xffffffffu, s2, off);
    }
    if ((tid & 31) == 0) { redS[tid >> 5] = s; redS2[tid >> 5] = s2; }
    __syncthreads();
    if (tid == 0) {
        float S = 0.f, S2 = 0.f;
#pragma unroll
        for (int w = 0; w < 8; w++) { S += redS[w]; S2 += redS2[w]; }
        redS[0] = S; redS2[0] = S2;
    }
    __syncthreads();
    float mu   = redS[0] * (1.f / 512.f);
    float var  = redS2[0] * (1.f / 512.f) - mu * mu;
    float rstd = rsqrtf(var + 1e-5f);
#pragma unroll
    for (int u = 0; u < 2; u++) {
        int col = tid + u * 256;
        float xv = u ? b : a;
        float hv = (xv - mu) * rstd * gam[col] + bet[col] + pr[col];
        size_t o = (size_t)row * DM + col;
        h[o] = hv;
        __nv_bfloat16 hi = __float2bfloat16(hv);
        hh[o] = hi;
        hl[o] = __float2bfloat16(hv - __bfloat162float(hi));
    }
}

// ---------------- LN2 + residuals ----------------
__global__ void ln2_kernel(const float* __restrict__ o2,
                           const float* __restrict__ r1,
                           const float* __restrict__ x,
                           const float* __restrict__ gam,
                           const float* __restrict__ bet,
                           float* __restrict__ out) {
    __shared__ float redS[8], redS2[8];
    int row = blockIdx.x;
    const float* or_ = o2 + (size_t)row * DM;
    const float* rr  = r1 + (size_t)row * DM;
    const float* xr  = x  + (size_t)row * DM;
    float*       wr  = out + (size_t)row * DM;
    int tid = threadIdx.x;

    float a = or_[tid]       + rr[tid];
    float b = or_[tid + 256] + rr[tid + 256];
    float s  = a + b;
    float s2 = a * a + b * b;
#pragma unroll
    for (int off = 16; off; off >>= 1) {
        s  += __shfl_xor_sync(0xffffffffu, s,  off);
        s2 += __shfl_xor_sync(0xffffffffu, s2, off);
    }
    if ((tid & 31) == 0) { redS[tid >> 5] = s; redS2[tid >> 5] = s2; }
    __syncthreads();
    if (tid == 0) {
        float S = 0.f, S2 = 0.f;
#pragma unroll
        for (int w = 0; w < 8; w++) { S += redS[w]; S2 += redS2[w]; }
        redS[0] = S; redS2[0] = S2;
    }
    __syncthreads();
    float mu   = redS[0] * (1.f / 512.f);
    float var  = redS2[0] * (1.f / 512.f) - mu * mu;
    float rstd = rsqrtf(var + 1e-6f);
#pragma unroll
    for (int u = 0; u < 2; u++) {
        int col = tid + u * 256;
        float vv = u ? b : a;
        wr[col] = (vv - mu) * rstd * gam[col] + bet[col] + xr[col];
    }
}

// ====== GEMM core (bf16x3, 128x256 tile, A db + B reg-prefetch, 1 CTA/SM) ====
#define GIDESC2 ((1u << 4) | (1u << 7) | (1u << 10) | ((256u / 8) << 17) | ((128u / 16) << 24))
#define GEMM_DSMEM 133120   // A db 64KB + B 64KB = 128KB + slack

#if HAS_TC
__device__ __forceinline__ uint32_t gemm_mainloop_tc(
    const __nv_bfloat16* __restrict__ Ah, const __nv_bfloat16* __restrict__ Al,
    const __nv_bfloat16* __restrict__ Bh, const __nv_bfloat16* __restrict__ Bl,
    int m0, int n0, char* dsm_raw,
    uint64_t* s_mbar, uint32_t* s_tm,
    uint32_t tid, uint32_t wid)
{
    uint32_t raw = smem_u32(dsm_raw);
    uint32_t sb  = (raw + 1023) & ~1023u;
    char* dsm = dsm_raw + (sb - raw);

    uint32_t mb = smem_u32(&s_mbar[0]);
    if (wid == 0) { TC_ALLOC(smem_u32(s_tm), 256); TC_RELINQ(); }
    if (tid == 0) { MBAR_INIT(mb, 1); }
    __syncthreads();
    uint32_t tmem = s_tm[0];

    // layout: A buf0 @0 (AH 16K, AL 16K), A buf1 @32768, B @65536 (BH 32K, BL 32K)
    const uint32_t OFF_B = 65536u;

    // A role: thread handles row tid>>1, 4 groups of 16B
    int ra = (int)tid >> 1, ga2 = ((int)tid & 1) * 4;
    uint32_t soffA[4];
#pragma unroll
    for (int i = 0; i < 4; i++) {
        uint32_t o = (uint32_t)(ra * 128 + (ga2 + i) * 16);
        soffA[i] = o ^ ((o >> 3) & 0x70);
    }
    // B role: thread handles row tid (0..255), 8 groups of 16B
    uint32_t soffB[8];
#pragma unroll
    for (int i = 0; i < 8; i++) {
        uint32_t o = (uint32_t)((int)tid * 128 + i * 16);
        soffB[i] = o ^ ((o >> 3) & 0x70);
    }

    const __nv_bfloat16* Ahb = Ah + (size_t)m0 * DM;
    const __nv_bfloat16* Alb = Al + (size_t)m0 * DM;
    const __nv_bfloat16* Bhb = Bh + (size_t)n0 * DM;
    const __nv_bfloat16* Blb = Bl + (size_t)n0 * DM;

    uint4 rbh[8], rbl[8];   // B register prefetch (full 256-row tile / 256 thr)

    auto copyA = [&](int c, uint32_t boff) {
        int k0 = c * 64;
#pragma unroll
        for (int i = 0; i < 4; i++) {
            size_t ga = (size_t)ra * DM + k0 + (ga2 + i) * 8;
            *(uint4*)(dsm + boff + soffA[i])         = *(const uint4*)(Ahb + ga);
            *(uint4*)(dsm + boff + 16384 + soffA[i]) = *(const uint4*)(Alb + ga);
        }
    };
    auto ldB = [&](int c) {
        int k0 = c * 64;
#pragma unroll
        for (int i = 0; i < 8; i++) {
            size_t gb = (size_t)tid * DM + k0 + i * 8;
            rbh[i] = *(const uint4*)(Bhb + gb);
            rbl[i] = *(const uint4*)(Blb + gb);
        }
    };
    auto stsB = [&]() {
#pragma unroll
        for (int i = 0; i < 8; i++) {
            *(uint4*)(dsm + OFF_B + soffB[i])         = rbh[i];
            *(uint4*)(dsm + OFF_B + 32768 + soffB[i]) = rbl[i];
        }
    };
    auto issue = [&](uint32_t boff, uint32_t en0) {
        if (wid == 0 && elect1()) {
            FENCE_ASYNC_SHARED();
            uint64_t dah = make_desc_sw128(sb + boff);
            uint64_t dal = make_desc_sw128(sb + boff + 16384);
            uint64_t dbh = make_desc_sw128(sb + OFF_B);
            uint64_t dbl = make_desc_sw128(sb + OFF_B + 32768);
#pragma unroll
            for (int ks = 0; ks < 4; ks++) {
                mma_f16_ss(tmem, dah + ks * 2, dbh + ks * 2, GIDESC2,
                           (ks == 0) ? en0 : 1u);
                mma_f16_ss(tmem, dah + ks * 2, dbl + ks * 2, GIDESC2, 1u);
                mma_f16_ss(tmem, dal + ks * 2, dbh + ks * 2, GIDESC2, 1u);
            }
            TC_COMMIT(mb);
        }
    };

    // prologue
    copyA(0, 0);
    ldB(0);
    stsB();
    __syncthreads();
    issue(0, 0u);
    copyA(1, 32768u);
    ldB(1);

#pragma unroll 1
    for (int c = 1; c < 8; c++) {
        mbar_wait(mb, (uint32_t)((c - 1) & 1));   // MMA(c-1) done -> B smem free
        stsB();
        __syncthreads();
        issue((uint32_t)(c & 1) * 32768u, 1u);
        if (c < 7) {
            copyA(c + 1, (uint32_t)((c + 1) & 1) * 32768u);
            ldB(c + 1);
        }
    }
    mbar_wait(mb, 1u);
    TC_FENCE_AFTER();
    return tmem;
}
#else
__device__ __forceinline__ void gemm_mainloop_simt(
    const __nv_bfloat16* __restrict__ Ah, const __nv_bfloat16* __restrict__ Al,
    const __nv_bfloat16* __restrict__ Bh, const __nv_bfloat16* __restrict__ Bl,
    int m0, int n0, char* dsm_raw, uint32_t tid, float acc[8][8])
{
    float* As = (float*)dsm_raw;
    float* Ws = As + 2 * 8 * 132;
    int tx = tid & 15, ty = (int)(tid >> 4);
    int r = tid & 127;
    bool isA = tid < 128;
    const __nv_bfloat16* Ph = isA ? Ah + (size_t)(m0 + r) * DM
                                  : Bh + (size_t)(n0 + r) * DM;
    const __nv_bfloat16* Pl = isA ? Al + (size_t)(m0 + r) * DM
                                  : Bl + (size_t)(n0 + r) * DM;
    int stride = isA ? 132 : 128;
#pragma unroll
    for (int i = 0; i < 8; i++)
#pragma unroll
        for (int j = 0; j < 8; j++) acc[i][j] = 0.f;

    auto stage = [&](int buf, int k0) {
        uint4 vh = *(const uint4*)(Ph + k0);
        uint4 vl = *(const uint4*)(Pl + k0);
        const __nv_bfloat16* bh = (const __nv_bfloat16*)&vh;
        const __nv_bfloat16* bl = (const __nv_bfloat16*)&vl;
        float* dst = (isA ? As + buf * 8 * 132 : Ws + buf * 8 * 128) + r;
#pragma unroll
        for (int k = 0; k < 8; k++)
            dst[k * stride] = __bfloat162float(bh[k]) + __bfloat162float(bl[k]);
    };
    stage(0, 0);
    __syncthreads();
    int buf = 0;
#pragma unroll 1
    for (int k0 = 0; k0 < 512; k0 += 8) {
        if (k0 + 8 < 512) stage(buf ^ 1, k0 + 8);
#pragma unroll
        for (int kk = 0; kk < 8; kk++) {
            float av[8], bv[8];
            const float* ar = As + buf * 8 * 132 + kk * 132;
            const float* wr = Ws + buf * 8 * 128 + kk * 128;
            *(float4*)(av)     = *(const float4*)(ar + ty * 4);
            *(float4*)(av + 4) = *(const float4*)(ar + 64 + ty * 4);
            *(float4*)(bv)     = *(const float4*)(wr + tx * 4);
            *(float4*)(bv + 4) = *(const float4*)(wr + 64 + tx * 4);
#pragma unroll
            for (int i = 0; i < 8; i++)
#pragma unroll
                for (int j = 0; j < 8; j++) acc[i][j] += av[i] * bv[j];
        }
        __syncthreads();
        buf ^= 1;
    }
}
#endif

// ---------------- fused Q/K/V projection (128x256 tiles) ----------------
__global__ void __launch_bounds__(256, 1)
gemm_qkv_kernel(const __nv_bfloat16* __restrict__ Ah,
                const __nv_bfloat16* __restrict__ Al,
                const __nv_bfloat16* __restrict__ Wh,
                const __nv_bfloat16* __restrict__ Wl,
                __nv_bfloat16* __restrict__ Qh, __nv_bfloat16* __restrict__ Ql,
                __nv_bfloat16* __restrict__ Kh, __nv_bfloat16* __restrict__ Kl,
                __half* __restrict__ Vt, float qscale) {
    extern __shared__ char dsm_raw[];
    uint32_t tid = threadIdx.x, wid = tid >> 5, lid = tid & 31;
    int m0 = blockIdx.x * 128, n0 = blockIdx.y * 256;
    int z = blockIdx.z;
    const __nv_bfloat16* Bh = Wh + (size_t)z * DM * DM;
    const __nv_bfloat16* Bl = Wl + (size_t)z * DM * DM;
    float scale = (z == 0) ? qscale : 1.0f;

#if HAS_TC
    __shared__ __align__(16) uint64_t s_mbar[1];
    __shared__ uint32_t s_tm[1];
    uint32_t tmem = gemm_mainloop_tc(Ah, Al, Bh, Bl, m0, n0, dsm_raw,
                                     s_mbar, s_tm, tid, wid);
    int sub  = wid & 3;
    int nblk = (int)(wid >> 2);
    int row  = m0 + sub * 32 + (int)lid;
    int b = row >> 11, t = row & (SEQ - 1);

#pragma unroll
    for (int cb = 0; cb < 4; cb++) {
        int colb = nblk * 128 + cb * 32;
        uint32_t d[32];
        tc_ld_x32(d, tmem + colb);
        TC_WAIT_LD();

        if (z < 2) {
            __nv_bfloat16* Ch = (z == 0) ? Qh : Kh;
            __nv_bfloat16* Cl = (z == 0) ? Ql : Kl;
            size_t rowoff = (size_t)row * DM + n0 + colb;
            uint32_t hw[16], lw[16];
#pragma unroll
            for (int m = 0; m < 16; m++) {
                float v0 = __uint_as_float(d[2*m])   * scale;
                float v1 = __uint_as_float(d[2*m+1]) * scale;
                __nv_bfloat162 h2 = __floats2bfloat162_rn(v0, v1);
                __nv_bfloat162 l2 = __floats2bfloat162_rn(v0 - __bfloat162float(h2.x),
                                                          v1 - __bfloat162float(h2.y));
                hw[m] = *(uint32_t*)&h2; lw[m] = *(uint32_t*)&l2;
            }
#pragma unroll
            for (int u = 0; u < 4; u++) {
                *(uint4*)(Ch + rowoff + u * 8) =
                    make_uint4(hw[4*u], hw[4*u+1], hw[4*u+2], hw[4*u+3]);
                *(uint4*)(Cl + rowoff + u * 8) =
                    make_uint4(lw[4*u], lw[4*u+1], lw[4*u+2], lw[4*u+3]);
            }
        } else {
#pragma unroll
            for (int j = 0; j < 32; j++) {
                int c = n0 + colb + j;
                size_t o = ((size_t)((b << 3) + (c >> 6)) * 64 + (c & 63)) * SEQ + t;
                Vt[o] = __float2half(__uint_as_float(d[j]));
            }
        }
    }
    TC_FENCE_BEFORE();
    __syncthreads();
    if (wid == 0) TC_DEALLOC(tmem, 256);
#else
    for (int nh = 0; nh < 2; nh++) {
        float acc[8][8];
        gemm_mainloop_simt(Ah, Al, Bh, Bl, m0, n0 + nh * 128, dsm_raw, tid, acc);
        int tx = tid & 15, ty = (int)(tid >> 4);
#pragma unroll
        for (int i = 0; i < 8; i++) {
            int row = m0 + ((i < 4) ? (ty * 4 + i) : (64 + ty * 4 + i - 4));
#pragma unroll
            for (int j = 0; j < 8; j++) {
                int col = n0 + nh * 128 + ((j < 4) ? (tx * 4 + j) : (64 + tx * 4 + j - 4));
                float v = acc[i][j] * scale;
                if (z < 2) {
                    __nv_bfloat16* Ch = (z == 0) ? Qh : Kh;
                    __nv_bfloat16* Cl = (z == 0) ? Ql : Kl;
                    __nv_bfloat16 h = __float2bfloat16(v);
                    Ch[(size_t)row * DM + col] = h;
                    Cl[(size_t)row * DM + col] = __float2bfloat16(v - __bfloat162float(h));
                } else {
                    int b = row >> 11, t = row & (SEQ - 1);
                    size_t o = ((size_t)((b << 3) + (col >> 6)) * 64 + (col & 63)) * SEQ + t;
                    Vt[o] = __float2half(v);
                }
            }
        }
        __syncthreads();
    }
#endif
}

// ---------------- FC projection (fp32 out, 128x256 tiles) ----------------
__global__ void __launch_bounds__(256, 1)
gemm_fc_kernel(const __nv_bfloat16* __restrict__ Ah,
               const __nv_bfloat16* __restrict__ Al,
               const __nv_bfloat16* __restrict__ Bh,
               const __nv_bfloat16* __restrict__ Bl,
               float* __restrict__ C) {
    extern __shared__ char dsm_raw[];
    uint32_t tid = threadIdx.x, wid = tid >> 5, lid = tid & 31;
    int m0 = blockIdx.x * 128, n0 = blockIdx.y * 256;
#if HAS_TC
    __shared__ __align__(16) uint64_t s_mbar[1];
    __shared__ uint32_t s_tm[1];
    uint32_t tmem = gemm_mainloop_tc(Ah, Al, Bh, Bl, m0, n0, dsm_raw,
                                     s_mbar, s_tm, tid, wid);
    int sub  = wid & 3;
    int nblk = (int)(wid >> 2);
    int row  = m0 + sub * 32 + (int)lid;

#pragma unroll
    for (int cb = 0; cb < 4; cb++) {
        int colb = nblk * 128 + cb * 32;
        uint32_t d[32];
        tc_ld_x32(d, tmem + colb);
        TC_WAIT_LD();
        float* Cr = C + (size_t)row * DM + n0 + colb;
#pragma unroll
        for (int j = 0; j < 8; j++)
            *(float4*)(Cr + j * 4) = make_float4(
                __uint_as_float(d[4*j]),   __uint_as_float(d[4*j+1]),
                __uint_as_float(d[4*j+2]), __uint_as_float(d[4*j+3]));
    }
    TC_FENCE_BEFORE();
    __syncthreads();
    if (wid == 0) TC_DEALLOC(tmem, 256);
#else
    for (int nh = 0; nh < 2; nh++) {
        float acc[8][8];
        gemm_mainloop_simt(Ah, Al, Bh, Bl, m0, n0 + nh * 128, dsm_raw, tid, acc);
        int tx = tid & 15, ty = (int)(tid >> 4);
#pragma unroll
        for (int i = 0; i < 8; i++) {
            int row = m0 + ((i < 4) ? (ty * 4 + i) : (64 + ty * 4 + i - 4));
#pragma unroll
            for (int j = 0; j < 8; j++) {
                int col = n0 + nh * 128 + ((j < 4) ? (tx * 4 + j) : (64 + tx * 4 + j - 4));
                C[(size_t)row * DM + col] = acc[i][j];
            }
        }
        __syncthreads();
    }
#endif
}

// ========== attention (pipelined, triple-buffered V, cheap softmax) ==========
#define AIDESC_S  ((1u << 4) | (1u << 7) | (1u << 10) | ((64u / 8) << 17) | ((128u / 16) << 24))
#define AIDESC_PV ((1u << 4) | ((64u / 8) << 17) | ((128u / 16) << 24))
#define ATTN_DSMEM 108544

#if HAS_TC
__global__ void __launch_bounds__(256, 2)
attn_kernel(const __nv_bfloat16* __restrict__ Qh, const __nv_bfloat16* __restrict__ Ql,
            const __nv_bfloat16* __restrict__ Kh, const __nv_bfloat16* __restrict__ Kl,
            const __half* __restrict__ Vt,
            __nv_bfloat16* __restrict__ Oh, __nv_bfloat16* __restrict__ Ol) {
    extern __shared__ char dsm_raw[];
    __shared__ __align__(16) uint64_t s_mbar[3];
    __shared__ uint32_t s_tm[1];
    uint32_t tid = threadIdx.x, wid = tid >> 5, lane = tid & 31;
    int qt = (int)(gridDim.x - 1) - (int)blockIdx.x;
    int bh = blockIdx.y, bb = bh >> 3, hd = bh & 7;

    uint32_t raw = smem_u32(dsm_raw);
    uint32_t sb  = (raw + 1023) & ~1023u;
    char* dsm = dsm_raw + (sb - raw);

    const uint32_t OFF_QH = 0,     OFF_QL = 16384,
                   OFF_KH = 32768, OFF_KL = 49152,
                   OFF_V  = 65536,
                   OFF_P  = 90112,
                   OFF_L  = 106496;

    uint32_t mbS0 = smem_u32(&s_mbar[0]);
    uint32_t mbS1 = smem_u32(&s_mbar[1]);
    uint32_t mbPV = smem_u32(&s_mbar[2]);
    if (wid == 0) { TC_ALLOC(smem_u32(s_tm), 256); TC_RELINQ(); }
    if (tid == 0) { MBAR_INIT(mbS0, 1); MBAR_INIT(mbS1, 1); MBAR_INIT(mbPV, 1); }
    __syncthreads();
    uint32_t tmem = s_tm[0];

    size_t rowbase = (size_t)bb * SEQ;
    const __nv_bfloat16* khb = Kh + rowbase * DM + hd * 64;
    const __nv_bfloat16* klb = Kl + rowbase * DM + hd * 64;
    const __half*        vtb = Vt + ((size_t)bh * 64) * SEQ;

    int cr0 = (int)tid >> 3,         cg0 = ((int)tid & 7) * 8;
    int cr1 = (int)(tid + 256) >> 3, cg1 = (((int)tid + 256) & 7) * 8;
    uint32_t so0, so1;
    {
        uint32_t o0 = (uint32_t)(cr0 * 128 + cg0 * 2), o1 = (uint32_t)(cr1 * 128 + cg1 * 2);
        so0 = o0 ^ ((o0 >> 3) & 0x70);
        so1 = o1 ^ ((o1 >> 3) & 0x70);
    }

    {
        const __nv_bfloat16* qhp = Qh + (rowbase + (size_t)qt * 128) * DM + hd * 64;
        const __nv_bfloat16* qlp = Ql + (rowbase + (size_t)qt * 128) * DM + hd * 64;
#pragma unroll
        for (int i = 0; i < 4; i++) {
            int idx = i * 256 + (int)tid;
            int r = idx >> 3, g = idx & 7;
            uint32_t o = (uint32_t)(r * 128 + g * 16), so = o ^ ((o >> 3) & 0x70);
            *(uint4*)(dsm + OFF_QH + so) = *(const uint4*)(qhp + (size_t)r * DM + g * 8);
            *(uint4*)(dsm + OFF_QL + so) = *(const uint4*)(qlp + (size_t)r * DM + g * 8);
        }
        *(uint4*)(dsm + OFF_KH + so0) = *(const uint4*)(khb + (size_t)cr0 * DM + cg0);
        *(uint4*)(dsm + OFF_KH + so1) = *(const uint4*)(khb + (size_t)cr1 * DM + cg1);
        *(uint4*)(dsm + OFF_KL + so0) = *(const uint4*)(klb + (size_t)cr0 * DM + cg0);
        *(uint4*)(dsm + OFF_KL + so1) = *(const uint4*)(klb + (size_t)cr1 * DM + cg1);
        *(uint4*)(dsm + OFF_V  + so0) = *(const uint4*)(vtb + (size_t)cr0 * SEQ + cg0);
        *(uint4*)(dsm + OFF_V  + so1) = *(const uint4*)(vtb + (size_t)cr1 * SEQ + cg1);
    }

    int ktmax = 2 * qt + 1;

    uint4 pkh0, pkh1, pkl0, pkl1, pv0, pv1;
    {
        const __nv_bfloat16* khp = khb + (size_t)64 * DM;
        const __nv_bfloat16* klp = klb + (size_t)64 * DM;
        const __half*        vhp = vtb + 64;
        pkh0 = *(const uint4*)(khp + (size_t)cr0 * DM + cg0);
        pkh1 = *(const uint4*)(khp + (size_t)cr1 * DM + cg1);
        pkl0 = *(const uint4*)(klp + (size_t)cr0 * DM + cg0);
        pkl1 = *(const uint4*)(klp + (size_t)cr1 * DM + cg1);
        pv0  = *(const uint4*)(vhp + (size_t)cr0 * SEQ + cg0);
        pv1  = *(const uint4*)(vhp + (size_t)cr1 * SEQ + cg1);
    }
    __syncthreads();

    uint64_t dqh = make_desc_sw128(sb + OFF_QH);
    uint64_t dql = make_desc_sw128(sb + OFF_QL);

    if (wid == 0 && elect1()) {
        FENCE_ASYNC_SHARED();
        uint64_t dkh = make_desc_sw128(sb + OFF_KH);
        uint64_t dkl = make_desc_sw128(sb + OFF_KL);
#pragma unroll
        for (int ks = 0; ks < 4; ks++)
            mma_f16_ss(tmem, dqh + ks * 2, dkh + ks * 2, AIDESC_S, ks ? 1u : 0u);
#pragma unroll
        for (int ks = 0; ks < 4; ks++)
            mma_f16_ss(tmem, dqh + ks * 2, dkl + ks * 2, AIDESC_S, 1u);
#pragma unroll
        for (int ks = 0; ks < 4; ks++)
            mma_f16_ss(tmem, dql + ks * 2, dkh + ks * 2, AIDESC_S, 1u);
        TC_COMMIT(mbS0);
    }

    int sub = wid & 3, half = (int)(wid >> 2);
    int rl = sub * 32 + (int)lane;
    int grow = qt * 128 + rl;
    float lsum = 0.f;
    uint32_t phS0 = 0, phS1 = 0, phPV = 0;
    int vslot = 0;

#pragma unroll 1
    for (int kt = 0; kt <= ktmax; kt++) {
        int buf = kt & 1;

        if (kt < ktmax) {
            int nbuf = buf ^ 1;
            int nvslot = vslot + 1; if (nvslot == 3) nvslot = 0;
            uint32_t kb   = OFF_KH + (uint32_t)nbuf * 8192u;
            uint32_t klb2 = OFF_KL + (uint32_t)nbuf * 8192u;
            uint32_t vb   = OFF_V  + (uint32_t)nvslot * 8192u;
            *(uint4*)(dsm + kb   + so0) = pkh0;
            *(uint4*)(dsm + kb   + so1) = pkh1;
            *(uint4*)(dsm + klb2 + so0) = pkl0;
            *(uint4*)(dsm + klb2 + so1) = pkl1;
            *(uint4*)(dsm + vb   + so0) = pv0;
            *(uint4*)(dsm + vb   + so1) = pv1;
            __syncthreads();
            if (wid == 0 && elect1()) {
                FENCE_ASYNC_SHARED();
                uint64_t dkh = make_desc_sw128(sb + kb);
                uint64_t dkl = make_desc_sw128(sb + klb2);
                uint32_t stm = tmem + (uint32_t)nbuf * 64u;
#pragma unroll
                for (int ks = 0; ks < 4; ks++)
                    mma_f16_ss(stm, dqh + ks * 2, dkh + ks * 2, AIDESC_S, ks ? 1u : 0u);
#pragma unroll
                for (int ks = 0; ks < 4; ks++)
                    mma_f16_ss(stm, dqh + ks * 2, dkl + ks * 2, AIDESC_S, 1u);
#pragma unroll
                for (int ks = 0; ks < 4; ks++)
                    mma_f16_ss(stm, dql + ks * 2, dkh + ks * 2, AIDESC_S, 1u);
                TC_COMMIT(nbuf == 0 ? mbS0 : mbS1);
            }
            if (kt + 2 <= ktmax) {
                const __nv_bfloat16* khp = khb + (size_t)(kt + 2) * 64 * DM;
                const __nv_bfloat16* klp = klb + (size_t)(kt + 2) * 64 * DM;
                const __half*        vhp = vtb + (size_t)(kt + 2) * 64;
                pkh0 = *(const uint4*)(khp + (size_t)cr0 * DM + cg0);
                pkh1 = *(const uint4*)(khp + (size_t)cr1 * DM + cg1);
                pkl0 = *(const uint4*)(klp + (size_t)cr0 * DM + cg0);
                pkl1 = *(const uint4*)(klp + (size_t)cr1 * DM + cg1);
                pv0  = *(const uint4*)(vhp + (size_t)cr0 * SEQ + cg0);
                pv1  = *(const uint4*)(vhp + (size_t)cr1 * SEQ + cg1);
            }
        }

        if (buf == 0) { mbar_wait(mbS0, phS0); phS0 ^= 1; }
        else          { mbar_wait(mbS1, phS1); phS1 ^= 1; }
        TC_FENCE_AFTER();

        uint32_t sreg[32];
        tc_ld_x32(sreg, tmem + (uint32_t)buf * 64u + half * 32);
        TC_WAIT_LD();

        if (kt >= 1) { mbar_wait(mbPV, phPV); phPV ^= 1; }

        int jmax = grow - (kt * 64 + half * 32);
        uint32_t pbase = (uint32_t)(rl * 128 + half * 64);
        if (jmax >= 31) {
#pragma unroll
            for (int gj = 0; gj < 4; gj++) {
                uint32_t w[4];
#pragma unroll
                for (int m = 0; m < 4; m++) {
                    int j0 = gj * 8 + m * 2;
                    float p0 = fexp2(__uint_as_float(sreg[j0]));
                    float p1 = fexp2(__uint_as_float(sreg[j0 + 1]));
                    lsum += p0 + p1;
                    __half2 h2 = __floats2half2_rn(p0, p1);
                    w[m] = *(uint32_t*)&h2;
                }
                uint32_t o = pbase + gj * 16, so = o ^ ((o >> 3) & 0x70);
                *(uint4*)(dsm + OFF_P + so) = make_uint4(w[0], w[1], w[2], w[3]);
            }
        } else {
#pragma unroll
            for (int gj = 0; gj < 4; gj++) {
                uint32_t w[4];
#pragma unroll
                for (int m = 0; m < 4; m++) {
                    int j0 = gj * 8 + m * 2;
                    float p0 = (j0     <= jmax) ? fexp2(__uint_as_float(sreg[j0]))     : 0.f;
                    float p1 = (j0 + 1 <= jmax) ? fexp2(__uint_as_float(sreg[j0 + 1])) : 0.f;
                    lsum += p0 + p1;
                    __half2 h2 = __floats2half2_rn(p0, p1);
                    w[m] = *(uint32_t*)&h2;
                }
                uint32_t o = pbase + gj * 16, so = o ^ ((o >> 3) & 0x70);
                *(uint4*)(dsm + OFF_P + so) = make_uint4(w[0], w[1], w[2], w[3]);
            }
        }
        __syncthreads();

        if (wid == 0 && elect1()) {
            FENCE_ASYNC_SHARED();
            uint64_t dp = make_desc_sw128(sb + OFF_P);
            uint64_t dv = make_desc_sw128(sb + OFF_V + (uint32_t)vslot * 8192u);
#pragma unroll
            for (int ks = 0; ks < 4; ks++)
                mma_f16_ss(tmem + 128, dp + ks * 2, dv + ks * 2, AIDESC_PV,
                           (kt == 0 && ks == 0) ? 0u : 1u);
            TC_COMMIT(mbPV);
        }
        vslot++; if (vslot == 3) vslot = 0;
    }

    mbar_wait(mbPV, phPV);
    TC_FENCE_AFTER();

    float* sl = (float*)(dsm + OFF_L);
    sl[rl * 2 + half] = lsum;
    __syncthreads();
    float inv = 1.f / (sl[rl * 2] + sl[rl * 2 + 1]);

    uint32_t oreg[32];
    tc_ld_x32(oreg, tmem + 128 + half * 32);
    TC_WAIT_LD();
    TC_FENCE_BEFORE();

    size_t obase = (rowbase + (size_t)grow) * DM + hd * 64 + half * 32;
    uint32_t hw[16], lw[16];
#pragma unroll
    for (int m = 0; m < 16; m++) {
        float v0 = __uint_as_float(oreg[2*m])   * inv;
        float v1 = __uint_as_float(oreg[2*m+1]) * inv;
        __nv_bfloat162 h2 = __floats2bfloat162_rn(v0, v1);
        __nv_bfloat162 l2 = __floats2bfloat162_rn(v0 - __bfloat162float(h2.x),
                                                  v1 - __bfloat162float(h2.y));
        hw[m] = *(uint32_t*)&h2; lw[m] = *(uint32_t*)&l2;
    }
#pragma unroll
    for (int u = 0; u < 4; u++) {
        *(uint4*)(Oh + obase + u * 8) = make_uint4(hw[4*u], hw[4*u+1], hw[4*u+2], hw[4*u+3]);
        *(uint4*)(Ol + obase + u * 8) = make_uint4(lw[4*u], lw[4*u+1], lw[4*u+2], lw[4*u+3]);
    }
    __syncthreads();
    if (wid == 0) TC_DEALLOC(tmem, 256);
}

#else  // ---------------- SIMT fallback attention ----------------
__global__ void __launch_bounds__(256)
attn_kernel(const __nv_bfloat16* __restrict__ Qh, const __nv_bfloat16* __restrict__ Ql,
            const __nv_bfloat16* __restrict__ Kh, const __nv_bfloat16* __restrict__ Kl,
            const __half* __restrict__ Vt,
            __nv_bfloat16* __restrict__ Oh, __nv_bfloat16* __restrict__ Ol) {
    extern __shared__ float sm[];
    float* sQ = sm;
    float* sK = sQ + 128 * 68;
    float* sV = sK + 64 * 68;
    float* sP = sV + 64 * 64;

    int qt = (int)(gridDim.x - 1) - (int)blockIdx.x;
    int bh = blockIdx.y;
    int bb = bh >> 3, hd = bh & 7;
    int tid = threadIdx.x;
    int tx = tid & 15, ty = tid >> 4;
    size_t base = ((size_t)bb * SEQ) * DM + (size_t)hd * DK;

    for (int idx = tid; idx < 128 * 64; idx += 256) {
        int r = idx >> 6, c = idx & 63;
        size_t o = base + (size_t)(qt * 128 + r) * DM + c;
        sQ[r * 68 + c] = __bfloat162float(Qh[o]) + __bfloat162float(Ql[o]);
    }

    float Oacc[8][4], m_i[8], l_i[8];
#pragma unroll
    for (int i = 0; i < 8; i++) {
        m_i[i] = -1e30f; l_i[i] = 0.f;
#pragma unroll
        for (int j = 0; j < 4; j++) Oacc[i][j] = 0.f;
    }

    int ktmax = 2 * qt + 1;
    for (int kt = 0; kt <= ktmax; kt++) {
        for (int idx = tid; idx < 64 * 64; idx += 256) {
            int r = idx >> 6, c = idx & 63;
            size_t ga = base + (size_t)(kt * 64 + r) * DM + c;
            sK[r * 68 + c] = __bfloat162float(Kh[ga]) + __bfloat162float(Kl[ga]);
            sV[r * 64 + c] = __half2float(Vt[((size_t)bh * 64 + c) * SEQ + kt * 64 + r]);
        }
        __syncthreads();

        float s[8][4];
#pragma unroll
        for (int i = 0; i < 8; i++)
#pragma unroll
            for (int j = 0; j < 4; j++) s[i][j] = 0.f;
#pragma unroll
        for (int d4 = 0; d4 < 16; d4++) {
            float4 kv[4];
#pragma unroll
            for (int j = 0; j < 4; j++)
                kv[j] = *(const float4*)&sK[(tx + 16 * j) * 68 + d4 * 4];
#pragma unroll
            for (int i = 0; i < 8; i++) {
                float4 qv = *(const float4*)&sQ[(ty + 16 * i) * 68 + d4 * 4];
#pragma unroll
                for (int j = 0; j < 4; j++)
                    s[i][j] += qv.x * kv[j].x + qv.y * kv[j].y +
                               qv.z * kv[j].z + qv.w * kv[j].w;
            }
        }
        if (kt >= 2 * qt) {
#pragma unroll
            for (int i = 0; i < 8; i++) {
                int grow = qt * 128 + ty + 16 * i;
#pragma unroll
                for (int j = 0; j < 4; j++)
                    if (kt * 64 + tx + 16 * j > grow) s[i][j] = -1e30f;
            }
        }
#pragma unroll
        for (int i = 0; i < 8; i++) {
            float mt = fmaxf(fmaxf(s[i][0], s[i][1]), fmaxf(s[i][2], s[i][3]));
#pragma unroll
            for (int off = 8; off; off >>= 1)
                mt = fmaxf(mt, __shfl_xor_sync(0xffffffffu, mt, off));
            float mn = fmaxf(m_i[i], mt);
            float corr = exp2f(m_i[i] - mn);
            m_i[i] = mn;
            float rs = 0.f;
#pragma unroll
            for (int j = 0; j < 4; j++) {
                float p = exp2f(s[i][j] - mn);
                s[i][j] = p; rs += p;
            }
#pragma unroll
            for (int off = 8; off; off >>= 1)
                rs += __shfl_xor_sync(0xffffffffu, rs, off);
            l_i[i] = l_i[i] * corr + rs;
#pragma unroll
            for (int j = 0; j < 4; j++) Oacc[i][j] *= corr;
#pragma unroll
            for (int j = 0; j < 4; j++)
                sP[(ty + 16 * i) * 68 + tx + 16 * j] = s[i][j];
        }
        __syncthreads();
#pragma unroll 4
        for (int k = 0; k < 64; k += 4) {
            float4 vv0 = *(const float4*)&sV[(k + 0) * 64 + tx * 4];
            float4 vv1 = *(const float4*)&sV[(k + 1) * 64 + tx * 4];
            float4 vv2 = *(const float4*)&sV[(k + 2) * 64 + tx * 4];
            float4 vv3 = *(const float4*)&sV[(k + 3) * 64 + tx * 4];
#pragma unroll
            for (int i = 0; i < 8; i++) {
                float4 pv = *(const float4*)&sP[(ty + 16 * i) * 68 + k];
                Oacc[i][0] += pv.x * vv0.x + pv.y * vv1.x + pv.z * vv2.x + pv.w * vv3.x;
                Oacc[i][1] += pv.x * vv0.y + pv.y * vv1.y + pv.z * vv2.y + pv.w * vv3.y;
                Oacc[i][2] += pv.x * vv0.z + pv.y * vv1.z + pv.z * vv2.z + pv.w * vv3.z;
                Oacc[i][3] += pv.x * vv0.w + pv.y * vv1.w + pv.z * vv2.w + pv.w * vv3.w;
            }
        }
        __syncthreads();
    }
#pragma unroll
    for (int i = 0; i < 8; i++) {
        float inv = 1.f / l_i[i];
        size_t rowa = base + (size_t)(qt * 128 + ty + 16 * i) * DM + tx * 4;
#pragma unroll
        for (int j = 0; j < 4; j++) {
            float v = Oacc[i][j] * inv;
            __nv_bfloat16 h = __float2bfloat16(v);
            Oh[rowa + j] = h;
            Ol[rowa + j] = __float2bfloat16(v - __bfloat162float(h));
        }
    }
}
#endif

// ---------------- launch ----------------
extern "C" void kernel_launch(void* const* d_in, const int* in_sizes, int n_in,
                              void* d_out, int out_size) {
    const float* x     = (const float*)d_in[0];
    const float* ln1_g = (const float*)d_in[1];
    const float* ln1_b = (const float*)d_in[2];
    const float* wq    = (const float*)d_in[3];
    const float* wk    = (const float*)d_in[4];
    const float* wv    = (const float*)d_in[5];
    const float* wfc   = (const float*)d_in[6];
    const float* ln2_g = (const float*)d_in[7];
    const float* ln2_b = (const float*)d_in[8];
    float* out = (float*)d_out;

    float *ppe, *ph, *pfc;
    __nv_bfloat16 *pwh, *pwl, *pah, *pal, *pqh, *pql, *pkh, *pkl, *poh, *pol;
    __half *pvt;
    cudaGetSymbolAddress((void**)&ppe,  g_pe);
    cudaGetSymbolAddress((void**)&ph,   g_h);
    cudaGetSymbolAddress((void**)&pfc,  g_fc);
    cudaGetSymbolAddress((void**)&pwh,  g_wth);
    cudaGetSymbolAddress((void**)&pwl,  g_wtl);
    cudaGetSymbolAddress((void**)&pah,  g_ah);
    cudaGetSymbolAddress((void**)&pal,  g_al);
    cudaGetSymbolAddress((void**)&pqh,  g_qh);
    cudaGetSymbolAddress((void**)&pql,  g_ql);
    cudaGetSymbolAddress((void**)&pkh,  g_kh);
    cudaGetSymbolAddress((void**)&pkl,  g_kl);
    cudaGetSymbolAddress((void**)&poh,  g_oh);
    cudaGetSymbolAddress((void**)&pol,  g_ol);
    cudaGetSymbolAddress((void**)&pvt,  g_vt);

    cudaFuncSetAttribute(attn_kernel,
                         cudaFuncAttributeMaxDynamicSharedMemorySize, ATTN_DSMEM);
    cudaFuncSetAttribute(gemm_qkv_kernel,
                         cudaFuncAttributeMaxDynamicSharedMemorySize, GEMM_DSMEM);
    cudaFuncSetAttribute(gemm_fc_kernel,
                         cudaFuncAttributeMaxDynamicSharedMemorySize, GEMM_DSMEM);

    const float qscale = 0.125f * 1.4426950408889634f;

    // #1: wsplit x4
    wsplit4_kernel<<<dim3(16, 16, 4), 256>>>(wq, wk, wv, wfc, pwh, pwl);
    // #2: pe
    pe_kernel<<<256, 256>>>(ppe);
    // #3: ln1
    ln1_pos_kernel<<<ROWS, 256>>>(x, ln1_g, ln1_b, ppe, ph, pah, pal);
    // #4: fused q/k/v projections (128x256 tiles; ncu capture target)
    gemm_qkv_kernel<<<dim3(ROWS / 128, DM / 256, 3), 256, GEMM_DSMEM>>>(
        pah, pal, pwh, pwl, pqh, pql, pkh, pkl, pvt, qscale);
    // #5: attention
    dim3 ga(SEQ / 128, BATCH * NH);
    attn_kernel<<<ga, 256, ATTN_DSMEM>>>(pqh, pql, pkh, pkl, pvt, poh, pol);
    // #6: fc
    gemm_fc_kernel<<<dim3(ROWS / 128, DM / 256), 256, GEMM_DSMEM>>>(
        poh, pol, pwh + 3 * (size_t)DM * DM, pwl + 3 * (size_t)DM * DM, pfc);
    // #7: ln2
    ln2_kernel<<<ROWS, 256>>>(pfc, ph, x, ln2_g, ln2_b, out);
}

// round 15
// speedup vs baseline: 1.2433x; 1.2155x over previous
#include <cuda_runtime.h>
#include <cuda.h>
#include <cuda_bf16.h>
#include <cuda_fp16.h>
#include <math.h>
#include <stdint.h>

#define BATCH 4
#define SEQ   2048
#define DM    512
#define NH    8
#define DK    64
#define ROWS  (BATCH * SEQ)   // 8192

#if defined(__CUDA_ARCH_FEAT_SM103_ALL) || defined(__CUDA_ARCH_FEAT_SM100_ALL) || \
    defined(__CUDA_ARCH_SPECIFIC__) || defined(__CUDA_ARCH_FAMILY_SPECIFIC__)
#define HAS_TC 1
#else
#define HAS_TC 0
#endif

// ---------------- scratch ----------------
__device__ float g_pe[SEQ * DM];
__device__ float g_h [ROWS * DM];
__device__ float g_fc[ROWS * DM];
__device__ __nv_bfloat16 g_ah[ROWS * DM];
__device__ __nv_bfloat16 g_al[ROWS * DM];
__device__ __nv_bfloat16 g_qh[ROWS * DM];
__device__ __nv_bfloat16 g_ql[ROWS * DM];
__device__ __nv_bfloat16 g_kh[ROWS * DM];
__device__ __nv_bfloat16 g_kl[ROWS * DM];
__device__ __nv_bfloat16 g_oh[ROWS * DM];
__device__ __nv_bfloat16 g_ol[ROWS * DM];
__device__ __half        g_vt[BATCH * NH * DK * SEQ];   // V^T fp16 [bh][dim][key]
__device__ __nv_bfloat16 g_wth[4][DM * DM];
__device__ __nv_bfloat16 g_wtl[4][DM * DM];

// ================= helpers =================
__device__ __forceinline__ uint32_t smem_u32(const void* p) {
    uint32_t a;
    asm("{ .reg .u64 t; cvta.to.shared.u64 t, %1; cvt.u32.u64 %0, t; }"
        : "=r"(a) : "l"(p));
    return a;
}

// cheap exp2: magic-constant rounding + deg-4 poly. Valid for |x| < ~60.
__device__ __forceinline__ float fexp2(float x) {
    float z = x + 12582912.f;
    int   iz = __float_as_int(z);
    float f  = x - (z - 12582912.f);
    float p  = 9.6788e-3f;
    p = fmaf(p, f, 5.55041e-2f);
    p = fmaf(p, f, 2.402265e-1f);
    p = fmaf(p, f, 6.931472e-1f);
    p = fmaf(p, f, 1.0f);
    return p * __int_as_float((iz << 23) + 0x3F800000);
}

#if HAS_TC
__device__ __forceinline__ uint32_t elect1() {
    uint32_t p;
    asm volatile("{\n\t.reg .pred p;\n\telect.sync _|p, 0xFFFFFFFF;\n\t"
                 "selp.b32 %0, 1, 0, p;\n\t}" : "=r"(p));
    return p;
}
#define TC_ALLOC(smemaddr, ncols) \
    asm volatile("tcgen05.alloc.cta_group::1.sync.aligned.shared::cta.b32 [%0], %1;" \
                 :: "r"(smemaddr), "r"(ncols) : "memory")
#define TC_RELINQ() \
    asm volatile("tcgen05.relinquish_alloc_permit.cta_group::1.sync.aligned;")
#define TC_DEALLOC(tmem, ncols) \
    asm volatile("tcgen05.dealloc.cta_group::1.sync.aligned.b32 %0, %1;" \
                 :: "r"(tmem), "r"(ncols))
#define TC_COMMIT(mbar) \
    asm volatile("tcgen05.commit.cta_group::1.mbarrier::arrive::one.shared::cluster.b64 [%0];" \
                 :: "r"(mbar) : "memory")
#define TC_FENCE_AFTER()  asm volatile("tcgen05.fence::after_thread_sync;" ::: "memory")
#define TC_FENCE_BEFORE() asm volatile("tcgen05.fence::before_thread_sync;" ::: "memory")
#define TC_WAIT_LD()      asm volatile("tcgen05.wait::ld.sync.aligned;" ::: "memory")
#define FENCE_ASYNC_SHARED() asm volatile("fence.proxy.async.shared::cta;" ::: "memory")
#define MBAR_INIT(mbar, cnt) \
    asm volatile("mbarrier.init.shared.b64 [%0], %1;" :: "r"(mbar), "r"(cnt) : "memory")
#define MBAR_EXPECT_TX(mbar, bytes) \
    asm volatile("mbarrier.arrive.expect_tx.shared.b64 _, [%0], %1;" \
                 :: "r"(mbar), "r"(bytes) : "memory")
#define TMA_LOAD_2D(smem, map, x, y, mbar) \
    asm volatile("cp.async.bulk.tensor.2d.shared::cta.global.tile.mbarrier::complete_tx::bytes " \
                 "[%0], [%1, {%2, %3}], [%4];" \
                 :: "r"(smem), "l"(map), "r"(x), "r"(y), "r"(mbar) : "memory")

__device__ __forceinline__ void mbar_wait(uint32_t mbar, uint32_t parity) {
    asm volatile(
        "{\n\t.reg .pred P;\n\t"
        "WL_%=:\n\t"
        "mbarrier.try_wait.parity.acquire.cta.shared::cta.b64 P, [%0], %1, 0x989680;\n\t"
        "@P bra.uni WD_%=;\n\t"
        "bra.uni WL_%=;\n\t"
        "WD_%=:\n\t}"
        :: "r"(mbar), "r"(parity) : "memory");
}

__device__ __forceinline__ void tc_ld_x32(uint32_t* r, uint32_t tmem_addr) {
    asm volatile(
        "tcgen05.ld.sync.aligned.32x32b.x32.b32 "
        "{%0, %1, %2, %3, %4, %5, %6, %7, %8, %9, %10, %11, %12, %13, %14, %15, "
        " %16, %17, %18, %19, %20, %21, %22, %23, %24, %25, %26, %27, %28, %29, %30, %31}, [%32];"
        : "=r"(r[0]),  "=r"(r[1]),  "=r"(r[2]),  "=r"(r[3]),
          "=r"(r[4]),  "=r"(r[5]),  "=r"(r[6]),  "=r"(r[7]),
          "=r"(r[8]),  "=r"(r[9]),  "=r"(r[10]), "=r"(r[11]),
          "=r"(r[12]), "=r"(r[13]), "=r"(r[14]), "=r"(r[15]),
          "=r"(r[16]), "=r"(r[17]), "=r"(r[18]), "=r"(r[19]),
          "=r"(r[20]), "=r"(r[21]), "=r"(r[22]), "=r"(r[23]),
          "=r"(r[24]), "=r"(r[25]), "=r"(r[26]), "=r"(r[27]),
          "=r"(r[28]), "=r"(r[29]), "=r"(r[30]), "=r"(r[31])
        : "r"(tmem_addr));
}

__device__ __forceinline__ void mma_f16_ss(uint32_t d, uint64_t a, uint64_t b,
                                           uint32_t idesc, uint32_t en) {
    asm volatile(
        "{\n\t.reg .pred p;\n\tsetp.ne.u32 p, %4, 0;\n\t"
        "tcgen05.mma.cta_group::1.kind::f16 [%0], %1, %2, %3, {%5, %5, %5, %5}, p;\n\t}"
        :: "r"(d), "l"(a), "l"(b), "r"(idesc), "r"(en), "r"(0u) : "memory");
}

static __device__ __forceinline__ uint64_t make_desc_sw128(uint32_t base) {
    const uint64_t BASE =
        (uint64_t(2) << 61) | (uint64_t(1) << 46) | (uint64_t(64) << 32) | (uint64_t(1) << 16);
    return BASE | ((uint64_t)(base >> 4) & 0x3FFF);
}
#endif  // HAS_TC

// ---------------- wsplit x4 (launch #1) ----------------
__global__ void wsplit4_kernel(const float* __restrict__ W0,
                               const float* __restrict__ W1,
                               const float* __restrict__ W2,
                               const float* __restrict__ W3,
                               __nv_bfloat16* __restrict__ Th,
                               __nv_bfloat16* __restrict__ Tl) {
    __shared__ float t[32][33];
    int z = blockIdx.z;
    int tid = threadIdx.x;
    const float* W = (z == 0) ? W0 : (z == 1) ? W1 : (z == 2) ? W2 : W3;
    __nv_bfloat16* th = Th + (size_t)z * DM * DM;
    __nv_bfloat16* tl = Tl + (size_t)z * DM * DM;
    int n0 = blockIdx.x * 32, k0 = blockIdx.y * 32;
    int tx = tid & 31, ty = tid >> 5;
#pragma unroll
    for (int i = 0; i < 32; i += 8)
        t[ty + i][tx] = W[(size_t)(k0 + ty + i) * DM + n0 + tx];
    __syncthreads();
#pragma unroll
    for (int i = 0; i < 32; i += 8) {
        float v = t[tx][ty + i];
        __nv_bfloat16 h = __float2bfloat16(v);
        __nv_bfloat16 l = __float2bfloat16(v - __bfloat162float(h));
        size_t o = (size_t)(n0 + ty + i) * DM + k0 + tx;
        th[o] = h; tl[o] = l;
    }
}

// ---------------- positional encoding (launch #2) ----------------
__global__ void pe_kernel(float* __restrict__ pe) {
    int tid = threadIdx.x;
    int trow = blockIdx.x * 8 + (tid >> 5);
    int lane = tid & 31;
    const double c = -(9.210340371976184 / 512.0);
#pragma unroll
    for (int u = 0; u < 16; u++) {
        int col = lane * 16 + u;
        int i2  = col & ~1;
        double arg = (double)trow * exp((double)i2 * c);
        pe[trow * DM + col] = (col & 1) ? (float)cos(arg) : (float)sin(arg);
    }
}

// ---------------- LN1 + pe (+ bf16 split of h) ----------------
__global__ void ln1_pos_kernel(const float* __restrict__ x,
                               const float* __restrict__ gam,
                               const float* __restrict__ bet,
                               const float* __restrict__ pe,
                               float* __restrict__ h,
                               __nv_bfloat16* __restrict__ hh,
                               __nv_bfloat16* __restrict__ hl) {
    __shared__ float redS[8], redS2[8];
    int row = blockIdx.x;
    int t   = row & (SEQ - 1);
    const float* xr = x  + (size_t)row * DM;
    const float* pr = pe + (size_t)t   * DM;
    int tid = threadIdx.x;

    float a = xr[tid], b = xr[tid + 256];
    float s  = a + b;
    float s2 = a * a + b * b;
#pragma unroll
    for (int off = 16; off; off >>= 1) {
        s  += __shfl_xor_sync(0xffffffffu, s,  off);
        s2 += __shfl_xor_sync(0xffffffffu, s2, off);
    }
    if ((tid & 31) == 0) { redS[tid >> 5] = s; redS2[tid >> 5] = s2; }
    __syncthreads();
    if (tid == 0) {
        float S = 0.f, S2 = 0.f;
#pragma unroll
        for (int w = 0; w < 8; w++) { S += redS[w]; S2 += redS2[w]; }
        redS[0] = S; redS2[0] = S2;
    }
    __syncthreads();
    float mu   = redS[0] * (1.f / 512.f);
    float var  = redS2[0] * (1.f / 512.f) - mu * mu;
    float rstd = rsqrtf(var + 1e-5f);
#pragma unroll
    for (int u = 0; u < 2; u++) {
        int col = tid + u * 256;
        float xv = u ? b : a;
        float hv = (xv - mu) * rstd * gam[col] + bet[col] + pr[col];
        size_t o = (size_t)row * DM + col;
        h[o] = hv;
        __nv_bfloat16 hi = __float2bfloat16(hv);
        hh[o] = hi;
        hl[o] = __float2bfloat16(hv - __bfloat162float(hi));
    }
}

// ---------------- LN2 + residuals ----------------
__global__ void ln2_kernel(const float* __restrict__ o2,
                           const float* __restrict__ r1,
                           const float* __restrict__ x,
                           const float* __restrict__ gam,
                           const float* __restrict__ bet,
                           float* __restrict__ out) {
    __shared__ float redS[8], redS2[8];
    int row = blockIdx.x;
    const float* or_ = o2 + (size_t)row * DM;
    const float* rr  = r1 + (size_t)row * DM;
    const float* xr  = x  + (size_t)row * DM;
    float*       wr  = out + (size_t)row * DM;
    int tid = threadIdx.x;

    float a = or_[tid]       + rr[tid];
    float b = or_[tid + 256] + rr[tid + 256];
    float s  = a + b;
    float s2 = a * a + b * b;
#pragma unroll
    for (int off = 16; off; off >>= 1) {
        s  += __shfl_xor_sync(0xffffffffu, s,  off);
        s2 += __shfl_xor_sync(0xffffffffu, s2, off);
    }
    if ((tid & 31) == 0) { redS[tid >> 5] = s; redS2[tid >> 5] = s2; }
    __syncthreads();
    if (tid == 0) {
        float S = 0.f, S2 = 0.f;
#pragma unroll
        for (int w = 0; w < 8; w++) { S += redS[w]; S2 += redS2[w]; }
        redS[0] = S; redS2[0] = S2;
    }
    __syncthreads();
    float mu   = redS[0] * (1.f / 512.f);
    float var  = redS2[0] * (1.f / 512.f) - mu * mu;
    float rstd = rsqrtf(var + 1e-6f);
#pragma unroll
    for (int u = 0; u < 2; u++) {
        int col = tid + u * 256;
        float vv = u ? b : a;
        wr[col] = (vv - mu) * rstd * gam[col] + bet[col] + xr[col];
    }
}

// ====== GEMM core (bf16x3, 128x256 tile, TMA-fed 2-stage pipeline) ====
#define GIDESC2 ((1u << 4) | (1u << 7) | (1u << 10) | ((256u / 8) << 17) | ((128u / 16) << 24))
#define GEMM_DSMEM 197632   // 2 x 96KB stages + 1KB align slack
#define STAGE_B   98304u
#define CHUNK_TX  98304u

#if HAS_TC
// Single elected thread drives TMA + MMA for the whole 128x256xK=512 tile.
__device__ __forceinline__ uint32_t gemm_mainloop_tma(
    const CUtensorMap* mAh, const CUtensorMap* mAl,
    const CUtensorMap* mWh, const CUtensorMap* mWl,
    int m0, int ny, char* dsm_raw,
    uint64_t* s_mbar, uint32_t* s_tm, uint32_t tid, uint32_t wid)
{
    uint32_t raw = smem_u32(dsm_raw);
    uint32_t sb  = (raw + 1023) & ~1023u;

    uint32_t mbF0 = smem_u32(&s_mbar[0]);
    uint32_t mbF1 = smem_u32(&s_mbar[1]);
    uint32_t mbD0 = smem_u32(&s_mbar[2]);
    uint32_t mbD1 = smem_u32(&s_mbar[3]);

    if (wid == 0) { TC_ALLOC(smem_u32(s_tm), 256); TC_RELINQ(); }
    if (tid == 0) {
        MBAR_INIT(mbF0, 1); MBAR_INIT(mbF1, 1);
        MBAR_INIT(mbD0, 1); MBAR_INIT(mbD1, 1);
    }
    __syncthreads();
    uint32_t tmem = s_tm[0];

    const uint32_t OAH = 0, OAL = 16384, OBH = 32768, OBL = 65536;

    if (wid == 0 && elect1()) {
        // prologue: load chunks 0,1
#pragma unroll
        for (int s = 0; s < 2; s++) {
            uint32_t base = sb + (uint32_t)s * STAGE_B;
            uint32_t mb = s ? mbF1 : mbF0;
            MBAR_EXPECT_TX(mb, CHUNK_TX);
            int k0 = s * 64;
            TMA_LOAD_2D(base + OAH, mAh, k0, m0, mb);
            TMA_LOAD_2D(base + OAL, mAl, k0, m0, mb);
            TMA_LOAD_2D(base + OBH, mWh, k0, ny, mb);
            TMA_LOAD_2D(base + OBL, mWl, k0, ny, mb);
        }
        uint32_t phF0 = 0, phF1 = 0, phD0 = 0, phD1 = 0;
#pragma unroll 1
        for (int c = 0; c < 8; c++) {
            int b = c & 1;
            if (b == 0) { mbar_wait(mbF0, phF0); phF0 ^= 1; }
            else        { mbar_wait(mbF1, phF1); phF1 ^= 1; }
            uint32_t base = sb + (uint32_t)b * STAGE_B;
            uint64_t dah = make_desc_sw128(base + OAH);
            uint64_t dal = make_desc_sw128(base + OAL);
            uint64_t dbh = make_desc_sw128(base + OBH);
            uint64_t dbl = make_desc_sw128(base + OBL);
#pragma unroll
            for (int ks = 0; ks < 4; ks++) {
                mma_f16_ss(tmem, dah + ks * 2, dbh + ks * 2, GIDESC2,
                           (c == 0 && ks == 0) ? 0u : 1u);
                mma_f16_ss(tmem, dah + ks * 2, dbl + ks * 2, GIDESC2, 1u);
                mma_f16_ss(tmem, dal + ks * 2, dbh + ks * 2, GIDESC2, 1u);
            }
            TC_COMMIT(b ? mbD1 : mbD0);
            if (c >= 1 && c <= 6) {
                int pb = b ^ 1;                       // stage of chunk c-1
                if (pb == 0) { mbar_wait(mbD0, phD0); phD0 ^= 1; }
                else         { mbar_wait(mbD1, phD1); phD1 ^= 1; }
                uint32_t pbase = sb + (uint32_t)pb * STAGE_B;
                uint32_t mb = pb ? mbF1 : mbF0;
                MBAR_EXPECT_TX(mb, CHUNK_TX);
                int k0 = (c + 1) * 64;
                TMA_LOAD_2D(pbase + OAH, mAh, k0, m0, mb);
                TMA_LOAD_2D(pbase + OAL, mAl, k0, m0, mb);
                TMA_LOAD_2D(pbase + OBH, mWh, k0, ny, mb);
                TMA_LOAD_2D(pbase + OBL, mWl, k0, ny, mb);
            }
        }
        mbar_wait(mbD1, phD1);   // MMA(7) done (4th commit on done[1])
    }
    __syncthreads();
    TC_FENCE_AFTER();
    return tmem;
}
#else
__device__ __forceinline__ void gemm_mainloop_simt(
    const __nv_bfloat16* __restrict__ Ah, const __nv_bfloat16* __restrict__ Al,
    const __nv_bfloat16* __restrict__ Bh, const __nv_bfloat16* __restrict__ Bl,
    int m0, int n0, char* dsm_raw, uint32_t tid, float acc[8][8])
{
    float* As = (float*)dsm_raw;
    float* Ws = As + 2 * 8 * 132;
    int tx = tid & 15, ty = (int)(tid >> 4);
    int r = tid & 127;
    bool isA = tid < 128;
    const __nv_bfloat16* Ph = isA ? Ah + (size_t)(m0 + r) * DM
                                  : Bh + (size_t)(n0 + r) * DM;
    const __nv_bfloat16* Pl = isA ? Al + (size_t)(m0 + r) * DM
                                  : Bl + (size_t)(n0 + r) * DM;
    int stride = isA ? 132 : 128;
#pragma unroll
    for (int i = 0; i < 8; i++)
#pragma unroll
        for (int j = 0; j < 8; j++) acc[i][j] = 0.f;

    auto stage = [&](int buf, int k0) {
        uint4 vh = *(const uint4*)(Ph + k0);
        uint4 vl = *(const uint4*)(Pl + k0);
        const __nv_bfloat16* bh = (const __nv_bfloat16*)&vh;
        const __nv_bfloat16* bl = (const __nv_bfloat16*)&vl;
        float* dst = (isA ? As + buf * 8 * 132 : Ws + buf * 8 * 128) + r;
#pragma unroll
        for (int k = 0; k < 8; k++)
            dst[k * stride] = __bfloat162float(bh[k]) + __bfloat162float(bl[k]);
    };
    stage(0, 0);
    __syncthreads();
    int buf = 0;
#pragma unroll 1
    for (int k0 = 0; k0 < 512; k0 += 8) {
        if (k0 + 8 < 512) stage(buf ^ 1, k0 + 8);
#pragma unroll
        for (int kk = 0; kk < 8; kk++) {
            float av[8], bv[8];
            const float* ar = As + buf * 8 * 132 + kk * 132;
            const float* wr = Ws + buf * 8 * 128 + kk * 128;
            *(float4*)(av)     = *(const float4*)(ar + ty * 4);
            *(float4*)(av + 4) = *(const float4*)(ar + 64 + ty * 4);
            *(float4*)(bv)     = *(const float4*)(wr + tx * 4);
            *(float4*)(bv + 4) = *(const float4*)(wr + 64 + tx * 4);
#pragma unroll
            for (int i = 0; i < 8; i++)
#pragma unroll
                for (int j = 0; j < 8; j++) acc[i][j] += av[i] * bv[j];
        }
        __syncthreads();
        buf ^= 1;
    }
}
#endif

// ---------------- fused Q/K/V projection (128x256 tiles, TMA) ----------------
__global__ void __launch_bounds__(256, 1)
gemm_qkv_kernel(const __grid_constant__ CUtensorMap mAh,
                const __grid_constant__ CUtensorMap mAl,
                const __grid_constant__ CUtensorMap mWh,
                const __grid_constant__ CUtensorMap mWl,
                const __nv_bfloat16* __restrict__ Ah,
                const __nv_bfloat16* __restrict__ Al,
                const __nv_bfloat16* __restrict__ Wh,
                const __nv_bfloat16* __restrict__ Wl,
                __nv_bfloat16* __restrict__ Qh, __nv_bfloat16* __restrict__ Ql,
                __nv_bfloat16* __restrict__ Kh, __nv_bfloat16* __restrict__ Kl,
                __half* __restrict__ Vt, float qscale) {
    extern __shared__ char dsm_raw[];
    uint32_t tid = threadIdx.x, wid = tid >> 5, lid = tid & 31;
    int m0 = blockIdx.x * 128, n0 = blockIdx.y * 256;
    int z = blockIdx.z;
    float scale = (z == 0) ? qscale : 1.0f;

#if HAS_TC
    __shared__ __align__(16) uint64_t s_mbar[4];
    __shared__ uint32_t s_tm[1];
    uint32_t tmem = gemm_mainloop_tma(&mAh, &mAl, &mWh, &mWl,
                                      m0, z * DM + n0, dsm_raw,
                                      s_mbar, s_tm, tid, wid);
    int sub  = wid & 3;
    int nblk = (int)(wid >> 2);
    int row  = m0 + sub * 32 + (int)lid;
    int b = row >> 11, t = row & (SEQ - 1);

#pragma unroll
    for (int cb = 0; cb < 4; cb++) {
        int colb = nblk * 128 + cb * 32;
        uint32_t d[32];
        tc_ld_x32(d, tmem + colb);
        TC_WAIT_LD();

        if (z < 2) {
            __nv_bfloat16* Ch = (z == 0) ? Qh : Kh;
            __nv_bfloat16* Cl = (z == 0) ? Ql : Kl;
            size_t rowoff = (size_t)row * DM + n0 + colb;
            uint32_t hw[16], lw[16];
#pragma unroll
            for (int m = 0; m < 16; m++) {
                float v0 = __uint_as_float(d[2*m])   * scale;
                float v1 = __uint_as_float(d[2*m+1]) * scale;
                __nv_bfloat162 h2 = __floats2bfloat162_rn(v0, v1);
                __nv_bfloat162 l2 = __floats2bfloat162_rn(v0 - __bfloat162float(h2.x),
                                                          v1 - __bfloat162float(h2.y));
                hw[m] = *(uint32_t*)&h2; lw[m] = *(uint32_t*)&l2;
            }
#pragma unroll
            for (int u = 0; u < 4; u++) {
                *(uint4*)(Ch + rowoff + u * 8) =
                    make_uint4(hw[4*u], hw[4*u+1], hw[4*u+2], hw[4*u+3]);
                *(uint4*)(Cl + rowoff + u * 8) =
                    make_uint4(lw[4*u], lw[4*u+1], lw[4*u+2], lw[4*u+3]);
            }
        } else {
#pragma unroll
            for (int j = 0; j < 32; j++) {
                int c = n0 + colb + j;
                size_t o = ((size_t)((b << 3) + (c >> 6)) * 64 + (c & 63)) * SEQ + t;
                Vt[o] = __float2half(__uint_as_float(d[j]));
            }
        }
    }
    TC_FENCE_BEFORE();
    __syncthreads();
    if (wid == 0) TC_DEALLOC(tmem, 256);
#else
    const __nv_bfloat16* Bh = Wh + (size_t)z * DM * DM;
    const __nv_bfloat16* Bl = Wl + (size_t)z * DM * DM;
    for (int nh = 0; nh < 2; nh++) {
        float acc[8][8];
        gemm_mainloop_simt(Ah, Al, Bh, Bl, m0, n0 + nh * 128, dsm_raw, tid, acc);
        int tx = tid & 15, ty = (int)(tid >> 4);
#pragma unroll
        for (int i = 0; i < 8; i++) {
            int row = m0 + ((i < 4) ? (ty * 4 + i) : (64 + ty * 4 + i - 4));
#pragma unroll
            for (int j = 0; j < 8; j++) {
                int col = n0 + nh * 128 + ((j < 4) ? (tx * 4 + j) : (64 + tx * 4 + j - 4));
                float v = acc[i][j] * scale;
                if (z < 2) {
                    __nv_bfloat16* Ch = (z == 0) ? Qh : Kh;
                    __nv_bfloat16* Cl = (z == 0) ? Ql : Kl;
                    __nv_bfloat16 h = __float2bfloat16(v);
                    Ch[(size_t)row * DM + col] = h;
                    Cl[(size_t)row * DM + col] = __float2bfloat16(v - __bfloat162float(h));
                } else {
                    int b = row >> 11, t = row & (SEQ - 1);
                    size_t o = ((size_t)((b << 3) + (col >> 6)) * 64 + (col & 63)) * SEQ + t;
                    Vt[o] = __float2half(v);
                }
            }
        }
        __syncthreads();
    }
#endif
}

// ---------------- FC projection (fp32 out, 128x256 tiles, TMA) ---------------
__global__ void __launch_bounds__(256, 1)
gemm_fc_kernel(const __grid_constant__ CUtensorMap mAh,
               const __grid_constant__ CUtensorMap mAl,
               const __grid_constant__ CUtensorMap mWh,
               const __grid_constant__ CUtensorMap mWl,
               const __nv_bfloat16* __restrict__ Ah,
               const __nv_bfloat16* __restrict__ Al,
               const __nv_bfloat16* __restrict__ Bh,
               const __nv_bfloat16* __restrict__ Bl,
               float* __restrict__ C) {
    extern __shared__ char dsm_raw[];
    uint32_t tid = threadIdx.x, wid = tid >> 5, lid = tid & 31;
    int m0 = blockIdx.x * 128, n0 = blockIdx.y * 256;
#if HAS_TC
    __shared__ __align__(16) uint64_t s_mbar[4];
    __shared__ uint32_t s_tm[1];
    uint32_t tmem = gemm_mainloop_tma(&mAh, &mAl, &mWh, &mWl,
                                      m0, 3 * DM + n0, dsm_raw,
                                      s_mbar, s_tm, tid, wid);
    int sub  = wid & 3;
    int nblk = (int)(wid >> 2);
    int row  = m0 + sub * 32 + (int)lid;

#pragma unroll
    for (int cb = 0; cb < 4; cb++) {
        int colb = nblk * 128 + cb * 32;
        uint32_t d[32];
        tc_ld_x32(d, tmem + colb);
        TC_WAIT_LD();
        float* Cr = C + (size_t)row * DM + n0 + colb;
#pragma unroll
        for (int j = 0; j < 8; j++)
            *(float4*)(Cr + j * 4) = make_float4(
                __uint_as_float(d[4*j]),   __uint_as_float(d[4*j+1]),
                __uint_as_float(d[4*j+2]), __uint_as_float(d[4*j+3]));
    }
    TC_FENCE_BEFORE();
    __syncthreads();
    if (wid == 0) TC_DEALLOC(tmem, 256);
#else
    for (int nh = 0; nh < 2; nh++) {
        float acc[8][8];
        gemm_mainloop_simt(Ah, Al, Bh, Bl, m0, n0 + nh * 128, dsm_raw, tid, acc);
        int tx = tid & 15, ty = (int)(tid >> 4);
#pragma unroll
        for (int i = 0; i < 8; i++) {
            int row = m0 + ((i < 4) ? (ty * 4 + i) : (64 + ty * 4 + i - 4));
#pragma unroll
            for (int j = 0; j < 8; j++) {
                int col = n0 + nh * 128 + ((j < 4) ? (tx * 4 + j) : (64 + tx * 4 + j - 4));
                C[(size_t)row * DM + col] = acc[i][j];
            }
        }
        __syncthreads();
    }
#endif
}

// ========== attention (pipelined, triple-buffered V, cheap softmax) ==========
#define AIDESC_S  ((1u << 4) | (1u << 7) | (1u << 10) | ((64u / 8) << 17) | ((128u / 16) << 24))
#define AIDESC_PV ((1u << 4) | ((64u / 8) << 17) | ((128u / 16) << 24))
#define ATTN_DSMEM 108544

#if HAS_TC
__global__ void __launch_bounds__(256, 2)
attn_kernel(const __nv_bfloat16* __restrict__ Qh, const __nv_bfloat16* __restrict__ Ql,
            const __nv_bfloat16* __restrict__ Kh, const __nv_bfloat16* __restrict__ Kl,
            const __half* __restrict__ Vt,
            __nv_bfloat16* __restrict__ Oh, __nv_bfloat16* __restrict__ Ol) {
    extern __shared__ char dsm_raw[];
    __shared__ __align__(16) uint64_t s_mbar[3];
    __shared__ uint32_t s_tm[1];
    uint32_t tid = threadIdx.x, wid = tid >> 5, lane = tid & 31;
    int qt = (int)(gridDim.x - 1) - (int)blockIdx.x;
    int bh = blockIdx.y, bb = bh >> 3, hd = bh & 7;

    uint32_t raw = smem_u32(dsm_raw);
    uint32_t sb  = (raw + 1023) & ~1023u;
    char* dsm = dsm_raw + (sb - raw);

    const uint32_t OFF_QH = 0,     OFF_QL = 16384,
                   OFF_KH = 32768, OFF_KL = 49152,
                   OFF_V  = 65536,
                   OFF_P  = 90112,
                   OFF_L  = 106496;

    uint32_t mbS0 = smem_u32(&s_mbar[0]);
    uint32_t mbS1 = smem_u32(&s_mbar[1]);
    uint32_t mbPV = smem_u32(&s_mbar[2]);
    if (wid == 0) { TC_ALLOC(smem_u32(s_tm), 256); TC_RELINQ(); }
    if (tid == 0) { MBAR_INIT(mbS0, 1); MBAR_INIT(mbS1, 1); MBAR_INIT(mbPV, 1); }
    __syncthreads();
    uint32_t tmem = s_tm[0];

    size_t rowbase = (size_t)bb * SEQ;
    const __nv_bfloat16* khb = Kh + rowbase * DM + hd * 64;
    const __nv_bfloat16* klb = Kl + rowbase * DM + hd * 64;
    const __half*        vtb = Vt + ((size_t)bh * 64) * SEQ;

    int cr0 = (int)tid >> 3,         cg0 = ((int)tid & 7) * 8;
    int cr1 = (int)(tid + 256) >> 3, cg1 = (((int)tid + 256) & 7) * 8;
    uint32_t so0, so1;
    {
        uint32_t o0 = (uint32_t)(cr0 * 128 + cg0 * 2), o1 = (uint32_t)(cr1 * 128 + cg1 * 2);
        so0 = o0 ^ ((o0 >> 3) & 0x70);
        so1 = o1 ^ ((o1 >> 3) & 0x70);
    }

    {
        const __nv_bfloat16* qhp = Qh + (rowbase + (size_t)qt * 128) * DM + hd * 64;
        const __nv_bfloat16* qlp = Ql + (rowbase + (size_t)qt * 128) * DM + hd * 64;
#pragma unroll
        for (int i = 0; i < 4; i++) {
            int idx = i * 256 + (int)tid;
            int r = idx >> 3, g = idx & 7;
            uint32_t o = (uint32_t)(r * 128 + g * 16), so = o ^ ((o >> 3) & 0x70);
            *(uint4*)(dsm + OFF_QH + so) = *(const uint4*)(qhp + (size_t)r * DM + g * 8);
            *(uint4*)(dsm + OFF_QL + so) = *(const uint4*)(qlp + (size_t)r * DM + g * 8);
        }
        *(uint4*)(dsm + OFF_KH + so0) = *(const uint4*)(khb + (size_t)cr0 * DM + cg0);
        *(uint4*)(dsm + OFF_KH + so1) = *(const uint4*)(khb + (size_t)cr1 * DM + cg1);
        *(uint4*)(dsm + OFF_KL + so0) = *(const uint4*)(klb + (size_t)cr0 * DM + cg0);
        *(uint4*)(dsm + OFF_KL + so1) = *(const uint4*)(klb + (size_t)cr1 * DM + cg1);
        *(uint4*)(dsm + OFF_V  + so0) = *(const uint4*)(vtb + (size_t)cr0 * SEQ + cg0);
        *(uint4*)(dsm + OFF_V  + so1) = *(const uint4*)(vtb + (size_t)cr1 * SEQ + cg1);
    }

    int ktmax = 2 * qt + 1;

    uint4 pkh0, pkh1, pkl0, pkl1, pv0, pv1;
    {
        const __nv_bfloat16* khp = khb + (size_t)64 * DM;
        const __nv_bfloat16* klp = klb + (size_t)64 * DM;
        const __half*        vhp = vtb + 64;
        pkh0 = *(const uint4*)(khp + (size_t)cr0 * DM + cg0);
        pkh1 = *(const uint4*)(khp + (size_t)cr1 * DM + cg1);
        pkl0 = *(const uint4*)(klp + (size_t)cr0 * DM + cg0);
        pkl1 = *(const uint4*)(klp + (size_t)cr1 * DM + cg1);
        pv0  = *(const uint4*)(vhp + (size_t)cr0 * SEQ + cg0);
        pv1  = *(const uint4*)(vhp + (size_t)cr1 * SEQ + cg1);
    }
    __syncthreads();

    uint64_t dqh = make_desc_sw128(sb + OFF_QH);
    uint64_t dql = make_desc_sw128(sb + OFF_QL);

    if (wid == 0 && elect1()) {
        FENCE_ASYNC_SHARED();
        uint64_t dkh = make_desc_sw128(sb + OFF_KH);
        uint64_t dkl = make_desc_sw128(sb + OFF_KL);
#pragma unroll
        for (int ks = 0; ks < 4; ks++)
            mma_f16_ss(tmem, dqh + ks * 2, dkh + ks * 2, AIDESC_S, ks ? 1u : 0u);
#pragma unroll
        for (int ks = 0; ks < 4; ks++)
            mma_f16_ss(tmem, dqh + ks * 2, dkl + ks * 2, AIDESC_S, 1u);
#pragma unroll
        for (int ks = 0; ks < 4; ks++)
            mma_f16_ss(tmem, dql + ks * 2, dkh + ks * 2, AIDESC_S, 1u);
        TC_COMMIT(mbS0);
    }

    int sub = wid & 3, half = (int)(wid >> 2);
    int rl = sub * 32 + (int)lane;
    int grow = qt * 128 + rl;
    float lsum = 0.f;
    uint32_t phS0 = 0, phS1 = 0, phPV = 0;
    int vslot = 0;

#pragma unroll 1
    for (int kt = 0; kt <= ktmax; kt++) {
        int buf = kt & 1;

        if (kt < ktmax) {
            int nbuf = buf ^ 1;
            int nvslot = vslot + 1; if (nvslot == 3) nvslot = 0;
            uint32_t kb   = OFF_KH + (uint32_t)nbuf * 8192u;
            uint32_t klb2 = OFF_KL + (uint32_t)nbuf * 8192u;
            uint32_t vb   = OFF_V  + (uint32_t)nvslot * 8192u;
            *(uint4*)(dsm + kb   + so0) = pkh0;
            *(uint4*)(dsm + kb   + so1) = pkh1;
            *(uint4*)(dsm + klb2 + so0) = pkl0;
            *(uint4*)(dsm + klb2 + so1) = pkl1;
            *(uint4*)(dsm + vb   + so0) = pv0;
            *(uint4*)(dsm + vb   + so1) = pv1;
            __syncthreads();
            if (wid == 0 && elect1()) {
                FENCE_ASYNC_SHARED();
                uint64_t dkh = make_desc_sw128(sb + kb);
                uint64_t dkl = make_desc_sw128(sb + klb2);
                uint32_t stm = tmem + (uint32_t)nbuf * 64u;
#pragma unroll
                for (int ks = 0; ks < 4; ks++)
                    mma_f16_ss(stm, dqh + ks * 2, dkh + ks * 2, AIDESC_S, ks ? 1u : 0u);
#pragma unroll
                for (int ks = 0; ks < 4; ks++)
                    mma_f16_ss(stm, dqh + ks * 2, dkl + ks * 2, AIDESC_S, 1u);
#pragma unroll
                for (int ks = 0; ks < 4; ks++)
                    mma_f16_ss(stm, dql + ks * 2, dkh + ks * 2, AIDESC_S, 1u);
                TC_COMMIT(nbuf == 0 ? mbS0 : mbS1);
            }
            if (kt + 2 <= ktmax) {
                const __nv_bfloat16* khp = khb + (size_t)(kt + 2) * 64 * DM;
                const __nv_bfloat16* klp = klb + (size_t)(kt + 2) * 64 * DM;
                const __half*        vhp = vtb + (size_t)(kt + 2) * 64;
                pkh0 = *(const uint4*)(khp + (size_t)cr0 * DM + cg0);
                pkh1 = *(const uint4*)(khp + (size_t)cr1 * DM + cg1);
                pkl0 = *(const uint4*)(klp + (size_t)cr0 * DM + cg0);
                pkl1 = *(const uint4*)(klp + (size_t)cr1 * DM + cg1);
                pv0  = *(const uint4*)(vhp + (size_t)cr0 * SEQ + cg0);
                pv1  = *(const uint4*)(vhp + (size_t)cr1 * SEQ + cg1);
            }
        }

        if (buf == 0) { mbar_wait(mbS0, phS0); phS0 ^= 1; }
        else          { mbar_wait(mbS1, phS1); phS1 ^= 1; }
        TC_FENCE_AFTER();

        uint32_t sreg[32];
        tc_ld_x32(sreg, tmem + (uint32_t)buf * 64u + half * 32);
        TC_WAIT_LD();

        if (kt >= 1) { mbar_wait(mbPV, phPV); phPV ^= 1; }

        int jmax = grow - (kt * 64 + half * 32);
        uint32_t pbase = (uint32_t)(rl * 128 + half * 64);
        if (jmax >= 31) {
#pragma unroll
            for (int gj = 0; gj < 4; gj++) {
                uint32_t w[4];
#pragma unroll
                for (int m = 0; m < 4; m++) {
                    int j0 = gj * 8 + m * 2;
                    float p0 = fexp2(__uint_as_float(sreg[j0]));
                    float p1 = fexp2(__uint_as_float(sreg[j0 + 1]));
                    lsum += p0 + p1;
                    __half2 h2 = __floats2half2_rn(p0, p1);
                    w[m] = *(uint32_t*)&h2;
                }
                uint32_t o = pbase + gj * 16, so = o ^ ((o >> 3) & 0x70);
                *(uint4*)(dsm + OFF_P + so) = make_uint4(w[0], w[1], w[2], w[3]);
            }
        } else {
#pragma unroll
            for (int gj = 0; gj < 4; gj++) {
                uint32_t w[4];
#pragma unroll
                for (int m = 0; m < 4; m++) {
                    int j0 = gj * 8 + m * 2;
                    float p0 = (j0     <= jmax) ? fexp2(__uint_as_float(sreg[j0]))     : 0.f;
                    float p1 = (j0 + 1 <= jmax) ? fexp2(__uint_as_float(sreg[j0 + 1])) : 0.f;
                    lsum += p0 + p1;
                    __half2 h2 = __floats2half2_rn(p0, p1);
                    w[m] = *(uint32_t*)&h2;
                }
                uint32_t o = pbase + gj * 16, so = o ^ ((o >> 3) & 0x70);
                *(uint4*)(dsm + OFF_P + so) = make_uint4(w[0], w[1], w[2], w[3]);
            }
        }
        __syncthreads();

        if (wid == 0 && elect1()) {
            FENCE_ASYNC_SHARED();
            uint64_t dp = make_desc_sw128(sb + OFF_P);
            uint64_t dv = make_desc_sw128(sb + OFF_V + (uint32_t)vslot * 8192u);
#pragma unroll
            for (int ks = 0; ks < 4; ks++)
                mma_f16_ss(tmem + 128, dp + ks * 2, dv + ks * 2, AIDESC_PV,
                           (kt == 0 && ks == 0) ? 0u : 1u);
            TC_COMMIT(mbPV);
        }
        vslot++; if (vslot == 3) vslot = 0;
    }

    mbar_wait(mbPV, phPV);
    TC_FENCE_AFTER();

    float* sl = (float*)(dsm + OFF_L);
    sl[rl * 2 + half] = lsum;
    __syncthreads();
    float inv = 1.f / (sl[rl * 2] + sl[rl * 2 + 1]);

    uint32_t oreg[32];
    tc_ld_x32(oreg, tmem + 128 + half * 32);
    TC_WAIT_LD();
    TC_FENCE_BEFORE();

    size_t obase = (rowbase + (size_t)grow) * DM + hd * 64 + half * 32;
    uint32_t hw[16], lw[16];
#pragma unroll
    for (int m = 0; m < 16; m++) {
        float v0 = __uint_as_float(oreg[2*m])   * inv;
        float v1 = __uint_as_float(oreg[2*m+1]) * inv;
        __nv_bfloat162 h2 = __floats2bfloat162_rn(v0, v1);
        __nv_bfloat162 l2 = __floats2bfloat162_rn(v0 - __bfloat162float(h2.x),
                                                  v1 - __bfloat162float(h2.y));
        hw[m] = *(uint32_t*)&h2; lw[m] = *(uint32_t*)&l2;
    }
#pragma unroll
    for (int u = 0; u < 4; u++) {
        *(uint4*)(Oh + obase + u * 8) = make_uint4(hw[4*u], hw[4*u+1], hw[4*u+2], hw[4*u+3]);
        *(uint4*)(Ol + obase + u * 8) = make_uint4(lw[4*u], lw[4*u+1], lw[4*u+2], lw[4*u+3]);
    }
    __syncthreads();
    if (wid == 0) TC_DEALLOC(tmem, 256);
}

#else  // ---------------- SIMT fallback attention ----------------
__global__ void __launch_bounds__(256)
attn_kernel(const __nv_bfloat16* __restrict__ Qh, const __nv_bfloat16* __restrict__ Ql,
            const __nv_bfloat16* __restrict__ Kh, const __nv_bfloat16* __restrict__ Kl,
            const __half* __restrict__ Vt,
            __nv_bfloat16* __restrict__ Oh, __nv_bfloat16* __restrict__ Ol) {
    extern __shared__ float sm[];
    float* sQ = sm;
    float* sK = sQ + 128 * 68;
    float* sV = sK + 64 * 68;
    float* sP = sV + 64 * 64;

    int qt = (int)(gridDim.x - 1) - (int)blockIdx.x;
    int bh = blockIdx.y;
    int bb = bh >> 3, hd = bh & 7;
    int tid = threadIdx.x;
    int tx = tid & 15, ty = tid >> 4;
    size_t base = ((size_t)bb * SEQ) * DM + (size_t)hd * DK;

    for (int idx = tid; idx < 128 * 64; idx += 256) {
        int r = idx >> 6, c = idx & 63;
        size_t o = base + (size_t)(qt * 128 + r) * DM + c;
        sQ[r * 68 + c] = __bfloat162float(Qh[o]) + __bfloat162float(Ql[o]);
    }

    float Oacc[8][4], m_i[8], l_i[8];
#pragma unroll
    for (int i = 0; i < 8; i++) {
        m_i[i] = -1e30f; l_i[i] = 0.f;
#pragma unroll
        for (int j = 0; j < 4; j++) Oacc[i][j] = 0.f;
    }

    int ktmax = 2 * qt + 1;
    for (int kt = 0; kt <= ktmax; kt++) {
        for (int idx = tid; idx < 64 * 64; idx += 256) {
            int r = idx >> 6, c = idx & 63;
            size_t ga = base + (size_t)(kt * 64 + r) * DM + c;
            sK[r * 68 + c] = __bfloat162float(Kh[ga]) + __bfloat162float(Kl[ga]);
            sV[r * 64 + c] = __half2float(Vt[((size_t)bh * 64 + c) * SEQ + kt * 64 + r]);
        }
        __syncthreads();

        float s[8][4];
#pragma unroll
        for (int i = 0; i < 8; i++)
#pragma unroll
            for (int j = 0; j < 4; j++) s[i][j] = 0.f;
#pragma unroll
        for (int d4 = 0; d4 < 16; d4++) {
            float4 kv[4];
#pragma unroll
            for (int j = 0; j < 4; j++)
                kv[j] = *(const float4*)&sK[(tx + 16 * j) * 68 + d4 * 4];
#pragma unroll
            for (int i = 0; i < 8; i++) {
                float4 qv = *(const float4*)&sQ[(ty + 16 * i) * 68 + d4 * 4];
#pragma unroll
                for (int j = 0; j < 4; j++)
                    s[i][j] += qv.x * kv[j].x + qv.y * kv[j].y +
                               qv.z * kv[j].z + qv.w * kv[j].w;
            }
        }
        if (kt >= 2 * qt) {
#pragma unroll
            for (int i = 0; i < 8; i++) {
                int grow = qt * 128 + ty + 16 * i;
#pragma unroll
                for (int j = 0; j < 4; j++)
                    if (kt * 64 + tx + 16 * j > grow) s[i][j] = -1e30f;
            }
        }
#pragma unroll
        for (int i = 0; i < 8; i++) {
            float mt = fmaxf(fmaxf(s[i][0], s[i][1]), fmaxf(s[i][2], s[i][3]));
#pragma unroll
            for (int off = 8; off; off >>= 1)
                mt = fmaxf(mt, __shfl_xor_sync(0xffffffffu, mt, off));
            float mn = fmaxf(m_i[i], mt);
            float corr = exp2f(m_i[i] - mn);
            m_i[i] = mn;
            float rs = 0.f;
#pragma unroll
            for (int j = 0; j < 4; j++) {
                float p = exp2f(s[i][j] - mn);
                s[i][j] = p; rs += p;
            }
#pragma unroll
            for (int off = 8; off; off >>= 1)
                rs += __shfl_xor_sync(0xffffffffu, rs, off);
            l_i[i] = l_i[i] * corr + rs;
#pragma unroll
            for (int j = 0; j < 4; j++) Oacc[i][j] *= corr;
#pragma unroll
            for (int j = 0; j < 4; j++)
                sP[(ty + 16 * i) * 68 + tx + 16 * j] = s[i][j];
        }
        __syncthreads();
#pragma unroll 4
        for (int k = 0; k < 64; k += 4) {
            float4 vv0 = *(const float4*)&sV[(k + 0) * 64 + tx * 4];
            float4 vv1 = *(const float4*)&sV[(k + 1) * 64 + tx * 4];
            float4 vv2 = *(const float4*)&sV[(k + 2) * 64 + tx * 4];
            float4 vv3 = *(const float4*)&sV[(k + 3) * 64 + tx * 4];
#pragma unroll
            for (int i = 0; i < 8; i++) {
                float4 pv = *(const float4*)&sP[(ty + 16 * i) * 68 + k];
                Oacc[i][0] += pv.x * vv0.x + pv.y * vv1.x + pv.z * vv2.x + pv.w * vv3.x;
                Oacc[i][1] += pv.x * vv0.y + pv.y * vv1.y + pv.z * vv2.y + pv.w * vv3.y;
                Oacc[i][2] += pv.x * vv0.z + pv.y * vv1.z + pv.z * vv2.z + pv.w * vv3.z;
                Oacc[i][3] += pv.x * vv0.w + pv.y * vv1.w + pv.z * vv2.w + pv.w * vv3.w;
            }
        }
        __syncthreads();
    }
#pragma unroll
    for (int i = 0; i < 8; i++) {
        float inv = 1.f / l_i[i];
        size_t rowa = base + (size_t)(qt * 128 + ty + 16 * i) * DM + tx * 4;
#pragma unroll
        for (int j = 0; j < 4; j++) {
            float v = Oacc[i][j] * inv;
            __nv_bfloat16 h = __float2bfloat16(v);
            Oh[rowa + j] = h;
            Ol[rowa + j] = __float2bfloat16(v - __bfloat162float(h));
        }
    }
}
#endif

// ---------------- host: tensormap encoding via driver entry point ------------
typedef CUresult (*PFN_cuTensorMapEncodeTiled_v12000)(
    CUtensorMap*, CUtensorMapDataType, cuuint32_t, void*,
    const cuuint64_t*, const cuuint64_t*, const cuuint32_t*, const cuuint32_t*,
    CUtensorMapInterleave, CUtensorMapSwizzle, CUtensorMapL2promotion,
    CUtensorMapFloatOOBfill);

static void encode_map(PFN_cuTensorMapEncodeTiled_v12000 fn, CUtensorMap* m,
                       void* base, unsigned long long d0, unsigned long long d1,
                       unsigned int b0, unsigned int b1) {
    cuuint64_t dims[2]    = {d0, d1};
    cuuint64_t strides[1] = {d0 * 2};           // bytes (bf16)
    cuuint32_t box[2]     = {b0, b1};
    cuuint32_t es[2]      = {1, 1};
    fn(m, CU_TENSOR_MAP_DATA_TYPE_BFLOAT16, 2, base, dims, strides, box, es,
       CU_TENSOR_MAP_INTERLEAVE_NONE, CU_TENSOR_MAP_SWIZZLE_128B,
       CU_TENSOR_MAP_L2_PROMOTION_L2_128B, CU_TENSOR_MAP_FLOAT_OOB_FILL_NONE);
}

// ---------------- launch ----------------
extern "C" void kernel_launch(void* const* d_in, const int* in_sizes, int n_in,
                              void* d_out, int out_size) {
    const float* x     = (const float*)d_in[0];
    const float* ln1_g = (const float*)d_in[1];
    const float* ln1_b = (const float*)d_in[2];
    const float* wq    = (const float*)d_in[3];
    const float* wk    = (const float*)d_in[4];
    const float* wv    = (const float*)d_in[5];
    const float* wfc   = (const float*)d_in[6];
    const float* ln2_g = (const float*)d_in[7];
    const float* ln2_b = (const float*)d_in[8];
    float* out = (float*)d_out;

    float *ppe, *ph, *pfc;
    __nv_bfloat16 *pwh, *pwl, *pah, *pal, *pqh, *pql, *pkh, *pkl, *poh, *pol;
    __half *pvt;
    cudaGetSymbolAddress((void**)&ppe,  g_pe);
    cudaGetSymbolAddress((void**)&ph,   g_h);
    cudaGetSymbolAddress((void**)&pfc,  g_fc);
    cudaGetSymbolAddress((void**)&pwh,  g_wth);
    cudaGetSymbolAddress((void**)&pwl,  g_wtl);
    cudaGetSymbolAddress((void**)&pah,  g_ah);
    cudaGetSymbolAddress((void**)&pal,  g_al);
    cudaGetSymbolAddress((void**)&pqh,  g_qh);
    cudaGetSymbolAddress((void**)&pql,  g_ql);
    cudaGetSymbolAddress((void**)&pkh,  g_kh);
    cudaGetSymbolAddress((void**)&pkl,  g_kl);
    cudaGetSymbolAddress((void**)&poh,  g_oh);
    cudaGetSymbolAddress((void**)&pol,  g_ol);
    cudaGetSymbolAddress((void**)&pvt,  g_vt);

    // tensormaps (host-side encode via driver entry point; no -lcuda needed)
    PFN_cuTensorMapEncodeTiled_v12000 enc = nullptr;
    {
        void* fn = nullptr;
        cudaDriverEntryPointQueryResult st;
        cudaGetDriverEntryPoint("cuTensorMapEncodeTiled", &fn,
                                cudaEnableDefault, &st);
        enc = (PFN_cuTensorMapEncodeTiled_v12000)fn;
    }
    CUtensorMap mAqh, mAql, mWh, mWl, mAoh, mAol;
    encode_map(enc, &mAqh, pah, DM, ROWS,    64, 128);
    encode_map(enc, &mAql, pal, DM, ROWS,    64, 128);
    encode_map(enc, &mWh,  pwh, DM, 4 * DM,  64, 256);
    encode_map(enc, &mWl,  pwl, DM, 4 * DM,  64, 256);
    encode_map(enc, &mAoh, poh, DM, ROWS,    64, 128);
    encode_map(enc, &mAol, pol, DM, ROWS,    64, 128);

    cudaFuncSetAttribute(attn_kernel,
                         cudaFuncAttributeMaxDynamicSharedMemorySize, ATTN_DSMEM);
    cudaFuncSetAttribute(gemm_qkv_kernel,
                         cudaFuncAttributeMaxDynamicSharedMemorySize, GEMM_DSMEM);
    cudaFuncSetAttribute(gemm_fc_kernel,
                         cudaFuncAttributeMaxDynamicSharedMemorySize, GEMM_DSMEM);

    const float qscale = 0.125f * 1.4426950408889634f;

    // #1: wsplit x4
    wsplit4_kernel<<<dim3(16, 16, 4), 256>>>(wq, wk, wv, wfc, pwh, pwl);
    // #2: pe
    pe_kernel<<<256, 256>>>(ppe);
    // #3: ln1
    ln1_pos_kernel<<<ROWS, 256>>>(x, ln1_g, ln1_b, ppe, ph, pah, pal);
    // #4: fused q/k/v projections (TMA mainloop; ncu capture target)
    gemm_qkv_kernel<<<dim3(ROWS / 128, DM / 256, 3), 256, GEMM_DSMEM>>>(
        mAqh, mAql, mWh, mWl,
        pah, pal, pwh, pwl, pqh, pql, pkh, pkl, pvt, qscale);
    // #5: attention
    dim3 ga(SEQ / 128, BATCH * NH);
    attn_kernel<<<ga, 256, ATTN_DSMEM>>>(pqh, pql, pkh, pkl, pvt, poh, pol);
    // #6: fc
    gemm_fc_kernel<<<dim3(ROWS / 128, DM / 256), 256, GEMM_DSMEM>>>(
        mAoh, mAol, mWh, mWl,
        poh, pol, pwh + 3 * (size_t)DM * DM, pwl + 3 * (size_t)DM * DM, pfc);
    // #7: ln2
    ln2_kernel<<<ROWS, 256>>>(pfc, ph, x, ln2_g, ln2_b, out);
}

// round 16
// speedup vs baseline: 1.3230x; 1.0642x over previous
#include <cuda_runtime.h>
#include <cuda.h>
#include <cuda_bf16.h>
#include <cuda_fp16.h>
#include <math.h>
#include <stdint.h>

#define BATCH 4
#define SEQ   2048
#define DM    512
#define NH    8
#define DK    64
#define ROWS  (BATCH * SEQ)   // 8192

#if defined(__CUDA_ARCH_FEAT_SM103_ALL) || defined(__CUDA_ARCH_FEAT_SM100_ALL) || \
    defined(__CUDA_ARCH_SPECIFIC__) || defined(__CUDA_ARCH_FAMILY_SPECIFIC__)
#define HAS_TC 1
#else
#define HAS_TC 0
#endif

// ---------------- scratch ----------------
__device__ float g_pe[SEQ * DM];
__device__ float g_h [ROWS * DM];
__device__ float g_fc[ROWS * DM];
__device__ __nv_bfloat16 g_ah[ROWS * DM];
__device__ __nv_bfloat16 g_al[ROWS * DM];
__device__ __nv_bfloat16 g_qh[ROWS * DM];
__device__ __nv_bfloat16 g_ql[ROWS * DM];
__device__ __nv_bfloat16 g_kh[ROWS * DM];
__device__ __nv_bfloat16 g_kl[ROWS * DM];
__device__ __nv_bfloat16 g_oh[ROWS * DM];
__device__ __nv_bfloat16 g_ol[ROWS * DM];
__device__ __half        g_vt[BATCH * NH * DK * SEQ];   // V^T fp16 [bh][dim][key]
__device__ __nv_bfloat16 g_wth[4][DM * DM];
__device__ __nv_bfloat16 g_wtl[4][DM * DM];

// ================= helpers =================
__device__ __forceinline__ uint32_t smem_u32(const void* p) {
    uint32_t a;
    asm("{ .reg .u64 t; cvta.to.shared.u64 t, %1; cvt.u32.u64 %0, t; }"
        : "=r"(a) : "l"(p));
    return a;
}

// cheap exp2: magic-constant rounding + deg-4 poly. Valid for |x| < ~60.
__device__ __forceinline__ float fexp2(float x) {
    float z = x + 12582912.f;
    int   iz = __float_as_int(z);
    float f  = x - (z - 12582912.f);
    float p  = 9.6788e-3f;
    p = fmaf(p, f, 5.55041e-2f);
    p = fmaf(p, f, 2.402265e-1f);
    p = fmaf(p, f, 6.931472e-1f);
    p = fmaf(p, f, 1.0f);
    return p * __int_as_float((iz << 23) + 0x3F800000);
}

#if HAS_TC
__device__ __forceinline__ uint32_t elect1() {
    uint32_t p;
    asm volatile("{\n\t.reg .pred p;\n\telect.sync _|p, 0xFFFFFFFF;\n\t"
                 "selp.b32 %0, 1, 0, p;\n\t}" : "=r"(p));
    return p;
}
#define TC_ALLOC(smemaddr, ncols) \
    asm volatile("tcgen05.alloc.cta_group::1.sync.aligned.shared::cta.b32 [%0], %1;" \
                 :: "r"(smemaddr), "r"(ncols) : "memory")
#define TC_RELINQ() \
    asm volatile("tcgen05.relinquish_alloc_permit.cta_group::1.sync.aligned;")
#define TC_DEALLOC(tmem, ncols) \
    asm volatile("tcgen05.dealloc.cta_group::1.sync.aligned.b32 %0, %1;" \
                 :: "r"(tmem), "r"(ncols))
#define TC_COMMIT(mbar) \
    asm volatile("tcgen05.commit.cta_group::1.mbarrier::arrive::one.shared::cluster.b64 [%0];" \
                 :: "r"(mbar) : "memory")
#define TC_FENCE_AFTER()  asm volatile("tcgen05.fence::after_thread_sync;" ::: "memory")
#define TC_FENCE_BEFORE() asm volatile("tcgen05.fence::before_thread_sync;" ::: "memory")
#define TC_WAIT_LD()      asm volatile("tcgen05.wait::ld.sync.aligned;" ::: "memory")
#define FENCE_ASYNC_SHARED() asm volatile("fence.proxy.async.shared::cta;" ::: "memory")
#define MBAR_INIT(mbar, cnt) \
    asm volatile("mbarrier.init.shared.b64 [%0], %1;" :: "r"(mbar), "r"(cnt) : "memory")
#define MBAR_EXPECT_TX(mbar, bytes) \
    asm volatile("mbarrier.arrive.expect_tx.shared.b64 _, [%0], %1;" \
                 :: "r"(mbar), "r"(bytes) : "memory")
#define TMA_LOAD_2D(smem, map, x, y, mbar) \
    asm volatile("cp.async.bulk.tensor.2d.shared::cta.global.tile.mbarrier::complete_tx::bytes " \
                 "[%0], [%1, {%2, %3}], [%4];" \
                 :: "r"(smem), "l"(map), "r"(x), "r"(y), "r"(mbar) : "memory")

__device__ __forceinline__ void mbar_wait(uint32_t mbar, uint32_t parity) {
    asm volatile(
        "{\n\t.reg .pred P;\n\t"
        "WL_%=:\n\t"
        "mbarrier.try_wait.parity.acquire.cta.shared::cta.b64 P, [%0], %1, 0x989680;\n\t"
        "@P bra.uni WD_%=;\n\t"
        "bra.uni WL_%=;\n\t"
        "WD_%=:\n\t}"
        :: "r"(mbar), "r"(parity) : "memory");
}

__device__ __forceinline__ void tc_ld_x32(uint32_t* r, uint32_t tmem_addr) {
    asm volatile(
        "tcgen05.ld.sync.aligned.32x32b.x32.b32 "
        "{%0, %1, %2, %3, %4, %5, %6, %7, %8, %9, %10, %11, %12, %13, %14, %15, "
        " %16, %17, %18, %19, %20, %21, %22, %23, %24, %25, %26, %27, %28, %29, %30, %31}, [%32];"
        : "=r"(r[0]),  "=r"(r[1]),  "=r"(r[2]),  "=r"(r[3]),
          "=r"(r[4]),  "=r"(r[5]),  "=r"(r[6]),  "=r"(r[7]),
          "=r"(r[8]),  "=r"(r[9]),  "=r"(r[10]), "=r"(r[11]),
          "=r"(r[12]), "=r"(r[13]), "=r"(r[14]), "=r"(r[15]),
          "=r"(r[16]), "=r"(r[17]), "=r"(r[18]), "=r"(r[19]),
          "=r"(r[20]), "=r"(r[21]), "=r"(r[22]), "=r"(r[23]),
          "=r"(r[24]), "=r"(r[25]), "=r"(r[26]), "=r"(r[27]),
          "=r"(r[28]), "=r"(r[29]), "=r"(r[30]), "=r"(r[31])
        : "r"(tmem_addr));
}

__device__ __forceinline__ void mma_f16_ss(uint32_t d, uint64_t a, uint64_t b,
                                           uint32_t idesc, uint32_t en) {
    asm volatile(
        "{\n\t.reg .pred p;\n\tsetp.ne.u32 p, %4, 0;\n\t"
        "tcgen05.mma.cta_group::1.kind::f16 [%0], %1, %2, %3, {%5, %5, %5, %5}, p;\n\t}"
        :: "r"(d), "l"(a), "l"(b), "r"(idesc), "r"(en), "r"(0u) : "memory");
}

static __device__ __forceinline__ uint64_t make_desc_sw128(uint32_t base) {
    const uint64_t BASE =
        (uint64_t(2) << 61) | (uint64_t(1) << 46) | (uint64_t(64) << 32) | (uint64_t(1) << 16);
    return BASE | ((uint64_t)(base >> 4) & 0x3FFF);
}
// SW64: layout=4, version=1, SBO=32 (512B = 8 rows x 64B), LBO=1 (16B)
static __device__ __forceinline__ uint64_t make_desc_sw64(uint32_t base) {
    const uint64_t BASE =
        (uint64_t(4) << 61) | (uint64_t(1) << 46) | (uint64_t(32) << 32) | (uint64_t(1) << 16);
    return BASE | ((uint64_t)(base >> 4) & 0x3FFF);
}
#endif  // HAS_TC

// ---------------- wsplit x4 (launch #1) ----------------
__global__ void wsplit4_kernel(const float* __restrict__ W0,
                               const float* __restrict__ W1,
                               const float* __restrict__ W2,
                               const float* __restrict__ W3,
                               __nv_bfloat16* __restrict__ Th,
                               __nv_bfloat16* __restrict__ Tl) {
    __shared__ float t[32][33];
    int z = blockIdx.z;
    int tid = threadIdx.x;
    const float* W = (z == 0) ? W0 : (z == 1) ? W1 : (z == 2) ? W2 : W3;
    __nv_bfloat16* th = Th + (size_t)z * DM * DM;
    __nv_bfloat16* tl = Tl + (size_t)z * DM * DM;
    int n0 = blockIdx.x * 32, k0 = blockIdx.y * 32;
    int tx = tid & 31, ty = tid >> 5;
#pragma unroll
    for (int i = 0; i < 32; i += 8)
        t[ty + i][tx] = W[(size_t)(k0 + ty + i) * DM + n0 + tx];
    __syncthreads();
#pragma unroll
    for (int i = 0; i < 32; i += 8) {
        float v = t[tx][ty + i];
        __nv_bfloat16 h = __float2bfloat16(v);
        __nv_bfloat16 l = __float2bfloat16(v - __bfloat162float(h));
        size_t o = (size_t)(n0 + ty + i) * DM + k0 + tx;
        th[o] = h; tl[o] = l;
    }
}

// ---------------- positional encoding (launch #2) ----------------
__global__ void pe_kernel(float* __restrict__ pe) {
    int tid = threadIdx.x;
    int trow = blockIdx.x * 8 + (tid >> 5);
    int lane = tid & 31;
    const double c = -(9.210340371976184 / 512.0);
#pragma unroll
    for (int u = 0; u < 16; u++) {
        int col = lane * 16 + u;
        int i2  = col & ~1;
        double arg = (double)trow * exp((double)i2 * c);
        pe[trow * DM + col] = (col & 1) ? (float)cos(arg) : (float)sin(arg);
    }
}

// ---------------- LN1 + pe (+ bf16 split of h) ----------------
__global__ void ln1_pos_kernel(const float* __restrict__ x,
                               const float* __restrict__ gam,
                               const float* __restrict__ bet,
                               const float* __restrict__ pe,
                               float* __restrict__ h,
                               __nv_bfloat16* __restrict__ hh,
                               __nv_bfloat16* __restrict__ hl) {
    __shared__ float redS[8], redS2[8];
    int row = blockIdx.x;
    int t   = row & (SEQ - 1);
    const float* xr = x  + (size_t)row * DM;
    const float* pr = pe + (size_t)t   * DM;
    int tid = threadIdx.x;

    float a = xr[tid], b = xr[tid + 256];
    float s  = a + b;
    float s2 = a * a + b * b;
#pragma unroll
    for (int off = 16; off; off >>= 1) {
        s  += __shfl_xor_sync(0xffffffffu, s,  off);
        s2 += __shfl_xor_sync(0xffffffffu, s2, off);
    }
    if ((tid & 31) == 0) { redS[tid >> 5] = s; redS2[tid >> 5] = s2; }
    __syncthreads();
    if (tid == 0) {
        float S = 0.f, S2 = 0.f;
#pragma unroll
        for (int w = 0; w < 8; w++) { S += redS[w]; S2 += redS2[w]; }
        redS[0] = S; redS2[0] = S2;
    }
    __syncthreads();
    float mu   = redS[0] * (1.f / 512.f);
    float var  = redS2[0] * (1.f / 512.f) - mu * mu;
    float rstd = rsqrtf(var + 1e-5f);
#pragma unroll
    for (int u = 0; u < 2; u++) {
        int col = tid + u * 256;
        float xv = u ? b : a;
        float hv = (xv - mu) * rstd * gam[col] + bet[col] + pr[col];
        size_t o = (size_t)row * DM + col;
        h[o] = hv;
        __nv_bfloat16 hi = __float2bfloat16(hv);
        hh[o] = hi;
        hl[o] = __float2bfloat16(hv - __bfloat162float(hi));
    }
}

// ---------------- LN2 + residuals ----------------
__global__ void ln2_kernel(const float* __restrict__ o2,
                           const float* __restrict__ r1,
                           const float* __restrict__ x,
                           const float* __restrict__ gam,
                           const float* __restrict__ bet,
                           float* __restrict__ out) {
    __shared__ float redS[8], redS2[8];
    int row = blockIdx.x;
    const float* or_ = o2 + (size_t)row * DM;
    const float* rr  = r1 + (size_t)row * DM;
    const float* xr  = x  + (size_t)row * DM;
    float*       wr  = out + (size_t)row * DM;
    int tid = threadIdx.x;

    float a = or_[tid]       + rr[tid];
    float b = or_[tid + 256] + rr[tid + 256];
    float s  = a + b;
    float s2 = a * a + b * b;
#pragma unroll
    for (int off = 16; off; off >>= 1) {
        s  += __shfl_xor_sync(0xffffffffu, s,  off);
        s2 += __shfl_xor_sync(0xffffffffu, s2, off);
    }
    if ((tid & 31) == 0) { redS[tid >> 5] = s; redS2[tid >> 5] = s2; }
    __syncthreads();
    if (tid == 0) {
        float S = 0.f, S2 = 0.f;
#pragma unroll
        for (int w = 0; w < 8; w++) { S += redS[w]; S2 += redS2[w]; }
        redS[0] = S; redS2[0] = S2;
    }
    __syncthreads();
    float mu   = redS[0] * (1.f / 512.f);
    float var  = redS2[0] * (1.f / 512.f) - mu * mu;
    float rstd = rsqrtf(var + 1e-6f);
#pragma unroll
    for (int u = 0; u < 2; u++) {
        int col = tid + u * 256;
        float vv = u ? b : a;
        wr[col] = (vv - mu) * rstd * gam[col] + bet[col] + xr[col];
    }
}

// ====== GEMM core (bf16x3, 128x256 tile, TMA 4-stage K=32 pipeline, SW64) ====
#define GIDESC2 ((1u << 4) | (1u << 7) | (1u << 10) | ((256u / 8) << 17) | ((128u / 16) << 24))
#define GEMM_DSMEM 197632   // 4 x 48KB stages + 1KB align slack
#define STAGE_B   49152u
#define CHUNK_TX  49152u

#if HAS_TC
// Single elected thread drives TMA + MMA. 16 chunks of K=32, 4-stage.
__device__ __forceinline__ uint32_t gemm_mainloop_tma(
    const CUtensorMap* mAh, const CUtensorMap* mAl,
    const CUtensorMap* mWh, const CUtensorMap* mWl,
    int m0, int ny, char* dsm_raw,
    uint64_t* s_mbar, uint32_t* s_tm, uint32_t tid, uint32_t wid)
{
    uint32_t raw = smem_u32(dsm_raw);
    uint32_t sb  = (raw + 1023) & ~1023u;

    uint32_t mbF[4], mbD[4];
#pragma unroll
    for (int i = 0; i < 4; i++) {
        mbF[i] = smem_u32(&s_mbar[i]);
        mbD[i] = smem_u32(&s_mbar[4 + i]);
    }

    if (wid == 0) { TC_ALLOC(smem_u32(s_tm), 256); TC_RELINQ(); }
    if (tid == 0) {
#pragma unroll
        for (int i = 0; i < 4; i++) { MBAR_INIT(mbF[i], 1); MBAR_INIT(mbD[i], 1); }
    }
    __syncthreads();
    uint32_t tmem = s_tm[0];

    // stage layout: AH 8K @0, AL 8K @8192, BH 16K @16384, BL 16K @32768
    const uint32_t OAH = 0, OAL = 8192, OBH = 16384, OBL = 32768;

    if (wid == 0 && elect1()) {
        // prologue: load chunks 0..2
#pragma unroll
        for (int s = 0; s < 3; s++) {
            uint32_t base = sb + (uint32_t)s * STAGE_B;
            MBAR_EXPECT_TX(mbF[s], CHUNK_TX);
            int k0 = s * 32;
            TMA_LOAD_2D(base + OAH, mAh, k0, m0, mbF[s]);
            TMA_LOAD_2D(base + OAL, mAl, k0, m0, mbF[s]);
            TMA_LOAD_2D(base + OBH, mWh, k0, ny, mbF[s]);
            TMA_LOAD_2D(base + OBL, mWl, k0, ny, mbF[s]);
        }
#pragma unroll 1
        for (int c = 0; c < 16; c++) {
            int b = c & 3;
            mbar_wait(mbF[b], (uint32_t)((c >> 2) & 1));
            uint32_t base = sb + (uint32_t)b * STAGE_B;
            uint64_t dah = make_desc_sw64(base + OAH);
            uint64_t dal = make_desc_sw64(base + OAL);
            uint64_t dbh = make_desc_sw64(base + OBH);
            uint64_t dbl = make_desc_sw64(base + OBL);
#pragma unroll
            for (int ks = 0; ks < 2; ks++) {
                mma_f16_ss(tmem, dah + ks * 2, dbh + ks * 2, GIDESC2,
                           (c == 0 && ks == 0) ? 0u : 1u);
                mma_f16_ss(tmem, dah + ks * 2, dbl + ks * 2, GIDESC2, 1u);
                mma_f16_ss(tmem, dal + ks * 2, dbh + ks * 2, GIDESC2, 1u);
            }
            TC_COMMIT(mbD[b]);
            if (c <= 12) {
                // load chunk c+3 into buffer (c+3)&3 == (c-1)&3
                if (c >= 1) {
                    int pb = (c - 1) & 3;
                    mbar_wait(mbD[pb], (uint32_t)(((c - 1) >> 2) & 1));
                }
                int nb = (c + 3) & 3;
                uint32_t nbase = sb + (uint32_t)nb * STAGE_B;
                MBAR_EXPECT_TX(mbF[nb], CHUNK_TX);
                int k0 = (c + 3) * 32;
                TMA_LOAD_2D(nbase + OAH, mAh, k0, m0, mbF[nb]);
                TMA_LOAD_2D(nbase + OAL, mAl, k0, m0, mbF[nb]);
                TMA_LOAD_2D(nbase + OBH, mWh, k0, ny, mbF[nb]);
                TMA_LOAD_2D(nbase + OBL, mWl, k0, ny, mbF[nb]);
            }
        }
        mbar_wait(mbD[3], 1u);   // chunk 15 done (4th arrival on buffer 3)
    }
    __syncthreads();
    TC_FENCE_AFTER();
    return tmem;
}
#else
__device__ __forceinline__ void gemm_mainloop_simt(
    const __nv_bfloat16* __restrict__ Ah, const __nv_bfloat16* __restrict__ Al,
    const __nv_bfloat16* __restrict__ Bh, const __nv_bfloat16* __restrict__ Bl,
    int m0, int n0, char* dsm_raw, uint32_t tid, float acc[8][8])
{
    float* As = (float*)dsm_raw;
    float* Ws = As + 2 * 8 * 132;
    int tx = tid & 15, ty = (int)(tid >> 4);
    int r = tid & 127;
    bool isA = tid < 128;
    const __nv_bfloat16* Ph = isA ? Ah + (size_t)(m0 + r) * DM
                                  : Bh + (size_t)(n0 + r) * DM;
    const __nv_bfloat16* Pl = isA ? Al + (size_t)(m0 + r) * DM
                                  : Bl + (size_t)(n0 + r) * DM;
    int stride = isA ? 132 : 128;
#pragma unroll
    for (int i = 0; i < 8; i++)
#pragma unroll
        for (int j = 0; j < 8; j++) acc[i][j] = 0.f;

    auto stage = [&](int buf, int k0) {
        uint4 vh = *(const uint4*)(Ph + k0);
        uint4 vl = *(const uint4*)(Pl + k0);
        const __nv_bfloat16* bh = (const __nv_bfloat16*)&vh;
        const __nv_bfloat16* bl = (const __nv_bfloat16*)&vl;
        float* dst = (isA ? As + buf * 8 * 132 : Ws + buf * 8 * 128) + r;
#pragma unroll
        for (int k = 0; k < 8; k++)
            dst[k * stride] = __bfloat162float(bh[k]) + __bfloat162float(bl[k]);
    };
    stage(0, 0);
    __syncthreads();
    int buf = 0;
#pragma unroll 1
    for (int k0 = 0; k0 < 512; k0 += 8) {
        if (k0 + 8 < 512) stage(buf ^ 1, k0 + 8);
#pragma unroll
        for (int kk = 0; kk < 8; kk++) {
            float av[8], bv[8];
            const float* ar = As + buf * 8 * 132 + kk * 132;
            const float* wr = Ws + buf * 8 * 128 + kk * 128;
            *(float4*)(av)     = *(const float4*)(ar + ty * 4);
            *(float4*)(av + 4) = *(const float4*)(ar + 64 + ty * 4);
            *(float4*)(bv)     = *(const float4*)(wr + tx * 4);
            *(float4*)(bv + 4) = *(const float4*)(wr + 64 + tx * 4);
#pragma unroll
            for (int i = 0; i < 8; i++)
#pragma unroll
                for (int j = 0; j < 8; j++) acc[i][j] += av[i] * bv[j];
        }
        __syncthreads();
        buf ^= 1;
    }
}
#endif

// ---------------- fused Q/K/V projection (128x256 tiles, TMA) ----------------
__global__ void __launch_bounds__(256, 1)
gemm_qkv_kernel(const __grid_constant__ CUtensorMap mAh,
                const __grid_constant__ CUtensorMap mAl,
                const __grid_constant__ CUtensorMap mWh,
                const __grid_constant__ CUtensorMap mWl,
                const __nv_bfloat16* __restrict__ Ah,
                const __nv_bfloat16* __restrict__ Al,
                const __nv_bfloat16* __restrict__ Wh,
                const __nv_bfloat16* __restrict__ Wl,
                __nv_bfloat16* __restrict__ Qh, __nv_bfloat16* __restrict__ Ql,
                __nv_bfloat16* __restrict__ Kh, __nv_bfloat16* __restrict__ Kl,
                __half* __restrict__ Vt, float qscale) {
    extern __shared__ char dsm_raw[];
    uint32_t tid = threadIdx.x, wid = tid >> 5, lid = tid & 31;
    int m0 = blockIdx.x * 128, n0 = blockIdx.y * 256;
    int z = blockIdx.z;
    float scale = (z == 0) ? qscale : 1.0f;

#if HAS_TC
    __shared__ __align__(16) uint64_t s_mbar[8];
    __shared__ uint32_t s_tm[1];
    uint32_t tmem = gemm_mainloop_tma(&mAh, &mAl, &mWh, &mWl,
                                      m0, z * DM + n0, dsm_raw,
                                      s_mbar, s_tm, tid, wid);
    int sub  = wid & 3;
    int nblk = (int)(wid >> 2);
    int row  = m0 + sub * 32 + (int)lid;
    int b = row >> 11, t = row & (SEQ - 1);

#pragma unroll
    for (int cb = 0; cb < 4; cb++) {
        int colb = nblk * 128 + cb * 32;
        uint32_t d[32];
        tc_ld_x32(d, tmem + colb);
        TC_WAIT_LD();

        if (z < 2) {
            __nv_bfloat16* Ch = (z == 0) ? Qh : Kh;
            __nv_bfloat16* Cl = (z == 0) ? Ql : Kl;
            size_t rowoff = (size_t)row * DM + n0 + colb;
            uint32_t hw[16], lw[16];
#pragma unroll
            for (int m = 0; m < 16; m++) {
                float v0 = __uint_as_float(d[2*m])   * scale;
                float v1 = __uint_as_float(d[2*m+1]) * scale;
                __nv_bfloat162 h2 = __floats2bfloat162_rn(v0, v1);
                __nv_bfloat162 l2 = __floats2bfloat162_rn(v0 - __bfloat162float(h2.x),
                                                          v1 - __bfloat162float(h2.y));
                hw[m] = *(uint32_t*)&h2; lw[m] = *(uint32_t*)&l2;
            }
#pragma unroll
            for (int u = 0; u < 4; u++) {
                *(uint4*)(Ch + rowoff + u * 8) =
                    make_uint4(hw[4*u], hw[4*u+1], hw[4*u+2], hw[4*u+3]);
                *(uint4*)(Cl + rowoff + u * 8) =
                    make_uint4(lw[4*u], lw[4*u+1], lw[4*u+2], lw[4*u+3]);
            }
        } else {
#pragma unroll
            for (int j = 0; j < 32; j++) {
                int c = n0 + colb + j;
                size_t o = ((size_t)((b << 3) + (c >> 6)) * 64 + (c & 63)) * SEQ + t;
                Vt[o] = __float2half(__uint_as_float(d[j]));
            }
        }
    }
    TC_FENCE_BEFORE();
    __syncthreads();
    if (wid == 0) TC_DEALLOC(tmem, 256);
#else
    const __nv_bfloat16* Bh = Wh + (size_t)z * DM * DM;
    const __nv_bfloat16* Bl = Wl + (size_t)z * DM * DM;
    for (int nh = 0; nh < 2; nh++) {
        float acc[8][8];
        gemm_mainloop_simt(Ah, Al, Bh, Bl, m0, n0 + nh * 128, dsm_raw, tid, acc);
        int tx = tid & 15, ty = (int)(tid >> 4);
#pragma unroll
        for (int i = 0; i < 8; i++) {
            int row = m0 + ((i < 4) ? (ty * 4 + i) : (64 + ty * 4 + i - 4));
#pragma unroll
            for (int j = 0; j < 8; j++) {
                int col = n0 + nh * 128 + ((j < 4) ? (tx * 4 + j) : (64 + tx * 4 + j - 4));
                float v = acc[i][j] * scale;
                if (z < 2) {
                    __nv_bfloat16* Ch = (z == 0) ? Qh : Kh;
                    __nv_bfloat16* Cl = (z == 0) ? Ql : Kl;
                    __nv_bfloat16 h = __float2bfloat16(v);
                    Ch[(size_t)row * DM + col] = h;
                    Cl[(size_t)row * DM + col] = __float2bfloat16(v - __bfloat162float(h));
                } else {
                    int b = row >> 11, t = row & (SEQ - 1);
                    size_t o = ((size_t)((b << 3) + (col >> 6)) * 64 + (col & 63)) * SEQ + t;
                    Vt[o] = __float2half(v);
                }
            }
        }
        __syncthreads();
    }
#endif
}

// ---------------- FC projection (fp32 out, 128x256 tiles, TMA) ---------------
__global__ void __launch_bounds__(256, 1)
gemm_fc_kernel(const __grid_constant__ CUtensorMap mAh,
               const __grid_constant__ CUtensorMap mAl,
               const __grid_constant__ CUtensorMap mWh,
               const __grid_constant__ CUtensorMap mWl,
               const __nv_bfloat16* __restrict__ Ah,
               const __nv_bfloat16* __restrict__ Al,
               const __nv_bfloat16* __restrict__ Bh,
               const __nv_bfloat16* __restrict__ Bl,
               float* __restrict__ C) {
    extern __shared__ char dsm_raw[];
    uint32_t tid = threadIdx.x, wid = tid >> 5, lid = tid & 31;
    int m0 = blockIdx.x * 128, n0 = blockIdx.y * 256;
#if HAS_TC
    __shared__ __align__(16) uint64_t s_mbar[8];
    __shared__ uint32_t s_tm[1];
    uint32_t tmem = gemm_mainloop_tma(&mAh, &mAl, &mWh, &mWl,
                                      m0, 3 * DM + n0, dsm_raw,
                                      s_mbar, s_tm, tid, wid);
    int sub  = wid & 3;
    int nblk = (int)(wid >> 2);
    int row  = m0 + sub * 32 + (int)lid;

#pragma unroll
    for (int cb = 0; cb < 4; cb++) {
        int colb = nblk * 128 + cb * 32;
        uint32_t d[32];
        tc_ld_x32(d, tmem + colb);
        TC_WAIT_LD();
        float* Cr = C + (size_t)row * DM + n0 + colb;
#pragma unroll
        for (int j = 0; j < 8; j++)
            *(float4*)(Cr + j * 4) = make_float4(
                __uint_as_float(d[4*j]),   __uint_as_float(d[4*j+1]),
                __uint_as_float(d[4*j+2]), __uint_as_float(d[4*j+3]));
    }
    TC_FENCE_BEFORE();
    __syncthreads();
    if (wid == 0) TC_DEALLOC(tmem, 256);
#else
    for (int nh = 0; nh < 2; nh++) {
        float acc[8][8];
        gemm_mainloop_simt(Ah, Al, Bh, Bl, m0, n0 + nh * 128, dsm_raw, tid, acc);
        int tx = tid & 15, ty = (int)(tid >> 4);
#pragma unroll
        for (int i = 0; i < 8; i++) {
            int row = m0 + ((i < 4) ? (ty * 4 + i) : (64 + ty * 4 + i - 4));
#pragma unroll
            for (int j = 0; j < 8; j++) {
                int col = n0 + nh * 128 + ((j < 4) ? (tx * 4 + j) : (64 + tx * 4 + j - 4));
                C[(size_t)row * DM + col] = acc[i][j];
            }
        }
        __syncthreads();
    }
#endif
}

// ========== attention (pipelined, triple-buffered V, cheap softmax) ==========
#define AIDESC_S  ((1u << 4) | (1u << 7) | (1u << 10) | ((64u / 8) << 17) | ((128u / 16) << 24))
#define AIDESC_PV ((1u << 4) | ((64u / 8) << 17) | ((128u / 16) << 24))
#define ATTN_DSMEM 108544

#if HAS_TC
__global__ void __launch_bounds__(256, 2)
attn_kernel(const __nv_bfloat16* __restrict__ Qh, const __nv_bfloat16* __restrict__ Ql,
            const __nv_bfloat16* __restrict__ Kh, const __nv_bfloat16* __restrict__ Kl,
            const __half* __restrict__ Vt,
            __nv_bfloat16* __restrict__ Oh, __nv_bfloat16* __restrict__ Ol) {
    extern __shared__ char dsm_raw[];
    __shared__ __align__(16) uint64_t s_mbar[3];
    __shared__ uint32_t s_tm[1];
    uint32_t tid = threadIdx.x, wid = tid >> 5, lane = tid & 31;
    int qt = (int)(gridDim.x - 1) - (int)blockIdx.x;
    int bh = blockIdx.y, bb = bh >> 3, hd = bh & 7;

    uint32_t raw = smem_u32(dsm_raw);
    uint32_t sb  = (raw + 1023) & ~1023u;
    char* dsm = dsm_raw + (sb - raw);

    const uint32_t OFF_QH = 0,     OFF_QL = 16384,
                   OFF_KH = 32768, OFF_KL = 49152,
                   OFF_V  = 65536,
                   OFF_P  = 90112,
                   OFF_L  = 106496;

    uint32_t mbS0 = smem_u32(&s_mbar[0]);
    uint32_t mbS1 = smem_u32(&s_mbar[1]);
    uint32_t mbPV = smem_u32(&s_mbar[2]);
    if (wid == 0) { TC_ALLOC(smem_u32(s_tm), 256); TC_RELINQ(); }
    if (tid == 0) { MBAR_INIT(mbS0, 1); MBAR_INIT(mbS1, 1); MBAR_INIT(mbPV, 1); }
    __syncthreads();
    uint32_t tmem = s_tm[0];

    size_t rowbase = (size_t)bb * SEQ;
    const __nv_bfloat16* khb = Kh + rowbase * DM + hd * 64;
    const __nv_bfloat16* klb = Kl + rowbase * DM + hd * 64;
    const __half*        vtb = Vt + ((size_t)bh * 64) * SEQ;

    int cr0 = (int)tid >> 3,         cg0 = ((int)tid & 7) * 8;
    int cr1 = (int)(tid + 256) >> 3, cg1 = (((int)tid + 256) & 7) * 8;
    uint32_t so0, so1;
    {
        uint32_t o0 = (uint32_t)(cr0 * 128 + cg0 * 2), o1 = (uint32_t)(cr1 * 128 + cg1 * 2);
        so0 = o0 ^ ((o0 >> 3) & 0x70);
        so1 = o1 ^ ((o1 >> 3) & 0x70);
    }

    {
        const __nv_bfloat16* qhp = Qh + (rowbase + (size_t)qt * 128) * DM + hd * 64;
        const __nv_bfloat16* qlp = Ql + (rowbase + (size_t)qt * 128) * DM + hd * 64;
#pragma unroll
        for (int i = 0; i < 4; i++) {
            int idx = i * 256 + (int)tid;
            int r = idx >> 3, g = idx & 7;
            uint32_t o = (uint32_t)(r * 128 + g * 16), so = o ^ ((o >> 3) & 0x70);
            *(uint4*)(dsm + OFF_QH + so) = *(const uint4*)(qhp + (size_t)r * DM + g * 8);
            *(uint4*)(dsm + OFF_QL + so) = *(const uint4*)(qlp + (size_t)r * DM + g * 8);
        }
        *(uint4*)(dsm + OFF_KH + so0) = *(const uint4*)(khb + (size_t)cr0 * DM + cg0);
        *(uint4*)(dsm + OFF_KH + so1) = *(const uint4*)(khb + (size_t)cr1 * DM + cg1);
        *(uint4*)(dsm + OFF_KL + so0) = *(const uint4*)(klb + (size_t)cr0 * DM + cg0);
        *(uint4*)(dsm + OFF_KL + so1) = *(const uint4*)(klb + (size_t)cr1 * DM + cg1);
        *(uint4*)(dsm + OFF_V  + so0) = *(const uint4*)(vtb + (size_t)cr0 * SEQ + cg0);
        *(uint4*)(dsm + OFF_V  + so1) = *(const uint4*)(vtb + (size_t)cr1 * SEQ + cg1);
    }

    int ktmax = 2 * qt + 1;

    uint4 pkh0, pkh1, pkl0, pkl1, pv0, pv1;
    {
        const __nv_bfloat16* khp = khb + (size_t)64 * DM;
        const __nv_bfloat16* klp = klb + (size_t)64 * DM;
        const __half*        vhp = vtb + 64;
        pkh0 = *(const uint4*)(khp + (size_t)cr0 * DM + cg0);
        pkh1 = *(const uint4*)(khp + (size_t)cr1 * DM + cg1);
        pkl0 = *(const uint4*)(klp + (size_t)cr0 * DM + cg0);
        pkl1 = *(const uint4*)(klp + (size_t)cr1 * DM + cg1);
        pv0  = *(const uint4*)(vhp + (size_t)cr0 * SEQ + cg0);
        pv1  = *(const uint4*)(vhp + (size_t)cr1 * SEQ + cg1);
    }
    __syncthreads();

    uint64_t dqh = make_desc_sw128(sb + OFF_QH);
    uint64_t dql = make_desc_sw128(sb + OFF_QL);

    if (wid == 0 && elect1()) {
        FENCE_ASYNC_SHARED();
        uint64_t dkh = make_desc_sw128(sb + OFF_KH);
        uint64_t dkl = make_desc_sw128(sb + OFF_KL);
#pragma unroll
        for (int ks = 0; ks < 4; ks++)
            mma_f16_ss(tmem, dqh + ks * 2, dkh + ks * 2, AIDESC_S, ks ? 1u : 0u);
#pragma unroll
        for (int ks = 0; ks < 4; ks++)
            mma_f16_ss(tmem, dqh + ks * 2, dkl + ks * 2, AIDESC_S, 1u);
#pragma unroll
        for (int ks = 0; ks < 4; ks++)
            mma_f16_ss(tmem, dql + ks * 2, dkh + ks * 2, AIDESC_S, 1u);
        TC_COMMIT(mbS0);
    }

    int sub = wid & 3, half = (int)(wid >> 2);
    int rl = sub * 32 + (int)lane;
    int grow = qt * 128 + rl;
    float lsum = 0.f;
    uint32_t phS0 = 0, phS1 = 0, phPV = 0;
    int vslot = 0;

#pragma unroll 1
    for (int kt = 0; kt <= ktmax; kt++) {
        int buf = kt & 1;

        if (kt < ktmax) {
            int nbuf = buf ^ 1;
            int nvslot = vslot + 1; if (nvslot == 3) nvslot = 0;
            uint32_t kb   = OFF_KH + (uint32_t)nbuf * 8192u;
            uint32_t klb2 = OFF_KL + (uint32_t)nbuf * 8192u;
            uint32_t vb   = OFF_V  + (uint32_t)nvslot * 8192u;
            *(uint4*)(dsm + kb   + so0) = pkh0;
            *(uint4*)(dsm + kb   + so1) = pkh1;
            *(uint4*)(dsm + klb2 + so0) = pkl0;
            *(uint4*)(dsm + klb2 + so1) = pkl1;
            *(uint4*)(dsm + vb   + so0) = pv0;
            *(uint4*)(dsm + vb   + so1) = pv1;
            __syncthreads();
            if (wid == 0 && elect1()) {
                FENCE_ASYNC_SHARED();
                uint64_t dkh = make_desc_sw128(sb + kb);
                uint64_t dkl = make_desc_sw128(sb + klb2);
                uint32_t stm = tmem + (uint32_t)nbuf * 64u;
#pragma unroll
                for (int ks = 0; ks < 4; ks++)
                    mma_f16_ss(stm, dqh + ks * 2, dkh + ks * 2, AIDESC_S, ks ? 1u : 0u);
#pragma unroll
                for (int ks = 0; ks < 4; ks++)
                    mma_f16_ss(stm, dqh + ks * 2, dkl + ks * 2, AIDESC_S, 1u);
#pragma unroll
                for (int ks = 0; ks < 4; ks++)
                    mma_f16_ss(stm, dql + ks * 2, dkh + ks * 2, AIDESC_S, 1u);
                TC_COMMIT(nbuf == 0 ? mbS0 : mbS1);
            }
            if (kt + 2 <= ktmax) {
                const __nv_bfloat16* khp = khb + (size_t)(kt + 2) * 64 * DM;
                const __nv_bfloat16* klp = klb + (size_t)(kt + 2) * 64 * DM;
                const __half*        vhp = vtb + (size_t)(kt + 2) * 64;
                pkh0 = *(const uint4*)(khp + (size_t)cr0 * DM + cg0);
                pkh1 = *(const uint4*)(khp + (size_t)cr1 * DM + cg1);
                pkl0 = *(const uint4*)(klp + (size_t)cr0 * DM + cg0);
                pkl1 = *(const uint4*)(klp + (size_t)cr1 * DM + cg1);
                pv0  = *(const uint4*)(vhp + (size_t)cr0 * SEQ + cg0);
                pv1  = *(const uint4*)(vhp + (size_t)cr1 * SEQ + cg1);
            }
        }

        if (buf == 0) { mbar_wait(mbS0, phS0); phS0 ^= 1; }
        else          { mbar_wait(mbS1, phS1); phS1 ^= 1; }
        TC_FENCE_AFTER();

        uint32_t sreg[32];
        tc_ld_x32(sreg, tmem + (uint32_t)buf * 64u + half * 32);
        TC_WAIT_LD();

        if (kt >= 1) { mbar_wait(mbPV, phPV); phPV ^= 1; }

        int jmax = grow - (kt * 64 + half * 32);
        uint32_t pbase = (uint32_t)(rl * 128 + half * 64);
        if (jmax >= 31) {
#pragma unroll
            for (int gj = 0; gj < 4; gj++) {
                uint32_t w[4];
#pragma unroll
                for (int m = 0; m < 4; m++) {
                    int j0 = gj * 8 + m * 2;
                    float p0 = fexp2(__uint_as_float(sreg[j0]));
                    float p1 = fexp2(__uint_as_float(sreg[j0 + 1]));
                    lsum += p0 + p1;
                    __half2 h2 = __floats2half2_rn(p0, p1);
                    w[m] = *(uint32_t*)&h2;
                }
                uint32_t o = pbase + gj * 16, so = o ^ ((o >> 3) & 0x70);
                *(uint4*)(dsm + OFF_P + so) = make_uint4(w[0], w[1], w[2], w[3]);
            }
        } else {
#pragma unroll
            for (int gj = 0; gj < 4; gj++) {
                uint32_t w[4];
#pragma unroll
                for (int m = 0; m < 4; m++) {
                    int j0 = gj * 8 + m * 2;
                    float p0 = (j0     <= jmax) ? fexp2(__uint_as_float(sreg[j0]))     : 0.f;
                    float p1 = (j0 + 1 <= jmax) ? fexp2(__uint_as_float(sreg[j0 + 1])) : 0.f;
                    lsum += p0 + p1;
                    __half2 h2 = __floats2half2_rn(p0, p1);
                    w[m] = *(uint32_t*)&h2;
                }
                uint32_t o = pbase + gj * 16, so = o ^ ((o >> 3) & 0x70);
                *(uint4*)(dsm + OFF_P + so) = make_uint4(w[0], w[1], w[2], w[3]);
            }
        }
        __syncthreads();

        if (wid == 0 && elect1()) {
            FENCE_ASYNC_SHARED();
            uint64_t dp = make_desc_sw128(sb + OFF_P);
            uint64_t dv = make_desc_sw128(sb + OFF_V + (uint32_t)vslot * 8192u);
#pragma unroll
            for (int ks = 0; ks < 4; ks++)
                mma_f16_ss(tmem + 128, dp + ks * 2, dv + ks * 2, AIDESC_PV,
                           (kt == 0 && ks == 0) ? 0u : 1u);
            TC_COMMIT(mbPV);
        }
        vslot++; if (vslot == 3) vslot = 0;
    }

    mbar_wait(mbPV, phPV);
    TC_FENCE_AFTER();

    float* sl = (float*)(dsm + OFF_L);
    sl[rl * 2 + half] = lsum;
    __syncthreads();
    float inv = 1.f / (sl[rl * 2] + sl[rl * 2 + 1]);

    uint32_t oreg[32];
    tc_ld_x32(oreg, tmem + 128 + half * 32);
    TC_WAIT_LD();
    TC_FENCE_BEFORE();

    size_t obase = (rowbase + (size_t)grow) * DM + hd * 64 + half * 32;
    uint32_t hw[16], lw[16];
#pragma unroll
    for (int m = 0; m < 16; m++) {
        float v0 = __uint_as_float(oreg[2*m])   * inv;
        float v1 = __uint_as_float(oreg[2*m+1]) * inv;
        __nv_bfloat162 h2 = __floats2bfloat162_rn(v0, v1);
        __nv_bfloat162 l2 = __floats2bfloat162_rn(v0 - __bfloat162float(h2.x),
                                                  v1 - __bfloat162float(h2.y));
        hw[m] = *(uint32_t*)&h2; lw[m] = *(uint32_t*)&l2;
    }
#pragma unroll
    for (int u = 0; u < 4; u++) {
        *(uint4*)(Oh + obase + u * 8) = make_uint4(hw[4*u], hw[4*u+1], hw[4*u+2], hw[4*u+3]);
        *(uint4*)(Ol + obase + u * 8) = make_uint4(lw[4*u], lw[4*u+1], lw[4*u+2], lw[4*u+3]);
    }
    __syncthreads();
    if (wid == 0) TC_DEALLOC(tmem, 256);
}

#else  // ---------------- SIMT fallback attention ----------------
__global__ void __launch_bounds__(256)
attn_kernel(const __nv_bfloat16* __restrict__ Qh, const __nv_bfloat16* __restrict__ Ql,
            const __nv_bfloat16* __restrict__ Kh, const __nv_bfloat16* __restrict__ Kl,
            const __half* __restrict__ Vt,
            __nv_bfloat16* __restrict__ Oh, __nv_bfloat16* __restrict__ Ol) {
    extern __shared__ float sm[];
    float* sQ = sm;
    float* sK = sQ + 128 * 68;
    float* sV = sK + 64 * 68;
    float* sP = sV + 64 * 64;

    int qt = (int)(gridDim.x - 1) - (int)blockIdx.x;
    int bh = blockIdx.y;
    int bb = bh >> 3, hd = bh & 7;
    int tid = threadIdx.x;
    int tx = tid & 15, ty = tid >> 4;
    size_t base = ((size_t)bb * SEQ) * DM + (size_t)hd * DK;

    for (int idx = tid; idx < 128 * 64; idx += 256) {
        int r = idx >> 6, c = idx & 63;
        size_t o = base + (size_t)(qt * 128 + r) * DM + c;
        sQ[r * 68 + c] = __bfloat162float(Qh[o]) + __bfloat162float(Ql[o]);
    }

    float Oacc[8][4], m_i[8], l_i[8];
#pragma unroll
    for (int i = 0; i < 8; i++) {
        m_i[i] = -1e30f; l_i[i] = 0.f;
#pragma unroll
        for (int j = 0; j < 4; j++) Oacc[i][j] = 0.f;
    }

    int ktmax = 2 * qt + 1;
    for (int kt = 0; kt <= ktmax; kt++) {
        for (int idx = tid; idx < 64 * 64; idx += 256) {
            int r = idx >> 6, c = idx & 63;
            size_t ga = base + (size_t)(kt * 64 + r) * DM + c;
            sK[r * 68 + c] = __bfloat162float(Kh[ga]) + __bfloat162float(Kl[ga]);
            sV[r * 64 + c] = __half2float(Vt[((size_t)bh * 64 + c) * SEQ + kt * 64 + r]);
        }
        __syncthreads();

        float s[8][4];
#pragma unroll
        for (int i = 0; i < 8; i++)
#pragma unroll
            for (int j = 0; j < 4; j++) s[i][j] = 0.f;
#pragma unroll
        for (int d4 = 0; d4 < 16; d4++) {
            float4 kv[4];
#pragma unroll
            for (int j = 0; j < 4; j++)
                kv[j] = *(const float4*)&sK[(tx + 16 * j) * 68 + d4 * 4];
#pragma unroll
            for (int i = 0; i < 8; i++) {
                float4 qv = *(const float4*)&sQ[(ty + 16 * i) * 68 + d4 * 4];
#pragma unroll
                for (int j = 0; j < 4; j++)
                    s[i][j] += qv.x * kv[j].x + qv.y * kv[j].y +
                               qv.z * kv[j].z + qv.w * kv[j].w;
            }
        }
        if (kt >= 2 * qt) {
#pragma unroll
            for (int i = 0; i < 8; i++) {
                int grow = qt * 128 + ty + 16 * i;
#pragma unroll
                for (int j = 0; j < 4; j++)
                    if (kt * 64 + tx + 16 * j > grow) s[i][j] = -1e30f;
            }
        }
#pragma unroll
        for (int i = 0; i < 8; i++) {
            float mt = fmaxf(fmaxf(s[i][0], s[i][1]), fmaxf(s[i][2], s[i][3]));
#pragma unroll
            for (int off = 8; off; off >>= 1)
                mt = fmaxf(mt, __shfl_xor_sync(0xffffffffu, mt, off));
            float mn = fmaxf(m_i[i], mt);
            float corr = exp2f(m_i[i] - mn);
            m_i[i] = mn;
            float rs = 0.f;
#pragma unroll
            for (int j = 0; j < 4; j++) {
                float p = exp2f(s[i][j] - mn);
                s[i][j] = p; rs += p;
            }
#pragma unroll
            for (int off = 8; off; off >>= 1)
                rs += __shfl_xor_sync(0xffffffffu, rs, off);
            l_i[i] = l_i[i] * corr + rs;
#pragma unroll
            for (int j = 0; j < 4; j++) Oacc[i][j] *= corr;
#pragma unroll
            for (int j = 0; j < 4; j++)
                sP[(ty + 16 * i) * 68 + tx + 16 * j] = s[i][j];
        }
        __syncthreads();
#pragma unroll 4
        for (int k = 0; k < 64; k += 4) {
            float4 vv0 = *(const float4*)&sV[(k + 0) * 64 + tx * 4];
            float4 vv1 = *(const float4*)&sV[(k + 1) * 64 + tx * 4];
            float4 vv2 = *(const float4*)&sV[(k + 2) * 64 + tx * 4];
            float4 vv3 = *(const float4*)&sV[(k + 3) * 64 + tx * 4];
#pragma unroll
            for (int i = 0; i < 8; i++) {
                float4 pv = *(const float4*)&sP[(ty + 16 * i) * 68 + k];
                Oacc[i][0] += pv.x * vv0.x + pv.y * vv1.x + pv.z * vv2.x + pv.w * vv3.x;
                Oacc[i][1] += pv.x * vv0.y + pv.y * vv1.y + pv.z * vv2.y + pv.w * vv3.y;
                Oacc[i][2] += pv.x * vv0.z + pv.y * vv1.z + pv.z * vv2.z + pv.w * vv3.z;
                Oacc[i][3] += pv.x * vv0.w + pv.y * vv1.w + pv.z * vv2.w + pv.w * vv3.w;
            }
        }
        __syncthreads();
    }
#pragma unroll
    for (int i = 0; i < 8; i++) {
        float inv = 1.f / l_i[i];
        size_t rowa = base + (size_t)(qt * 128 + ty + 16 * i) * DM + tx * 4;
#pragma unroll
        for (int j = 0; j < 4; j++) {
            float v = Oacc[i][j] * inv;
            __nv_bfloat16 h = __float2bfloat16(v);
            Oh[rowa + j] = h;
            Ol[rowa + j] = __float2bfloat16(v - __bfloat162float(h));
        }
    }
}
#endif

// ---------------- host: tensormap encoding via driver entry point ------------
typedef CUresult (*PFN_cuTensorMapEncodeTiled_v12000)(
    CUtensorMap*, CUtensorMapDataType, cuuint32_t, void*,
    const cuuint64_t*, const cuuint64_t*, const cuuint32_t*, const cuuint32_t*,
    CUtensorMapInterleave, CUtensorMapSwizzle, CUtensorMapL2promotion,
    CUtensorMapFloatOOBfill);

static void encode_map(PFN_cuTensorMapEncodeTiled_v12000 fn, CUtensorMap* m,
                       void* base, unsigned long long d0, unsigned long long d1,
                       unsigned int b0, unsigned int b1,
                       CUtensorMapSwizzle sw) {
    cuuint64_t dims[2]    = {d0, d1};
    cuuint64_t strides[1] = {d0 * 2};           // bytes (bf16)
    cuuint32_t box[2]     = {b0, b1};
    cuuint32_t es[2]      = {1, 1};
    fn(m, CU_TENSOR_MAP_DATA_TYPE_BFLOAT16, 2, base, dims, strides, box, es,
       CU_TENSOR_MAP_INTERLEAVE_NONE, sw,
       CU_TENSOR_MAP_L2_PROMOTION_L2_128B, CU_TENSOR_MAP_FLOAT_OOB_FILL_NONE);
}

// ---------------- launch ----------------
extern "C" void kernel_launch(void* const* d_in, const int* in_sizes, int n_in,
                              void* d_out, int out_size) {
    const float* x     = (const float*)d_in[0];
    const float* ln1_g = (const float*)d_in[1];
    const float* ln1_b = (const float*)d_in[2];
    const float* wq    = (const float*)d_in[3];
    const float* wk    = (const float*)d_in[4];
    const float* wv    = (const float*)d_in[5];
    const float* wfc   = (const float*)d_in[6];
    const float* ln2_g = (const float*)d_in[7];
    const float* ln2_b = (const float*)d_in[8];
    float* out = (float*)d_out;

    float *ppe, *ph, *pfc;
    __nv_bfloat16 *pwh, *pwl, *pah, *pal, *pqh, *pql, *pkh, *pkl, *poh, *pol;
    __half *pvt;
    cudaGetSymbolAddress((void**)&ppe,  g_pe);
    cudaGetSymbolAddress((void**)&ph,   g_h);
    cudaGetSymbolAddress((void**)&pfc,  g_fc);
    cudaGetSymbolAddress((void**)&pwh,  g_wth);
    cudaGetSymbolAddress((void**)&pwl,  g_wtl);
    cudaGetSymbolAddress((void**)&pah,  g_ah);
    cudaGetSymbolAddress((void**)&pal,  g_al);
    cudaGetSymbolAddress((void**)&pqh,  g_qh);
    cudaGetSymbolAddress((void**)&pql,  g_ql);
    cudaGetSymbolAddress((void**)&pkh,  g_kh);
    cudaGetSymbolAddress((void**)&pkl,  g_kl);
    cudaGetSymbolAddress((void**)&poh,  g_oh);
    cudaGetSymbolAddress((void**)&pol,  g_ol);
    cudaGetSymbolAddress((void**)&pvt,  g_vt);

    PFN_cuTensorMapEncodeTiled_v12000 enc = nullptr;
    {
        void* fn = nullptr;
        cudaDriverEntryPointQueryResult st;
        cudaGetDriverEntryPoint("cuTensorMapEncodeTiled", &fn,
                                cudaEnableDefault, &st);
        enc = (PFN_cuTensorMapEncodeTiled_v12000)fn;
    }
    CUtensorMap mAqh, mAql, mWh, mWl, mAoh, mAol;
    encode_map(enc, &mAqh, pah, DM, ROWS,   32, 128, CU_TENSOR_MAP_SWIZZLE_64B);
    encode_map(enc, &mAql, pal, DM, ROWS,   32, 128, CU_TENSOR_MAP_SWIZZLE_64B);
    encode_map(enc, &mWh,  pwh, DM, 4 * DM, 32, 256, CU_TENSOR_MAP_SWIZZLE_64B);
    encode_map(enc, &mWl,  pwl, DM, 4 * DM, 32, 256, CU_TENSOR_MAP_SWIZZLE_64B);
    encode_map(enc, &mAoh, poh, DM, ROWS,   32, 128, CU_TENSOR_MAP_SWIZZLE_64B);
    encode_map(enc, &mAol, pol, DM, ROWS,   32, 128, CU_TENSOR_MAP_SWIZZLE_64B);

    cudaFuncSetAttribute(attn_kernel,
                         cudaFuncAttributeMaxDynamicSharedMemorySize, ATTN_DSMEM);
    cudaFuncSetAttribute(gemm_qkv_kernel,
                         cudaFuncAttributeMaxDynamicSharedMemorySize, GEMM_DSMEM);
    cudaFuncSetAttribute(gemm_fc_kernel,
                         cudaFuncAttributeMaxDynamicSharedMemorySize, GEMM_DSMEM);

    const float qscale = 0.125f * 1.4426950408889634f;

    // #1: wsplit x4
    wsplit4_kernel<<<dim3(16, 16, 4), 256>>>(wq, wk, wv, wfc, pwh, pwl);
    // #2: pe
    pe_kernel<<<256, 256>>>(ppe);
    // #3: ln1
    ln1_pos_kernel<<<ROWS, 256>>>(x, ln1_g, ln1_b, ppe, ph, pah, pal);
    // #4: fused q/k/v projections (TMA 4-stage; ncu capture target)
    gemm_qkv_kernel<<<dim3(ROWS / 128, DM / 256, 3), 256, GEMM_DSMEM>>>(
        mAqh, mAql, mWh, mWl,
        pah, pal, pwh, pwl, pqh, pql, pkh, pkl, pvt, qscale);
    // #5: attention
    dim3 ga(SEQ / 128, BATCH * NH);
    attn_kernel<<<ga, 256, ATTN_DSMEM>>>(pqh, pql, pkh, pkl, pvt, poh, pol);
    // #6: fc
    gemm_fc_kernel<<<dim3(ROWS / 128, DM / 256), 256, GEMM_DSMEM>>>(
        mAoh, mAol, mWh, mWl,
        poh, pol, pwh + 3 * (size_t)DM * DM, pwl + 3 * (size_t)DM * DM, pfc);
    // #7: ln2
    ln2_kernel<<<ROWS, 256>>>(pfc, ph, x, ln2_g, ln2_b, out);
}

// round 17
// speedup vs baseline: 1.3347x; 1.0088x over previous
#include <cuda_runtime.h>
#include <cuda.h>
#include <cuda_bf16.h>
#include <cuda_fp16.h>
#include <math.h>
#include <stdint.h>

#define BATCH 4
#define SEQ   2048
#define DM    512
#define NH    8
#define DK    64
#define ROWS  (BATCH * SEQ)   // 8192

#if defined(__CUDA_ARCH_FEAT_SM103_ALL) || defined(__CUDA_ARCH_FEAT_SM100_ALL) || \
    defined(__CUDA_ARCH_SPECIFIC__) || defined(__CUDA_ARCH_FAMILY_SPECIFIC__)
#define HAS_TC 1
#else
#define HAS_TC 0
#endif

// ---------------- scratch ----------------
__device__ float g_pe[SEQ * DM];
__device__ float g_fc[ROWS * DM];
__device__ __nv_bfloat16 g_ah[ROWS * DM];
__device__ __nv_bfloat16 g_al[ROWS * DM];
__device__ __nv_bfloat16 g_qh[ROWS * DM];
__device__ __nv_bfloat16 g_ql[ROWS * DM];
__device__ __nv_bfloat16 g_kh[ROWS * DM];
__device__ __nv_bfloat16 g_kl[ROWS * DM];
__device__ __nv_bfloat16 g_oh[ROWS * DM];
__device__ __nv_bfloat16 g_ol[ROWS * DM];
__device__ __half        g_vt[BATCH * NH * DK * SEQ];   // V^T fp16 [bh][dim][key]
__device__ __nv_bfloat16 g_wth[4][DM * DM];
__device__ __nv_bfloat16 g_wtl[4][DM * DM];

// ================= helpers =================
__device__ __forceinline__ uint32_t smem_u32(const void* p) {
    uint32_t a;
    asm("{ .reg .u64 t; cvta.to.shared.u64 t, %1; cvt.u32.u64 %0, t; }"
        : "=r"(a) : "l"(p));
    return a;
}

// cheap exp2: magic-constant rounding + deg-3 poly. Valid for |x| < ~60.
__device__ __forceinline__ float fexp2(float x) {
    float z = x + 12582912.f;
    int   iz = __float_as_int(z);
    float f  = x - (z - 12582912.f);
    float p  = 5.7708e-2f;                 // deg-3 minimax on [-0.5,0.5]
    p = fmaf(p, f, 2.39991e-1f);
    p = fmaf(p, f, 6.93147e-1f);
    p = fmaf(p, f, 1.0f);
    return p * __int_as_float((iz << 23) + 0x3F800000);
}

#if HAS_TC
__device__ __forceinline__ uint32_t elect1() {
    uint32_t p;
    asm volatile("{\n\t.reg .pred p;\n\telect.sync _|p, 0xFFFFFFFF;\n\t"
                 "selp.b32 %0, 1, 0, p;\n\t}" : "=r"(p));
    return p;
}
#define TC_ALLOC(smemaddr, ncols) \
    asm volatile("tcgen05.alloc.cta_group::1.sync.aligned.shared::cta.b32 [%0], %1;" \
                 :: "r"(smemaddr), "r"(ncols) : "memory")
#define TC_RELINQ() \
    asm volatile("tcgen05.relinquish_alloc_permit.cta_group::1.sync.aligned;")
#define TC_DEALLOC(tmem, ncols) \
    asm volatile("tcgen05.dealloc.cta_group::1.sync.aligned.b32 %0, %1;" \
                 :: "r"(tmem), "r"(ncols))
#define TC_COMMIT(mbar) \
    asm volatile("tcgen05.commit.cta_group::1.mbarrier::arrive::one.shared::cluster.b64 [%0];" \
                 :: "r"(mbar) : "memory")
#define TC_FENCE_AFTER()  asm volatile("tcgen05.fence::after_thread_sync;" ::: "memory")
#define TC_FENCE_BEFORE() asm volatile("tcgen05.fence::before_thread_sync;" ::: "memory")
#define TC_WAIT_LD()      asm volatile("tcgen05.wait::ld.sync.aligned;" ::: "memory")
#define FENCE_ASYNC_SHARED() asm volatile("fence.proxy.async.shared::cta;" ::: "memory")
#define MBAR_INIT(mbar, cnt) \
    asm volatile("mbarrier.init.shared.b64 [%0], %1;" :: "r"(mbar), "r"(cnt) : "memory")
#define MBAR_EXPECT_TX(mbar, bytes) \
    asm volatile("mbarrier.arrive.expect_tx.shared.b64 _, [%0], %1;" \
                 :: "r"(mbar), "r"(bytes) : "memory")
#define TMA_LOAD_2D(smem, map, x, y, mbar) \
    asm volatile("cp.async.bulk.tensor.2d.shared::cta.global.tile.mbarrier::complete_tx::bytes " \
                 "[%0], [%1, {%2, %3}], [%4];" \
                 :: "r"(smem), "l"(map), "r"(x), "r"(y), "r"(mbar) : "memory")

__device__ __forceinline__ void mbar_wait(uint32_t mbar, uint32_t parity) {
    asm volatile(
        "{\n\t.reg .pred P;\n\t"
        "WL_%=:\n\t"
        "mbarrier.try_wait.parity.acquire.cta.shared::cta.b64 P, [%0], %1, 0x989680;\n\t"
        "@P bra.uni WD_%=;\n\t"
        "bra.uni WL_%=;\n\t"
        "WD_%=:\n\t}"
        :: "r"(mbar), "r"(parity) : "memory");
}

__device__ __forceinline__ void tc_ld_x32(uint32_t* r, uint32_t tmem_addr) {
    asm volatile(
        "tcgen05.ld.sync.aligned.32x32b.x32.b32 "
        "{%0, %1, %2, %3, %4, %5, %6, %7, %8, %9, %10, %11, %12, %13, %14, %15, "
        " %16, %17, %18, %19, %20, %21, %22, %23, %24, %25, %26, %27, %28, %29, %30, %31}, [%32];"
        : "=r"(r[0]),  "=r"(r[1]),  "=r"(r[2]),  "=r"(r[3]),
          "=r"(r[4]),  "=r"(r[5]),  "=r"(r[6]),  "=r"(r[7]),
          "=r"(r[8]),  "=r"(r[9]),  "=r"(r[10]), "=r"(r[11]),
          "=r"(r[12]), "=r"(r[13]), "=r"(r[14]), "=r"(r[15]),
          "=r"(r[16]), "=r"(r[17]), "=r"(r[18]), "=r"(r[19]),
          "=r"(r[20]), "=r"(r[21]), "=r"(r[22]), "=r"(r[23]),
          "=r"(r[24]), "=r"(r[25]), "=r"(r[26]), "=r"(r[27]),
          "=r"(r[28]), "=r"(r[29]), "=r"(r[30]), "=r"(r[31])
        : "r"(tmem_addr));
}

__device__ __forceinline__ void mma_f16_ss(uint32_t d, uint64_t a, uint64_t b,
                                           uint32_t idesc, uint32_t en) {
    asm volatile(
        "{\n\t.reg .pred p;\n\tsetp.ne.u32 p, %4, 0;\n\t"
        "tcgen05.mma.cta_group::1.kind::f16 [%0], %1, %2, %3, {%5, %5, %5, %5}, p;\n\t}"
        :: "r"(d), "l"(a), "l"(b), "r"(idesc), "r"(en), "r"(0u) : "memory");
}

static __device__ __forceinline__ uint64_t make_desc_sw128(uint32_t base) {
    const uint64_t BASE =
        (uint64_t(2) << 61) | (uint64_t(1) << 46) | (uint64_t(64) << 32) | (uint64_t(1) << 16);
    return BASE | ((uint64_t)(base >> 4) & 0x3FFF);
}
// SW64: layout=4, version=1, SBO=32 (512B = 8 rows x 64B), LBO=1 (16B)
static __device__ __forceinline__ uint64_t make_desc_sw64(uint32_t base) {
    const uint64_t BASE =
        (uint64_t(4) << 61) | (uint64_t(1) << 46) | (uint64_t(32) << 32) | (uint64_t(1) << 16);
    return BASE | ((uint64_t)(base >> 4) & 0x3FFF);
}
#endif  // HAS_TC

// ---------------- wsplit x4 (launch #1) ----------------
__global__ void wsplit4_kernel(const float* __restrict__ W0,
                               const float* __restrict__ W1,
                               const float* __restrict__ W2,
                               const float* __restrict__ W3,
                               __nv_bfloat16* __restrict__ Th,
                               __nv_bfloat16* __restrict__ Tl) {
    __shared__ float t[32][33];
    int z = blockIdx.z;
    int tid = threadIdx.x;
    const float* W = (z == 0) ? W0 : (z == 1) ? W1 : (z == 2) ? W2 : W3;
    __nv_bfloat16* th = Th + (size_t)z * DM * DM;
    __nv_bfloat16* tl = Tl + (size_t)z * DM * DM;
    int n0 = blockIdx.x * 32, k0 = blockIdx.y * 32;
    int tx = tid & 31, ty = tid >> 5;
#pragma unroll
    for (int i = 0; i < 32; i += 8)
        t[ty + i][tx] = W[(size_t)(k0 + ty + i) * DM + n0 + tx];
    __syncthreads();
#pragma unroll
    for (int i = 0; i < 32; i += 8) {
        float v = t[tx][ty + i];
        __nv_bfloat16 h = __float2bfloat16(v);
        __nv_bfloat16 l = __float2bfloat16(v - __bfloat162float(h));
        size_t o = (size_t)(n0 + ty + i) * DM + k0 + tx;
        th[o] = h; tl[o] = l;
    }
}

// ---------------- positional encoding (launch #2) ----------------
__global__ void pe_kernel(float* __restrict__ pe) {
    int tid = threadIdx.x;
    int trow = blockIdx.x * 8 + (tid >> 5);
    int lane = tid & 31;
    const double c = -(9.210340371976184 / 512.0);
#pragma unroll
    for (int u = 0; u < 16; u++) {
        int col = lane * 16 + u;
        int i2  = col & ~1;
        double arg = (double)trow * exp((double)i2 * c);
        pe[trow * DM + col] = (col & 1) ? (float)cos(arg) : (float)sin(arg);
    }
}

// ---------------- LN1 + pe -> bf16 splits only ----------------
__global__ void ln1_pos_kernel(const float* __restrict__ x,
                               const float* __restrict__ gam,
                               const float* __restrict__ bet,
                               const float* __restrict__ pe,
                               __nv_bfloat16* __restrict__ hh,
                               __nv_bfloat16* __restrict__ hl) {
    __shared__ float redS[8], redS2[8];
    int row = blockIdx.x;
    int t   = row & (SEQ - 1);
    const float* xr = x  + (size_t)row * DM;
    const float* pr = pe + (size_t)t   * DM;
    int tid = threadIdx.x;

    float a = xr[tid], b = xr[tid + 256];
    float s  = a + b;
    float s2 = a * a + b * b;
#pragma unroll
    for (int off = 16; off; off >>= 1) {
        s  += __shfl_xor_sync(0xffffffffu, s,  off);
        s2 += __shfl_xor_sync(0xffffffffu, s2, off);
    }
    if ((tid & 31) == 0) { redS[tid >> 5] = s; redS2[tid >> 5] = s2; }
    __syncthreads();
    if (tid == 0) {
        float S = 0.f, S2 = 0.f;
#pragma unroll
        for (int w = 0; w < 8; w++) { S += redS[w]; S2 += redS2[w]; }
        redS[0] = S; redS2[0] = S2;
    }
    __syncthreads();
    float mu   = redS[0] * (1.f / 512.f);
    float var  = redS2[0] * (1.f / 512.f) - mu * mu;
    float rstd = rsqrtf(var + 1e-5f);
#pragma unroll
    for (int u = 0; u < 2; u++) {
        int col = tid + u * 256;
        float xv = u ? b : a;
        float hv = (xv - mu) * rstd * gam[col] + bet[col] + pr[col];
        size_t o = (size_t)row * DM + col;
        __nv_bfloat16 hi = __float2bfloat16(hv);
        hh[o] = hi;
        hl[o] = __float2bfloat16(hv - __bfloat162float(hi));
    }
}

// ---------------- LN2 + residuals (residual1 rebuilt from splits) ------------
__global__ void ln2_kernel(const float* __restrict__ o2,
                           const __nv_bfloat16* __restrict__ hh,
                           const __nv_bfloat16* __restrict__ hl,
                           const float* __restrict__ x,
                           const float* __restrict__ gam,
                           const float* __restrict__ bet,
                           float* __restrict__ out) {
    __shared__ float redS[8], redS2[8];
    int row = blockIdx.x;
    const float* or_ = o2 + (size_t)row * DM;
    const __nv_bfloat16* hhr = hh + (size_t)row * DM;
    const __nv_bfloat16* hlr = hl + (size_t)row * DM;
    const float* xr  = x  + (size_t)row * DM;
    float*       wr  = out + (size_t)row * DM;
    int tid = threadIdx.x;

    float r1a = __bfloat162float(hhr[tid])       + __bfloat162float(hlr[tid]);
    float r1b = __bfloat162float(hhr[tid + 256]) + __bfloat162float(hlr[tid + 256]);
    float a = or_[tid]       + r1a;
    float b = or_[tid + 256] + r1b;
    float s  = a + b;
    float s2 = a * a + b * b;
#pragma unroll
    for (int off = 16; off; off >>= 1) {
        s  += __shfl_xor_sync(0xffffffffu, s,  off);
        s2 += __shfl_xor_sync(0xffffffffu, s2, off);
    }
    if ((tid & 31) == 0) { redS[tid >> 5] = s; redS2[tid >> 5] = s2; }
    __syncthreads();
    if (tid == 0) {
        float S = 0.f, S2 = 0.f;
#pragma unroll
        for (int w = 0; w < 8; w++) { S += redS[w]; S2 += redS2[w]; }
        redS[0] = S; redS2[0] = S2;
    }
    __syncthreads();
    float mu   = redS[0] * (1.f / 512.f);
    float var  = redS2[0] * (1.f / 512.f) - mu * mu;
    float rstd = rsqrtf(var + 1e-6f);
#pragma unroll
    for (int u = 0; u < 2; u++) {
        int col = tid + u * 256;
        float vv = u ? b : a;
        wr[col] = (vv - mu) * rstd * gam[col] + bet[col] + xr[col];
    }
}

// ====== GEMM core (bf16x3, 128x256 tile, TMA 4-stage K=32 pipeline, SW64) ====
#define GIDESC2 ((1u << 4) | (1u << 7) | (1u << 10) | ((256u / 8) << 17) | ((128u / 16) << 24))
#define GEMM_DSMEM 197632
#define STAGE_B   49152u
#define CHUNK_TX  49152u

#if HAS_TC
__device__ __forceinline__ uint32_t gemm_mainloop_tma(
    const CUtensorMap* mAh, const CUtensorMap* mAl,
    const CUtensorMap* mWh, const CUtensorMap* mWl,
    int m0, int ny, char* dsm_raw,
    uint64_t* s_mbar, uint32_t* s_tm, uint32_t tid, uint32_t wid)
{
    uint32_t raw = smem_u32(dsm_raw);
    uint32_t sb  = (raw + 1023) & ~1023u;

    uint32_t mbF[4], mbD[4];
#pragma unroll
    for (int i = 0; i < 4; i++) {
        mbF[i] = smem_u32(&s_mbar[i]);
        mbD[i] = smem_u32(&s_mbar[4 + i]);
    }

    if (wid == 0) { TC_ALLOC(smem_u32(s_tm), 256); TC_RELINQ(); }
    if (tid == 0) {
#pragma unroll
        for (int i = 0; i < 4; i++) { MBAR_INIT(mbF[i], 1); MBAR_INIT(mbD[i], 1); }
    }
    __syncthreads();
    uint32_t tmem = s_tm[0];

    const uint32_t OAH = 0, OAL = 8192, OBH = 16384, OBL = 32768;

    if (wid == 0 && elect1()) {
#pragma unroll
        for (int s = 0; s < 3; s++) {
            uint32_t base = sb + (uint32_t)s * STAGE_B;
            MBAR_EXPECT_TX(mbF[s], CHUNK_TX);
            int k0 = s * 32;
            TMA_LOAD_2D(base + OAH, mAh, k0, m0, mbF[s]);
            TMA_LOAD_2D(base + OAL, mAl, k0, m0, mbF[s]);
            TMA_LOAD_2D(base + OBH, mWh, k0, ny, mbF[s]);
            TMA_LOAD_2D(base + OBL, mWl, k0, ny, mbF[s]);
        }
#pragma unroll 1
        for (int c = 0; c < 16; c++) {
            int b = c & 3;
            mbar_wait(mbF[b], (uint32_t)((c >> 2) & 1));
            uint32_t base = sb + (uint32_t)b * STAGE_B;
            uint64_t dah = make_desc_sw64(base + OAH);
            uint64_t dal = make_desc_sw64(base + OAL);
            uint64_t dbh = make_desc_sw64(base + OBH);
            uint64_t dbl = make_desc_sw64(base + OBL);
#pragma unroll
            for (int ks = 0; ks < 2; ks++) {
                mma_f16_ss(tmem, dah + ks * 2, dbh + ks * 2, GIDESC2,
                           (c == 0 && ks == 0) ? 0u : 1u);
                mma_f16_ss(tmem, dah + ks * 2, dbl + ks * 2, GIDESC2, 1u);
                mma_f16_ss(tmem, dal + ks * 2, dbh + ks * 2, GIDESC2, 1u);
            }
            TC_COMMIT(mbD[b]);
            if (c <= 12) {
                if (c >= 1) {
                    int pb = (c - 1) & 3;
                    mbar_wait(mbD[pb], (uint32_t)(((c - 1) >> 2) & 1));
                }
                int nb = (c + 3) & 3;
                uint32_t nbase = sb + (uint32_t)nb * STAGE_B;
                MBAR_EXPECT_TX(mbF[nb], CHUNK_TX);
                int k0 = (c + 3) * 32;
                TMA_LOAD_2D(nbase + OAH, mAh, k0, m0, mbF[nb]);
                TMA_LOAD_2D(nbase + OAL, mAl, k0, m0, mbF[nb]);
                TMA_LOAD_2D(nbase + OBH, mWh, k0, ny, mbF[nb]);
                TMA_LOAD_2D(nbase + OBL, mWl, k0, ny, mbF[nb]);
            }
        }
        mbar_wait(mbD[3], 1u);
    }
    __syncthreads();
    TC_FENCE_AFTER();
    return tmem;
}
#else
__device__ __forceinline__ void gemm_mainloop_simt(
    const __nv_bfloat16* __restrict__ Ah, const __nv_bfloat16* __restrict__ Al,
    const __nv_bfloat16* __restrict__ Bh, const __nv_bfloat16* __restrict__ Bl,
    int m0, int n0, char* dsm_raw, uint32_t tid, float acc[8][8])
{
    float* As = (float*)dsm_raw;
    float* Ws = As + 2 * 8 * 132;
    int tx = tid & 15, ty = (int)(tid >> 4);
    int r = tid & 127;
    bool isA = tid < 128;
    const __nv_bfloat16* Ph = isA ? Ah + (size_t)(m0 + r) * DM
                                  : Bh + (size_t)(n0 + r) * DM;
    const __nv_bfloat16* Pl = isA ? Al + (size_t)(m0 + r) * DM
                                  : Bl + (size_t)(n0 + r) * DM;
    int stride = isA ? 132 : 128;
#pragma unroll
    for (int i = 0; i < 8; i++)
#pragma unroll
        for (int j = 0; j < 8; j++) acc[i][j] = 0.f;

    auto stage = [&](int buf, int k0) {
        uint4 vh = *(const uint4*)(Ph + k0);
        uint4 vl = *(const uint4*)(Pl + k0);
        const __nv_bfloat16* bh = (const __nv_bfloat16*)&vh;
        const __nv_bfloat16* bl = (const __nv_bfloat16*)&vl;
        float* dst = (isA ? As + buf * 8 * 132 : Ws + buf * 8 * 128) + r;
#pragma unroll
        for (int k = 0; k < 8; k++)
            dst[k * stride] = __bfloat162float(bh[k]) + __bfloat162float(bl[k]);
    };
    stage(0, 0);
    __syncthreads();
    int buf = 0;
#pragma unroll 1
    for (int k0 = 0; k0 < 512; k0 += 8) {
        if (k0 + 8 < 512) stage(buf ^ 1, k0 + 8);
#pragma unroll
        for (int kk = 0; kk < 8; kk++) {
            float av[8], bv[8];
            const float* ar = As + buf * 8 * 132 + kk * 132;
            const float* wr = Ws + buf * 8 * 128 + kk * 128;
            *(float4*)(av)     = *(const float4*)(ar + ty * 4);
            *(float4*)(av + 4) = *(const float4*)(ar + 64 + ty * 4);
            *(float4*)(bv)     = *(const float4*)(wr + tx * 4);
            *(float4*)(bv + 4) = *(const float4*)(wr + 64 + tx * 4);
#pragma unroll
            for (int i = 0; i < 8; i++)
#pragma unroll
                for (int j = 0; j < 8; j++) acc[i][j] += av[i] * bv[j];
        }
        __syncthreads();
        buf ^= 1;
    }
}
#endif

// ---------------- fused Q/K/V projection (128x256 tiles, TMA) ----------------
__global__ void __launch_bounds__(256, 1)
gemm_qkv_kernel(const __grid_constant__ CUtensorMap mAh,
                const __grid_constant__ CUtensorMap mAl,
                const __grid_constant__ CUtensorMap mWh,
                const __grid_constant__ CUtensorMap mWl,
                const __nv_bfloat16* __restrict__ Ah,
                const __nv_bfloat16* __restrict__ Al,
                const __nv_bfloat16* __restrict__ Wh,
                const __nv_bfloat16* __restrict__ Wl,
                __nv_bfloat16* __restrict__ Qh, __nv_bfloat16* __restrict__ Ql,
                __nv_bfloat16* __restrict__ Kh, __nv_bfloat16* __restrict__ Kl,
                __half* __restrict__ Vt, float qscale) {
    extern __shared__ char dsm_raw[];
    uint32_t tid = threadIdx.x, wid = tid >> 5, lid = tid & 31;
    int m0 = blockIdx.x * 128, n0 = blockIdx.y * 256;
    int z = blockIdx.z;
    float scale = (z == 0) ? qscale : 1.0f;

#if HAS_TC
    __shared__ __align__(16) uint64_t s_mbar[8];
    __shared__ uint32_t s_tm[1];
    uint32_t tmem = gemm_mainloop_tma(&mAh, &mAl, &mWh, &mWl,
                                      m0, z * DM + n0, dsm_raw,
                                      s_mbar, s_tm, tid, wid);
    int sub  = wid & 3;
    int nblk = (int)(wid >> 2);
    int row  = m0 + sub * 32 + (int)lid;
    int b = row >> 11, t = row & (SEQ - 1);

#pragma unroll
    for (int cb = 0; cb < 4; cb++) {
        int colb = nblk * 128 + cb * 32;
        uint32_t d[32];
        tc_ld_x32(d, tmem + colb);
        TC_WAIT_LD();

        if (z < 2) {
            __nv_bfloat16* Ch = (z == 0) ? Qh : Kh;
            __nv_bfloat16* Cl = (z == 0) ? Ql : Kl;
            size_t rowoff = (size_t)row * DM + n0 + colb;
            uint32_t hw[16], lw[16];
#pragma unroll
            for (int m = 0; m < 16; m++) {
                float v0 = __uint_as_float(d[2*m])   * scale;
                float v1 = __uint_as_float(d[2*m+1]) * scale;
                __nv_bfloat162 h2 = __floats2bfloat162_rn(v0, v1);
                __nv_bfloat162 l2 = __floats2bfloat162_rn(v0 - __bfloat162float(h2.x),
                                                          v1 - __bfloat162float(h2.y));
                hw[m] = *(uint32_t*)&h2; lw[m] = *(uint32_t*)&l2;
            }
#pragma unroll
            for (int u = 0; u < 4; u++) {
                *(uint4*)(Ch + rowoff + u * 8) =
                    make_uint4(hw[4*u], hw[4*u+1], hw[4*u+2], hw[4*u+3]);
                *(uint4*)(Cl + rowoff + u * 8) =
                    make_uint4(lw[4*u], lw[4*u+1], lw[4*u+2], lw[4*u+3]);
            }
        } else {
#pragma unroll
            for (int j = 0; j < 32; j++) {
                int c = n0 + colb + j;
                size_t o = ((size_t)((b << 3) + (c >> 6)) * 64 + (c & 63)) * SEQ + t;
                Vt[o] = __float2half(__uint_as_float(d[j]));
            }
        }
    }
    TC_FENCE_BEFORE();
    __syncthreads();
    if (wid == 0) TC_DEALLOC(tmem, 256);
#else
    const __nv_bfloat16* Bh = Wh + (size_t)z * DM * DM;
    const __nv_bfloat16* Bl = Wl + (size_t)z * DM * DM;
    for (int nh = 0; nh < 2; nh++) {
        float acc[8][8];
        gemm_mainloop_simt(Ah, Al, Bh, Bl, m0, n0 + nh * 128, dsm_raw, tid, acc);
        int tx = tid & 15, ty = (int)(tid >> 4);
#pragma unroll
        for (int i = 0; i < 8; i++) {
            int row = m0 + ((i < 4) ? (ty * 4 + i) : (64 + ty * 4 + i - 4));
#pragma unroll
            for (int j = 0; j < 8; j++) {
                int col = n0 + nh * 128 + ((j < 4) ? (tx * 4 + j) : (64 + tx * 4 + j - 4));
                float v = acc[i][j] * scale;
                if (z < 2) {
                    __nv_bfloat16* Ch = (z == 0) ? Qh : Kh;
                    __nv_bfloat16* Cl = (z == 0) ? Ql : Kl;
                    __nv_bfloat16 h = __float2bfloat16(v);
                    Ch[(size_t)row * DM + col] = h;
                    Cl[(size_t)row * DM + col] = __float2bfloat16(v - __bfloat162float(h));
                } else {
                    int b = row >> 11, t = row & (SEQ - 1);
                    size_t o = ((size_t)((b << 3) + (col >> 6)) * 64 + (col & 63)) * SEQ + t;
                    Vt[o] = __float2half(v);
                }
            }
        }
        __syncthreads();
    }
#endif
}

// ---------------- FC projection (fp32 out, 128x256 tiles, TMA) ---------------
__global__ void __launch_bounds__(256, 1)
gemm_fc_kernel(const __grid_constant__ CUtensorMap mAh,
               const __grid_constant__ CUtensorMap mAl,
               const __grid_constant__ CUtensorMap mWh,
               const __grid_constant__ CUtensorMap mWl,
               const __nv_bfloat16* __restrict__ Ah,
               const __nv_bfloat16* __restrict__ Al,
               const __nv_bfloat16* __restrict__ Bh,
               const __nv_bfloat16* __restrict__ Bl,
               float* __restrict__ C) {
    extern __shared__ char dsm_raw[];
    uint32_t tid = threadIdx.x, wid = tid >> 5, lid = tid & 31;
    int m0 = blockIdx.x * 128, n0 = blockIdx.y * 256;
#if HAS_TC
    __shared__ __align__(16) uint64_t s_mbar[8];
    __shared__ uint32_t s_tm[1];
    uint32_t tmem = gemm_mainloop_tma(&mAh, &mAl, &mWh, &mWl,
                                      m0, 3 * DM + n0, dsm_raw,
                                      s_mbar, s_tm, tid, wid);
    int sub  = wid & 3;
    int nblk = (int)(wid >> 2);
    int row  = m0 + sub * 32 + (int)lid;

#pragma unroll
    for (int cb = 0; cb < 4; cb++) {
        int colb = nblk * 128 + cb * 32;
        uint32_t d[32];
        tc_ld_x32(d, tmem + colb);
        TC_WAIT_LD();
        float* Cr = C + (size_t)row * DM + n0 + colb;
#pragma unroll
        for (int j = 0; j < 8; j++)
            *(float4*)(Cr + j * 4) = make_float4(
                __uint_as_float(d[4*j]),   __uint_as_float(d[4*j+1]),
                __uint_as_float(d[4*j+2]), __uint_as_float(d[4*j+3]));
    }
    TC_FENCE_BEFORE();
    __syncthreads();
    if (wid == 0) TC_DEALLOC(tmem, 256);
#else
    for (int nh = 0; nh < 2; nh++) {
        float acc[8][8];
        gemm_mainloop_simt(Ah, Al, Bh, Bl, m0, n0 + nh * 128, dsm_raw, tid, acc);
        int tx = tid & 15, ty = (int)(tid >> 4);
#pragma unroll
        for (int i = 0; i < 8; i++) {
            int row = m0 + ((i < 4) ? (ty * 4 + i) : (64 + ty * 4 + i - 4));
#pragma unroll
            for (int j = 0; j < 8; j++) {
                int col = n0 + nh * 128 + ((j < 4) ? (tx * 4 + j) : (64 + tx * 4 + j - 4));
                C[(size_t)row * DM + col] = acc[i][j];
            }
        }
        __syncthreads();
    }
#endif
}

// ========== attention (pipelined, triple-buffered V, cheap softmax) ==========
#define AIDESC_S  ((1u << 4) | (1u << 7) | (1u << 10) | ((64u / 8) << 17) | ((128u / 16) << 24))
#define AIDESC_PV ((1u << 4) | ((64u / 8) << 17) | ((128u / 16) << 24))
#define ATTN_DSMEM 108544

#if HAS_TC
__global__ void __launch_bounds__(256, 2)
attn_kernel(const __nv_bfloat16* __restrict__ Qh, const __nv_bfloat16* __restrict__ Ql,
            const __nv_bfloat16* __restrict__ Kh, const __nv_bfloat16* __restrict__ Kl,
            const __half* __restrict__ Vt,
            __nv_bfloat16* __restrict__ Oh, __nv_bfloat16* __restrict__ Ol) {
    extern __shared__ char dsm_raw[];
    __shared__ __align__(16) uint64_t s_mbar[3];
    __shared__ uint32_t s_tm[1];
    uint32_t tid = threadIdx.x, wid = tid >> 5, lane = tid & 31;
    int qt = (int)(gridDim.x - 1) - (int)blockIdx.x;
    int bh = blockIdx.y, bb = bh >> 3, hd = bh & 7;

    uint32_t raw = smem_u32(dsm_raw);
    uint32_t sb  = (raw + 1023) & ~1023u;
    char* dsm = dsm_raw + (sb - raw);

    const uint32_t OFF_QH = 0,     OFF_QL = 16384,
                   OFF_KH = 32768, OFF_KL = 49152,
                   OFF_V  = 65536,
                   OFF_P  = 90112,
                   OFF_L  = 106496;

    uint32_t mbS0 = smem_u32(&s_mbar[0]);
    uint32_t mbS1 = smem_u32(&s_mbar[1]);
    uint32_t mbPV = smem_u32(&s_mbar[2]);
    if (wid == 0) { TC_ALLOC(smem_u32(s_tm), 256); TC_RELINQ(); }
    if (tid == 0) { MBAR_INIT(mbS0, 1); MBAR_INIT(mbS1, 1); MBAR_INIT(mbPV, 1); }
    __syncthreads();
    uint32_t tmem = s_tm[0];

    size_t rowbase = (size_t)bb * SEQ;
    const __nv_bfloat16* khb = Kh + rowbase * DM + hd * 64;
    const __nv_bfloat16* klb = Kl + rowbase * DM + hd * 64;
    const __half*        vtb = Vt + ((size_t)bh * 64) * SEQ;

    int cr0 = (int)tid >> 3,         cg0 = ((int)tid & 7) * 8;
    int cr1 = (int)(tid + 256) >> 3, cg1 = (((int)tid + 256) & 7) * 8;
    uint32_t so0, so1;
    {
        uint32_t o0 = (uint32_t)(cr0 * 128 + cg0 * 2), o1 = (uint32_t)(cr1 * 128 + cg1 * 2);
        so0 = o0 ^ ((o0 >> 3) & 0x70);
        so1 = o1 ^ ((o1 >> 3) & 0x70);
    }

    {
        const __nv_bfloat16* qhp = Qh + (rowbase + (size_t)qt * 128) * DM + hd * 64;
        const __nv_bfloat16* qlp = Ql + (rowbase + (size_t)qt * 128) * DM + hd * 64;
#pragma unroll
        for (int i = 0; i < 4; i++) {
            int idx = i * 256 + (int)tid;
            int r = idx >> 3, g = idx & 7;
            uint32_t o = (uint32_t)(r * 128 + g * 16), so = o ^ ((o >> 3) & 0x70);
            *(uint4*)(dsm + OFF_QH + so) = *(const uint4*)(qhp + (size_t)r * DM + g * 8);
            *(uint4*)(dsm + OFF_QL + so) = *(const uint4*)(qlp + (size_t)r * DM + g * 8);
        }
        *(uint4*)(dsm + OFF_KH + so0) = *(const uint4*)(khb + (size_t)cr0 * DM + cg0);
        *(uint4*)(dsm + OFF_KH + so1) = *(const uint4*)(khb + (size_t)cr1 * DM + cg1);
        *(uint4*)(dsm + OFF_KL + so0) = *(const uint4*)(klb + (size_t)cr0 * DM + cg0);
        *(uint4*)(dsm + OFF_KL + so1) = *(const uint4*)(klb + (size_t)cr1 * DM + cg1);
        *(uint4*)(dsm + OFF_V  + so0) = *(const uint4*)(vtb + (size_t)cr0 * SEQ + cg0);
        *(uint4*)(dsm + OFF_V  + so1) = *(const uint4*)(vtb + (size_t)cr1 * SEQ + cg1);
    }

    int ktmax = 2 * qt + 1;

    uint4 pkh0, pkh1, pkl0, pkl1, pv0, pv1;
    {
        const __nv_bfloat16* khp = khb + (size_t)64 * DM;
        const __nv_bfloat16* klp = klb + (size_t)64 * DM;
        const __half*        vhp = vtb + 64;
        pkh0 = *(const uint4*)(khp + (size_t)cr0 * DM + cg0);
        pkh1 = *(const uint4*)(khp + (size_t)cr1 * DM + cg1);
        pkl0 = *(const uint4*)(klp + (size_t)cr0 * DM + cg0);
        pkl1 = *(const uint4*)(klp + (size_t)cr1 * DM + cg1);
        pv0  = *(const uint4*)(vhp + (size_t)cr0 * SEQ + cg0);
        pv1  = *(const uint4*)(vhp + (size_t)cr1 * SEQ + cg1);
    }
    __syncthreads();

    uint64_t dqh = make_desc_sw128(sb + OFF_QH);
    uint64_t dql = make_desc_sw128(sb + OFF_QL);

    if (wid == 0 && elect1()) {
        FENCE_ASYNC_SHARED();
        uint64_t dkh = make_desc_sw128(sb + OFF_KH);
        uint64_t dkl = make_desc_sw128(sb + OFF_KL);
#pragma unroll
        for (int ks = 0; ks < 4; ks++)
            mma_f16_ss(tmem, dqh + ks * 2, dkh + ks * 2, AIDESC_S, ks ? 1u : 0u);
#pragma unroll
        for (int ks = 0; ks < 4; ks++)
            mma_f16_ss(tmem, dqh + ks * 2, dkl + ks * 2, AIDESC_S, 1u);
#pragma unroll
        for (int ks = 0; ks < 4; ks++)
            mma_f16_ss(tmem, dql + ks * 2, dkh + ks * 2, AIDESC_S, 1u);
        TC_COMMIT(mbS0);
    }

    int sub = wid & 3, half = (int)(wid >> 2);
    int rl = sub * 32 + (int)lane;
    int grow = qt * 128 + rl;
    float lsum = 0.f;
    uint32_t phS0 = 0, phS1 = 0, phPV = 0;
    int vslot = 0;

#pragma unroll 1
    for (int kt = 0; kt <= ktmax; kt++) {
        int buf = kt & 1;

        if (kt < ktmax) {
            int nbuf = buf ^ 1;
            int nvslot = vslot + 1; if (nvslot == 3) nvslot = 0;
            uint32_t kb   = OFF_KH + (uint32_t)nbuf * 8192u;
            uint32_t klb2 = OFF_KL + (uint32_t)nbuf * 8192u;
            uint32_t vb   = OFF_V  + (uint32_t)nvslot * 8192u;
            *(uint4*)(dsm + kb   + so0) = pkh0;
            *(uint4*)(dsm + kb   + so1) = pkh1;
            *(uint4*)(dsm + klb2 + so0) = pkl0;
            *(uint4*)(dsm + klb2 + so1) = pkl1;
            *(uint4*)(dsm + vb   + so0) = pv0;
            *(uint4*)(dsm + vb   + so1) = pv1;
            __syncthreads();
            if (wid == 0 && elect1()) {
                FENCE_ASYNC_SHARED();
                uint64_t dkh = make_desc_sw128(sb + kb);
                uint64_t dkl = make_desc_sw128(sb + klb2);
                uint32_t stm = tmem + (uint32_t)nbuf * 64u;
#pragma unroll
                for (int ks = 0; ks < 4; ks++)
                    mma_f16_ss(stm, dqh + ks * 2, dkh + ks * 2, AIDESC_S, ks ? 1u : 0u);
#pragma unroll
                for (int ks = 0; ks < 4; ks++)
                    mma_f16_ss(stm, dqh + ks * 2, dkl + ks * 2, AIDESC_S, 1u);
#pragma unroll
                for (int ks = 0; ks < 4; ks++)
                    mma_f16_ss(stm, dql + ks * 2, dkh + ks * 2, AIDESC_S, 1u);
                TC_COMMIT(nbuf == 0 ? mbS0 : mbS1);
            }
            if (kt + 2 <= ktmax) {
                const __nv_bfloat16* khp = khb + (size_t)(kt + 2) * 64 * DM;
                const __nv_bfloat16* klp = klb + (size_t)(kt + 2) * 64 * DM;
                const __half*        vhp = vtb + (size_t)(kt + 2) * 64;
                pkh0 = *(const uint4*)(khp + (size_t)cr0 * DM + cg0);
                pkh1 = *(const uint4*)(khp + (size_t)cr1 * DM + cg1);
                pkl0 = *(const uint4*)(klp + (size_t)cr0 * DM + cg0);
                pkl1 = *(const uint4*)(klp + (size_t)cr1 * DM + cg1);
                pv0  = *(const uint4*)(vhp + (size_t)cr0 * SEQ + cg0);
                pv1  = *(const uint4*)(vhp + (size_t)cr1 * SEQ + cg1);
            }
        }

        if (buf == 0) { mbar_wait(mbS0, phS0); phS0 ^= 1; }
        else          { mbar_wait(mbS1, phS1); phS1 ^= 1; }
        TC_FENCE_AFTER();

        uint32_t sreg[32];
        tc_ld_x32(sreg, tmem + (uint32_t)buf * 64u + half * 32);
        TC_WAIT_LD();

        if (kt >= 1) { mbar_wait(mbPV, phPV); phPV ^= 1; }

        int jmax = grow - (kt * 64 + half * 32);
        uint32_t pbase = (uint32_t)(rl * 128 + half * 64);
        if (jmax >= 31) {
#pragma unroll
            for (int gj = 0; gj < 4; gj++) {
                uint32_t w[4];
#pragma unroll
                for (int m = 0; m < 4; m++) {
                    int j0 = gj * 8 + m * 2;
                    float p0 = fexp2(__uint_as_float(sreg[j0]));
                    float p1 = fexp2(__uint_as_float(sreg[j0 + 1]));
                    lsum += p0 + p1;
                    __half2 h2 = __floats2half2_rn(p0, p1);
                    w[m] = *(uint32_t*)&h2;
                }
                uint32_t o = pbase + gj * 16, so = o ^ ((o >> 3) & 0x70);
                *(uint4*)(dsm + OFF_P + so) = make_uint4(w[0], w[1], w[2], w[3]);
            }
        } else {
#pragma unroll
            for (int gj = 0; gj < 4; gj++) {
                uint32_t w[4];
#pragma unroll
                for (int m = 0; m < 4; m++) {
                    int j0 = gj * 8 + m * 2;
                    float p0 = (j0     <= jmax) ? fexp2(__uint_as_float(sreg[j0]))     : 0.f;
                    float p1 = (j0 + 1 <= jmax) ? fexp2(__uint_as_float(sreg[j0 + 1])) : 0.f;
                    lsum += p0 + p1;
                    __half2 h2 = __floats2half2_rn(p0, p1);
                    w[m] = *(uint32_t*)&h2;
                }
                uint32_t o = pbase + gj * 16, so = o ^ ((o >> 3) & 0x70);
                *(uint4*)(dsm + OFF_P + so) = make_uint4(w[0], w[1], w[2], w[3]);
            }
        }
        __syncthreads();

        if (wid == 0 && elect1()) {
            FENCE_ASYNC_SHARED();
            uint64_t dp = make_desc_sw128(sb + OFF_P);
            uint64_t dv = make_desc_sw128(sb + OFF_V + (uint32_t)vslot * 8192u);
#pragma unroll
            for (int ks = 0; ks < 4; ks++)
                mma_f16_ss(tmem + 128, dp + ks * 2, dv + ks * 2, AIDESC_PV,
                           (kt == 0 && ks == 0) ? 0u : 1u);
            TC_COMMIT(mbPV);
        }
        vslot++; if (vslot == 3) vslot = 0;
    }

    mbar_wait(mbPV, phPV);
    TC_FENCE_AFTER();

    float* sl = (float*)(dsm + OFF_L);
    sl[rl * 2 + half] = lsum;
    __syncthreads();
    float inv = 1.f / (sl[rl * 2] + sl[rl * 2 + 1]);

    uint32_t oreg[32];
    tc_ld_x32(oreg, tmem + 128 + half * 32);
    TC_WAIT_LD();
    TC_FENCE_BEFORE();

    size_t obase = (rowbase + (size_t)grow) * DM + hd * 64 + half * 32;
    uint32_t hw[16], lw[16];
#pragma unroll
    for (int m = 0; m < 16; m++) {
        float v0 = __uint_as_float(oreg[2*m])   * inv;
        float v1 = __uint_as_float(oreg[2*m+1]) * inv;
        __nv_bfloat162 h2 = __floats2bfloat162_rn(v0, v1);
        __nv_bfloat162 l2 = __floats2bfloat162_rn(v0 - __bfloat162float(h2.x),
                                                  v1 - __bfloat162float(h2.y));
        hw[m] = *(uint32_t*)&h2; lw[m] = *(uint32_t*)&l2;
    }
#pragma unroll
    for (int u = 0; u < 4; u++) {
        *(uint4*)(Oh + obase + u * 8) = make_uint4(hw[4*u], hw[4*u+1], hw[4*u+2], hw[4*u+3]);
        *(uint4*)(Ol + obase + u * 8) = make_uint4(lw[4*u], lw[4*u+1], lw[4*u+2], lw[4*u+3]);
    }
    __syncthreads();
    if (wid == 0) TC_DEALLOC(tmem, 256);
}

#else  // ---------------- SIMT fallback attention ----------------
__global__ void __launch_bounds__(256)
attn_kernel(const __nv_bfloat16* __restrict__ Qh, const __nv_bfloat16* __restrict__ Ql,
            const __nv_bfloat16* __restrict__ Kh, const __nv_bfloat16* __restrict__ Kl,
            const __half* __restrict__ Vt,
            __nv_bfloat16* __restrict__ Oh, __nv_bfloat16* __restrict__ Ol) {
    extern __shared__ float sm[];
    float* sQ = sm;
    float* sK = sQ + 128 * 68;
    float* sV = sK + 64 * 68;
    float* sP = sV + 64 * 64;

    int qt = (int)(gridDim.x - 1) - (int)blockIdx.x;
    int bh = blockIdx.y;
    int bb = bh >> 3, hd = bh & 7;
    int tid = threadIdx.x;
    int tx = tid & 15, ty = tid >> 4;
    size_t base = ((size_t)bb * SEQ) * DM + (size_t)hd * DK;

    for (int idx = tid; idx < 128 * 64; idx += 256) {
        int r = idx >> 6, c = idx & 63;
        size_t o = base + (size_t)(qt * 128 + r) * DM + c;
        sQ[r * 68 + c] = __bfloat162float(Qh[o]) + __bfloat162float(Ql[o]);
    }

    float Oacc[8][4], m_i[8], l_i[8];
#pragma unroll
    for (int i = 0; i < 8; i++) {
        m_i[i] = -1e30f; l_i[i] = 0.f;
#pragma unroll
        for (int j = 0; j < 4; j++) Oacc[i][j] = 0.f;
    }

    int ktmax = 2 * qt + 1;
    for (int kt = 0; kt <= ktmax; kt++) {
        for (int idx = tid; idx < 64 * 64; idx += 256) {
            int r = idx >> 6, c = idx & 63;
            size_t ga = base + (size_t)(kt * 64 + r) * DM + c;
            sK[r * 68 + c] = __bfloat162float(Kh[ga]) + __bfloat162float(Kl[ga]);
            sV[r * 64 + c] = __half2float(Vt[((size_t)bh * 64 + c) * SEQ + kt * 64 + r]);
        }
        __syncthreads();

        float s[8][4];
#pragma unroll
        for (int i = 0; i < 8; i++)
#pragma unroll
            for (int j = 0; j < 4; j++) s[i][j] = 0.f;
#pragma unroll
        for (int d4 = 0; d4 < 16; d4++) {
            float4 kv[4];
#pragma unroll
            for (int j = 0; j < 4; j++)
                kv[j] = *(const float4*)&sK[(tx + 16 * j) * 68 + d4 * 4];
#pragma unroll
            for (int i = 0; i < 8; i++) {
                float4 qv = *(const float4*)&sQ[(ty + 16 * i) * 68 + d4 * 4];
#pragma unroll
                for (int j = 0; j < 4; j++)
                    s[i][j] += qv.x * kv[j].x + qv.y * kv[j].y +
                               qv.z * kv[j].z + qv.w * kv[j].w;
            }
        }
        if (kt >= 2 * qt) {
#pragma unroll
            for (int i = 0; i < 8; i++) {
                int grow = qt * 128 + ty + 16 * i;
#pragma unroll
                for (int j = 0; j < 4; j++)
                    if (kt * 64 + tx + 16 * j > grow) s[i][j] = -1e30f;
            }
        }
#pragma unroll
        for (int i = 0; i < 8; i++) {
            float mt = fmaxf(fmaxf(s[i][0], s[i][1]), fmaxf(s[i][2], s[i][3]));
#pragma unroll
            for (int off = 8; off; off >>= 1)
                mt = fmaxf(mt, __shfl_xor_sync(0xffffffffu, mt, off));
            float mn = fmaxf(m_i[i], mt);
            float corr = exp2f(m_i[i] - mn);
            m_i[i] = mn;
            float rs = 0.f;
#pragma unroll
            for (int j = 0; j < 4; j++) {
                float p = exp2f(s[i][j] - mn);
                s[i][j] = p; rs += p;
            }
#pragma unroll
            for (int off = 8; off; off >>= 1)
                rs += __shfl_xor_sync(0xffffffffu, rs, off);
            l_i[i] = l_i[i] * corr + rs;
#pragma unroll
            for (int j = 0; j < 4; j++) Oacc[i][j] *= corr;
#pragma unroll
            for (int j = 0; j < 4; j++)
                sP[(ty + 16 * i) * 68 + tx + 16 * j] = s[i][j];
        }
        __syncthreads();
#pragma unroll 4
        for (int k = 0; k < 64; k += 4) {
            float4 vv0 = *(const float4*)&sV[(k + 0) * 64 + tx * 4];
            float4 vv1 = *(const float4*)&sV[(k + 1) * 64 + tx * 4];
            float4 vv2 = *(const float4*)&sV[(k + 2) * 64 + tx * 4];
            float4 vv3 = *(const float4*)&sV[(k + 3) * 64 + tx * 4];
#pragma unroll
            for (int i = 0; i < 8; i++) {
                float4 pv = *(const float4*)&sP[(ty + 16 * i) * 68 + k];
                Oacc[i][0] += pv.x * vv0.x + pv.y * vv1.x + pv.z * vv2.x + pv.w * vv3.x;
                Oacc[i][1] += pv.x * vv0.y + pv.y * vv1.y + pv.z * vv2.y + pv.w * vv3.y;
                Oacc[i][2] += pv.x * vv0.z + pv.y * vv1.z + pv.z * vv2.z + pv.w * vv3.z;
                Oacc[i][3] += pv.x * vv0.w + pv.y * vv1.w + pv.z * vv2.w + pv.w * vv3.w;
            }
        }
        __syncthreads();
    }
#pragma unroll
    for (int i = 0; i < 8; i++) {
        float inv = 1.f / l_i[i];
        size_t rowa = base + (size_t)(qt * 128 + ty + 16 * i) * DM + tx * 4;
#pragma unroll
        for (int j = 0; j < 4; j++) {
            float v = Oacc[i][j] * inv;
            __nv_bfloat16 h = __float2bfloat16(v);
            Oh[rowa + j] = h;
            Ol[rowa + j] = __float2bfloat16(v - __bfloat162float(h));
        }
    }
}
#endif

// ---------------- host: tensormap encoding via driver entry point ------------
typedef CUresult (*PFN_cuTensorMapEncodeTiled_v12000)(
    CUtensorMap*, CUtensorMapDataType, cuuint32_t, void*,
    const cuuint64_t*, const cuuint64_t*, const cuuint32_t*, const cuuint32_t*,
    CUtensorMapInterleave, CUtensorMapSwizzle, CUtensorMapL2promotion,
    CUtensorMapFloatOOBfill);

static void encode_map(PFN_cuTensorMapEncodeTiled_v12000 fn, CUtensorMap* m,
                       void* base, unsigned long long d0, unsigned long long d1,
                       unsigned int b0, unsigned int b1,
                       CUtensorMapSwizzle sw) {
    cuuint64_t dims[2]    = {d0, d1};
    cuuint64_t strides[1] = {d0 * 2};
    cuuint32_t box[2]     = {b0, b1};
    cuuint32_t es[2]      = {1, 1};
    fn(m, CU_TENSOR_MAP_DATA_TYPE_BFLOAT16, 2, base, dims, strides, box, es,
       CU_TENSOR_MAP_INTERLEAVE_NONE, sw,
       CU_TENSOR_MAP_L2_PROMOTION_L2_256B, CU_TENSOR_MAP_FLOAT_OOB_FILL_NONE);
}

// ---------------- launch ----------------
extern "C" void kernel_launch(void* const* d_in, const int* in_sizes, int n_in,
                              void* d_out, int out_size) {
    const float* x     = (const float*)d_in[0];
    const float* ln1_g = (const float*)d_in[1];
    const float* ln1_b = (const float*)d_in[2];
    const float* wq    = (const float*)d_in[3];
    const float* wk    = (const float*)d_in[4];
    const float* wv    = (const float*)d_in[5];
    const float* wfc   = (const float*)d_in[6];
    const float* ln2_g = (const float*)d_in[7];
    const float* ln2_b = (const float*)d_in[8];
    float* out = (float*)d_out;

    float *ppe, *pfc;
    __nv_bfloat16 *pwh, *pwl, *pah, *pal, *pqh, *pql, *pkh, *pkl, *poh, *pol;
    __half *pvt;
    cudaGetSymbolAddress((void**)&ppe,  g_pe);
    cudaGetSymbolAddress((void**)&pfc,  g_fc);
    cudaGetSymbolAddress((void**)&pwh,  g_wth);
    cudaGetSymbolAddress((void**)&pwl,  g_wtl);
    cudaGetSymbolAddress((void**)&pah,  g_ah);
    cudaGetSymbolAddress((void**)&pal,  g_al);
    cudaGetSymbolAddress((void**)&pqh,  g_qh);
    cudaGetSymbolAddress((void**)&pql,  g_ql);
    cudaGetSymbolAddress((void**)&pkh,  g_kh);
    cudaGetSymbolAddress((void**)&pkl,  g_kl);
    cudaGetSymbolAddress((void**)&poh,  g_oh);
    cudaGetSymbolAddress((void**)&pol,  g_ol);
    cudaGetSymbolAddress((void**)&pvt,  g_vt);

    PFN_cuTensorMapEncodeTiled_v12000 enc = nullptr;
    {
        void* fn = nullptr;
        cudaDriverEntryPointQueryResult st;
        cudaGetDriverEntryPoint("cuTensorMapEncodeTiled", &fn,
                                cudaEnableDefault, &st);
        enc = (PFN_cuTensorMapEncodeTiled_v12000)fn;
    }
    CUtensorMap mAqh, mAql, mWh, mWl, mAoh, mAol;
    encode_map(enc, &mAqh, pah, DM, ROWS,   32, 128, CU_TENSOR_MAP_SWIZZLE_64B);
    encode_map(enc, &mAql, pal, DM, ROWS,   32, 128, CU_TENSOR_MAP_SWIZZLE_64B);
    encode_map(enc, &mWh,  pwh, DM, 4 * DM, 32, 256, CU_TENSOR_MAP_SWIZZLE_64B);
    encode_map(enc, &mWl,  pwl, DM, 4 * DM, 32, 256, CU_TENSOR_MAP_SWIZZLE_64B);
    encode_map(enc, &mAoh, poh, DM, ROWS,   32, 128, CU_TENSOR_MAP_SWIZZLE_64B);
    encode_map(enc, &mAol, pol, DM, ROWS,   32, 128, CU_TENSOR_MAP_SWIZZLE_64B);

    cudaFuncSetAttribute(attn_kernel,
                         cudaFuncAttributeMaxDynamicSharedMemorySize, ATTN_DSMEM);
    cudaFuncSetAttribute(gemm_qkv_kernel,
                         cudaFuncAttributeMaxDynamicSharedMemorySize, GEMM_DSMEM);
    cudaFuncSetAttribute(gemm_fc_kernel,
                         cudaFuncAttributeMaxDynamicSharedMemorySize, GEMM_DSMEM);

    const float qscale = 0.125f * 1.4426950408889634f;

    // #1: wsplit x4
    wsplit4_kernel<<<dim3(16, 16, 4), 256>>>(wq, wk, wv, wfc, pwh, pwl);
    // #2: pe
    pe_kernel<<<256, 256>>>(ppe);
    // #3: ln1
    ln1_pos_kernel<<<ROWS, 256>>>(x, ln1_g, ln1_b, ppe, pah, pal);
    // #4: fused q/k/v projections (TMA 4-stage; ncu capture target)
    gemm_qkv_kernel<<<dim3(ROWS / 128, DM / 256, 3), 256, GEMM_DSMEM>>>(
        mAqh, mAql, mWh, mWl,
        pah, pal, pwh, pwl, pqh, pql, pkh, pkl, pvt, qscale);
    // #5: attention
    dim3 ga(SEQ / 128, BATCH * NH);
    attn_kernel<<<ga, 256, ATTN_DSMEM>>>(pqh, pql, pkh, pkl, pvt, poh, pol);
    // #6: fc
    gemm_fc_kernel<<<dim3(ROWS / 128, DM / 256), 256, GEMM_DSMEM>>>(
        mAoh, mAol, mWh, mWl,
        poh, pol, pwh + 3 * (size_t)DM * DM, pwl + 3 * (size_t)DM * DM, pfc);
    // #7: ln2
    ln2_kernel<<<ROWS, 256>>>(pfc, pah, pal, x, ln2_g, ln2_b, out);
}